// round 2
// baseline (speedup 1.0000x reference)
#include <cuda_runtime.h>
#include <cuda_bf16.h>
#include <math.h>

// Problem constants
#define Bb 4
#define Tt 1024
#define Vv 50304
#define Ee 768
#define Ll 12
#define Hh 6
#define HDd 128
#define HIDh 3072
#define NTOK (Bb*Tt)          // 4096
#define EPS 1e-6f

// ---------------- scratch (static device globals; no allocation) -------------
__device__ float g_x [NTOK*Ee];
__device__ float g_x0[NTOK*Ee];
__device__ float g_h [NTOK*Ee];
__device__ float g_w [NTOK*Ee];
__device__ float g_o [NTOK*Ee];
__device__ float g_a [NTOK*HIDh];
__device__ float g_dots[(long long)Bb*Hh*Tt*Tt];   // 24 * 1024 * 1024

// ---------------- reductions -------------------------------------------------
__device__ __forceinline__ float warpSum(float v){
    #pragma unroll
    for (int o=16;o;o>>=1) v += __shfl_xor_sync(0xffffffffu, v, o);
    return v;
}
__device__ __forceinline__ float warpMax(float v){
    #pragma unroll
    for (int o=16;o;o>>=1) v = fmaxf(v, __shfl_xor_sync(0xffffffffu, v, o));
    return v;
}
__device__ __forceinline__ float blockSum(float v){
    __shared__ float sh[33];
    __syncthreads();
    int lane = threadIdx.x & 31, wid = threadIdx.x >> 5;
    v = warpSum(v);
    if (lane == 0) sh[wid] = v;
    __syncthreads();
    int nw = (blockDim.x + 31) >> 5;
    float r = (threadIdx.x < nw) ? sh[threadIdx.x] : 0.0f;
    if (wid == 0) r = warpSum(r);
    if (threadIdx.x == 0) sh[32] = r;
    __syncthreads();
    return sh[32];
}
__device__ __forceinline__ float blockMax(float v){
    __shared__ float sh[33];
    __syncthreads();
    int lane = threadIdx.x & 31, wid = threadIdx.x >> 5;
    v = warpMax(v);
    if (lane == 0) sh[wid] = v;
    __syncthreads();
    int nw = (blockDim.x + 31) >> 5;
    float r = (threadIdx.x < nw) ? sh[threadIdx.x] : -INFINITY;
    if (wid == 0) r = warpMax(r);
    if (threadIdx.x == 0) sh[32] = r;
    __syncthreads();
    return sh[32];
}

// ---------------- SGEMM 128x128x8, 256 threads, 8x8 per thread ---------------
// C[M,N] (op) A[M,K] x B ;  TB: B is [N,K] row-major (NT), else B is [K,N] (NN)
// EPI: 0 = store, 1 = accumulate into C, 2 = relu(acc - bias[n]) store
template<bool TB, int EPI>
__global__ __launch_bounds__(256)
void gemm_kernel(const float* __restrict__ A, const float* __restrict__ B,
                 float* __restrict__ C, const float* __restrict__ bias,
                 int M, int N, int K, int lda, int ldb, int ldc,
                 int zdiv,
                 long long sA1, long long sA2,
                 long long sB1, long long sB2,
                 long long sC1, long long sC2)
{
    int z  = blockIdx.z;
    int zq = z / zdiv, zr = z % zdiv;
    A += zq*sA1 + zr*sA2;
    B += zq*sB1 + zr*sB2;
    C += zq*sC1 + zr*sC2;

    __shared__ __align__(16) float As[8*128];
    __shared__ __align__(16) float Bs[8*128];

    const int bm = blockIdx.y * 128;
    const int bn = blockIdx.x * 128;
    const int tid = threadIdx.x;
    const int tx = tid & 15;      // N direction
    const int ty = tid >> 4;      // M direction

    float acc[8][8];
    #pragma unroll
    for (int i=0;i<8;i++)
        #pragma unroll
        for (int j=0;j<8;j++) acc[i][j]=0.0f;

    const int arow = tid >> 1;         // 0..127
    const int acol = (tid & 1) * 4;    // 0 or 4

    for (int k0 = 0; k0 < K; k0 += 8) {
        // A tile: 128 rows x 8 k, store transposed As[k][m]
        {
            float4 av = *(const float4*)(A + (long long)(bm+arow)*lda + k0 + acol);
            As[(acol+0)*128 + arow] = av.x;
            As[(acol+1)*128 + arow] = av.y;
            As[(acol+2)*128 + arow] = av.z;
            As[(acol+3)*128 + arow] = av.w;
        }
        if (TB) {
            float4 bv = *(const float4*)(B + (long long)(bn+arow)*ldb + k0 + acol);
            Bs[(acol+0)*128 + arow] = bv.x;
            Bs[(acol+1)*128 + arow] = bv.y;
            Bs[(acol+2)*128 + arow] = bv.z;
            Bs[(acol+3)*128 + arow] = bv.w;
        } else {
            int krow = tid >> 5;           // 0..7
            int c    = (tid & 31) * 4;     // 0..124
            *(float4*)&Bs[krow*128 + c] =
                *(const float4*)(B + (long long)(k0+krow)*ldb + bn + c);
        }
        __syncthreads();

        #pragma unroll
        for (int k=0;k<8;k++){
            float4 a0 = *(const float4*)&As[k*128 + ty*8    ];
            float4 a1 = *(const float4*)&As[k*128 + ty*8 + 4];
            float4 b0 = *(const float4*)&Bs[k*128 + tx*8    ];
            float4 b1 = *(const float4*)&Bs[k*128 + tx*8 + 4];
            float ar[8] = {a0.x,a0.y,a0.z,a0.w,a1.x,a1.y,a1.z,a1.w};
            float br[8] = {b0.x,b0.y,b0.z,b0.w,b1.x,b1.y,b1.z,b1.w};
            #pragma unroll
            for (int i=0;i<8;i++)
                #pragma unroll
                for (int j=0;j<8;j++)
                    acc[i][j] += ar[i]*br[j];
        }
        __syncthreads();
    }

    float bregs[8];
    if (EPI == 2) {
        #pragma unroll
        for (int j=0;j<8;j++) bregs[j] = bias[bn + tx*8 + j];
    }

    #pragma unroll
    for (int i=0;i<8;i++){
        float* cp = C + (long long)(bm + ty*8 + i)*ldc + bn + tx*8;
        if (EPI == 0) {
            *(float4*)(cp  ) = make_float4(acc[i][0],acc[i][1],acc[i][2],acc[i][3]);
            *(float4*)(cp+4) = make_float4(acc[i][4],acc[i][5],acc[i][6],acc[i][7]);
        } else if (EPI == 1) {
            float4 o0 = *(const float4*)(cp), o1 = *(const float4*)(cp+4);
            o0.x += acc[i][0]; o0.y += acc[i][1]; o0.z += acc[i][2]; o0.w += acc[i][3];
            o1.x += acc[i][4]; o1.y += acc[i][5]; o1.z += acc[i][6]; o1.w += acc[i][7];
            *(float4*)(cp) = o0; *(float4*)(cp+4) = o1;
        } else {
            float4 o0, o1;
            o0.x = fmaxf(acc[i][0]-bregs[0], 0.f);
            o0.y = fmaxf(acc[i][1]-bregs[1], 0.f);
            o0.z = fmaxf(acc[i][2]-bregs[2], 0.f);
            o0.w = fmaxf(acc[i][3]-bregs[3], 0.f);
            o1.x = fmaxf(acc[i][4]-bregs[4], 0.f);
            o1.y = fmaxf(acc[i][5]-bregs[5], 0.f);
            o1.z = fmaxf(acc[i][6]-bregs[6], 0.f);
            o1.w = fmaxf(acc[i][7]-bregs[7], 0.f);
            *(float4*)(cp) = o0; *(float4*)(cp+4) = o1;
        }
    }
}

// ---------------- elementwise kernels ---------------------------------------
// x = rmsnorm(wte[idx]); x0 = x.   grid=NTOK blocks, 256 threads
__global__ void embed_norm_kernel(const int* __restrict__ idx,
                                  const float* __restrict__ wte,
                                  float* __restrict__ x, float* __restrict__ x0)
{
    int t = blockIdx.x;
    int tok = idx[t];
    const float* row = wte + (long long)tok * Ee;
    long long base = (long long)t * Ee;
    float v[3]; float ss = 0.f;
    #pragma unroll
    for (int j=0;j<3;j++){ int c = threadIdx.x + j*256; float m = row[c]; v[j]=m; ss += m*m; }
    ss = blockSum(ss);
    float inv = rsqrtf(ss*(1.0f/Ee) + EPS);
    #pragma unroll
    for (int j=0;j<3;j++){ int c = threadIdx.x + j*256; float o = v[j]*inv; x[base+c]=o; x0[base+c]=o; }
}

// x = rl*x + xl*x0 (in-place); h = rmsnorm(x).   grid=NTOK, 256 threads
__global__ void mix_norm_kernel(float* __restrict__ x, const float* __restrict__ x0,
                                float* __restrict__ h,
                                const float* lamr, const float* lamx, int li)
{
    int t = blockIdx.x;
    float rl = lamr ? lamr[li] : 1.0f;
    float xl = lamx ? lamx[li] : 0.0f;
    long long base = (long long)t * Ee;
    float v[3]; float ss = 0.f;
    #pragma unroll
    for (int j=0;j<3;j++){
        int c = threadIdx.x + j*256;
        float m = rl*x[base+c] + xl*x0[base+c];
        v[j]=m; ss += m*m;
    }
    ss = blockSum(ss);
    float inv = rsqrtf(ss*(1.0f/Ee) + EPS);
    #pragma unroll
    for (int j=0;j<3;j++){
        int c = threadIdx.x + j*256;
        x[base+c] = v[j];
        h[base+c] = v[j]*inv;
    }
}

// rope + per-head rmsnorm, in place on w.  grid = NTOK*H blocks, 128 threads.
// (rope preserves per-pair sum of squares, so rms is computed pre-rope.)
__global__ void rope_norm_kernel(float* __restrict__ w)
{
    int n  = blockIdx.x / Hh;       // token index 0..4095
    int hh = blockIdx.x % Hh;
    int t  = n & (Tt-1);            // position within sequence
    float* base = w + (long long)n*Ee + hh*HDd;
    int d = threadIdx.x;            // 0..127
    __shared__ float s[HDd];
    float v = base[d];
    s[d] = v;
    float ss = blockSum(v*v);       // contains syncthreads; s[] visible after
    float inv = rsqrtf(ss*(1.0f/HDd) + EPS);
    float out;
    if (d < 64) {
        int j = d;
        float x1 = s[j], x2 = s[j+64];
        float fr = (float)t * powf(10000.0f, -((float)(2*j)) * (1.0f/128.0f));
        out = (x1*cosf(fr) + x2*sinf(fr)) * inv;
    } else {
        int j = d - 64;
        float x1 = s[j], x2 = s[d];
        float fr = (float)t * powf(10000.0f, -((float)(2*j)) * (1.0f/128.0f));
        out = (-x1*sinf(fr) + x2*cosf(fr)) * inv;
    }
    base[d] = out;
}

// causal softmax over dots rows. grid = B*H*T blocks (layout [z][q][k]), 256 thr.
__global__ void softmax_kernel(float* __restrict__ dots, float scale)
{
    long long r = blockIdx.x;            // z*T + q
    int q = (int)(r & (Tt-1));
    float* row = dots + r * Tt;
    int nv = q + 1;
    float vals[4];
    float m = -INFINITY;
    #pragma unroll
    for (int it=0; it<4; it++){
        int k = threadIdx.x + it*256;
        float v = (k < nv) ? row[k]*scale : -INFINITY;
        vals[it] = v;
        m = fmaxf(m, v);
    }
    m = blockMax(m);
    float sum = 0.f;
    #pragma unroll
    for (int it=0; it<4; it++){
        int k = threadIdx.x + it*256;
        float e = (k < nv) ? expf(vals[it]-m) : 0.0f;
        vals[it] = e; sum += e;
    }
    sum = blockSum(sum);
    float invs = 1.0f / sum;
    #pragma unroll
    for (int it=0; it<4; it++){
        int k = threadIdx.x + it*256;
        row[k] = vals[it]*invs;
    }
}

// ---------------- host-side launch helpers -----------------------------------
typedef long long ll;

static void launch_gemm(bool tb, int epi,
                        const float* A, const float* B, float* C, const float* bias,
                        int M, int N, int K, int lda, int ldb, int ldc,
                        int batch, int zdiv,
                        ll sA1, ll sA2, ll sB1, ll sB2, ll sC1, ll sC2)
{
    dim3 grid(N/128, M/128, batch);
    dim3 blk(256);
    if (tb) {
        if      (epi==0) gemm_kernel<true ,0><<<grid,blk>>>(A,B,C,bias,M,N,K,lda,ldb,ldc,zdiv,sA1,sA2,sB1,sB2,sC1,sC2);
        else if (epi==1) gemm_kernel<true ,1><<<grid,blk>>>(A,B,C,bias,M,N,K,lda,ldb,ldc,zdiv,sA1,sA2,sB1,sB2,sC1,sC2);
        else             gemm_kernel<true ,2><<<grid,blk>>>(A,B,C,bias,M,N,K,lda,ldb,ldc,zdiv,sA1,sA2,sB1,sB2,sC1,sC2);
    } else {
        if      (epi==0) gemm_kernel<false,0><<<grid,blk>>>(A,B,C,bias,M,N,K,lda,ldb,ldc,zdiv,sA1,sA2,sB1,sB2,sC1,sC2);
        else if (epi==1) gemm_kernel<false,1><<<grid,blk>>>(A,B,C,bias,M,N,K,lda,ldb,ldc,zdiv,sA1,sA2,sB1,sB2,sC1,sC2);
        else             gemm_kernel<false,2><<<grid,blk>>>(A,B,C,bias,M,N,K,lda,ldb,ldc,zdiv,sA1,sA2,sB1,sB2,sC1,sC2);
    }
}

extern "C" void kernel_launch(void* const* d_in, const int* in_sizes, int n_in,
                              void* d_out, int out_size)
{
    const int*   idx  = (const int*)  d_in[0];
    const float* wte  = (const float*)d_in[1];
    const float* lmh  = (const float*)d_in[2];
    const float* qkvw = (const float*)d_in[3];
    const float* cpjw = (const float*)d_in[4];
    const float* denc = (const float*)d_in[5];
    const float* ddec = (const float*)d_in[6];
    const float* thr  = (const float*)d_in[7];
    const float* lamr = (const float*)d_in[8];
    const float* lamx = (const float*)d_in[9];
    float* out = (float*)d_out;

    float *x, *x0, *h, *w, *o, *a, *dots;
    cudaGetSymbolAddress((void**)&x,    g_x);
    cudaGetSymbolAddress((void**)&x0,   g_x0);
    cudaGetSymbolAddress((void**)&h,    g_h);
    cudaGetSymbolAddress((void**)&w,    g_w);
    cudaGetSymbolAddress((void**)&o,    g_o);
    cudaGetSymbolAddress((void**)&a,    g_a);
    cudaGetSymbolAddress((void**)&dots, g_dots);

    const float scale = 0.08838834764831845f;   // HD^-0.5
    const ll TE = (ll)Tt*Ee;
    const ll TT = (ll)Tt*Tt;

    embed_norm_kernel<<<NTOK,256>>>(idx, wte, x, x0);

    for (int i=0;i<Ll;i++){
        // x = rl*x + xl*x0 ; h = rmsnorm(x)
        mix_norm_kernel<<<NTOK,256>>>(x, x0, h, lamr, lamx, i);

        // w = h @ qkv_w[i]^T
        launch_gemm(true,0, h, qkvw + (ll)i*Ee*Ee, w, nullptr,
                    NTOK, Ee, Ee, Ee, Ee, Ee, 1,1, 0,0,0,0,0,0);

        // rope + head rmsnorm in place
        rope_norm_kernel<<<NTOK*Hh,128>>>(w);

        // dots[z] = Wz Wz^T   (z = b*H + h), batched NT
        launch_gemm(true,0, w, w, dots, nullptr,
                    Tt, Tt, HDd, Ee, Ee, Tt, Bb*Hh, Hh,
                    TE, HDd, TE, HDd, (ll)Hh*TT, TT);

        // causal softmax (scale folded in)
        softmax_kernel<<<Bb*Hh*Tt,256>>>(dots, scale);

        // o[z] = P[z] @ V[z]   batched NN
        launch_gemm(false,0, dots, w, o, nullptr,
                    Tt, HDd, Tt, Tt, Ee, Ee, Bb*Hh, Hh,
                    (ll)Hh*TT, TT, TE, HDd, TE, HDd);

        // x += o @ cproj_w[i]^T
        launch_gemm(true,1, o, cpjw + (ll)i*Ee*Ee, x, nullptr,
                    NTOK, Ee, Ee, Ee, Ee, Ee, 1,1, 0,0,0,0,0,0);

        // h = rmsnorm(x)
        mix_norm_kernel<<<NTOK,256>>>(x, x0, h, nullptr, nullptr, 0);

        // a = relu(h @ denc_w[i]^T - thr[i])
        launch_gemm(true,2, h, denc + (ll)i*HIDh*Ee, a, thr + (ll)i*HIDh,
                    NTOK, HIDh, Ee, Ee, Ee, HIDh, 1,1, 0,0,0,0,0,0);

        // x += a @ ddec_w[i]^T
        launch_gemm(true,1, a, ddec + (ll)i*Ee*HIDh, x, nullptr,
                    NTOK, Ee, HIDh, HIDh, HIDh, Ee, 1,1, 0,0,0,0,0,0);
    }

    // final norm + lm head
    mix_norm_kernel<<<NTOK,256>>>(x, x0, h, nullptr, nullptr, 0);
    launch_gemm(true,0, h, lmh, out, nullptr,
                NTOK, Vv, Ee, Ee, Ee, Vv, 1,1, 0,0,0,0,0,0);
}

// round 4
// speedup vs baseline: 2.4717x; 2.4717x over previous
#include <cuda_runtime.h>
#include <cuda_bf16.h>
#include <math.h>
#include <stdint.h>

#define Bb 4
#define Tt 1024
#define Vv 50304
#define Ee 768
#define Ll 12
#define Hh 6
#define HDd 128
#define HIDh 3072
#define NTOK (Bb*Tt)
#define EPS 1e-6f
typedef long long ll;
typedef __nv_bfloat16 bf16;

// ---------------- scratch ----------------------------------------------------
__device__ float g_x [NTOK*Ee];
__device__ float g_x0[NTOK*Ee];
__device__ float g_w [NTOK*Ee];
__device__ float g_dots[(ll)Bb*Hh*Tt*Tt];

__device__ bf16 g_hh[NTOK*Ee],  g_hl[NTOK*Ee];
__device__ bf16 g_wh[NTOK*Ee],  g_wl[NTOK*Ee];
__device__ bf16 g_wth[Bb*Hh*HDd*Tt], g_wtl[Bb*Hh*HDd*Tt];
__device__ bf16 g_ph[(ll)Bb*Hh*Tt*Tt], g_pl[(ll)Bb*Hh*Tt*Tt];
__device__ bf16 g_oh[NTOK*Ee],  g_ol[NTOK*Ee];
__device__ bf16 g_ah[NTOK*HIDh], g_al[NTOK*HIDh];

__device__ bf16 g_qkvh[Ll*Ee*Ee],   g_qkvl[Ll*Ee*Ee];
__device__ bf16 g_cpjh[Ll*Ee*Ee],   g_cpjl[Ll*Ee*Ee];
__device__ bf16 g_dech[Ll*HIDh*Ee], g_decl[Ll*HIDh*Ee];
__device__ bf16 g_ddh[Ll*Ee*HIDh],  g_ddl[Ll*Ee*HIDh];
__device__ bf16 g_lmhh[(ll)Vv*Ee],  g_lmhl[(ll)Vv*Ee];

// ---------------- helpers -----------------------------------------------------
__device__ __forceinline__ uint32_t smem_u32(const void* p){
    uint32_t a;
    asm("{ .reg .u64 t; cvta.to.shared.u64 t, %1; cvt.u32.u64 %0, t; }" : "=r"(a) : "l"(p));
    return a;
}
__device__ __forceinline__ void cp16(uint32_t dst, const void* src){
    asm volatile("cp.async.cg.shared.global [%0], [%1], 16;" :: "r"(dst), "l"(src));
}
#define CP_COMMIT() asm volatile("cp.async.commit_group;" ::: "memory")
#define CP_WAIT1()  asm volatile("cp.async.wait_group 1;" ::: "memory")

__device__ __forceinline__ void ldm4(uint32_t a, uint32_t& r0, uint32_t& r1, uint32_t& r2, uint32_t& r3){
    asm volatile("ldmatrix.sync.aligned.m8n8.x4.shared.b16 {%0,%1,%2,%3}, [%4];"
        : "=r"(r0), "=r"(r1), "=r"(r2), "=r"(r3) : "r"(a));
}
__device__ __forceinline__ void mma16816(float* c, const uint32_t* a, const uint32_t* b){
    asm volatile("mma.sync.aligned.m16n8k16.row.col.f32.bf16.bf16.f32 "
        "{%0,%1,%2,%3}, {%4,%5,%6,%7}, {%8,%9}, {%0,%1,%2,%3};"
        : "+f"(c[0]), "+f"(c[1]), "+f"(c[2]), "+f"(c[3])
        : "r"(a[0]), "r"(a[1]), "r"(a[2]), "r"(a[3]), "r"(b[0]), "r"(b[1]));
}
__device__ __forceinline__ void split2(float v, bf16& h, bf16& l){
    h = __float2bfloat16(v);
    l = __float2bfloat16(v - __bfloat162float(h));
}

// ---------------- reductions -------------------------------------------------
__device__ __forceinline__ float warpSum(float v){
    #pragma unroll
    for (int o=16;o;o>>=1) v += __shfl_xor_sync(0xffffffffu, v, o);
    return v;
}
__device__ __forceinline__ float warpMax(float v){
    #pragma unroll
    for (int o=16;o;o>>=1) v = fmaxf(v, __shfl_xor_sync(0xffffffffu, v, o));
    return v;
}
__device__ __forceinline__ float blockSum(float v){
    __shared__ float sh[33];
    __syncthreads();
    int lane = threadIdx.x & 31, wid = threadIdx.x >> 5;
    v = warpSum(v);
    if (lane == 0) sh[wid] = v;
    __syncthreads();
    int nw = (blockDim.x + 31) >> 5;
    float r = (threadIdx.x < nw) ? sh[threadIdx.x] : 0.0f;
    if (wid == 0) r = warpSum(r);
    if (threadIdx.x == 0) sh[32] = r;
    __syncthreads();
    return sh[32];
}
__device__ __forceinline__ float blockMax(float v){
    __shared__ float sh[33];
    __syncthreads();
    int lane = threadIdx.x & 31, wid = threadIdx.x >> 5;
    v = warpMax(v);
    if (lane == 0) sh[wid] = v;
    __syncthreads();
    int nw = (blockDim.x + 31) >> 5;
    float r = (threadIdx.x < nw) ? sh[threadIdx.x] : -INFINITY;
    if (wid == 0) r = warpMax(r);
    if (threadIdx.x == 0) sh[32] = r;
    __syncthreads();
    return sh[32];
}

// ---------------- HMMA GEMM ----------------------------------------------------
// C[M,N] = A[M,K] @ B[N,K]^T with hi/lo bf16 split (3 products -> fp32 accuracy).
// Block 128x128, 8 warps of 64x32, mma.m16n8k16, KC=32, 3-stage cp.async.
// EPI: 0 store f32, 1 accumulate f32, 2 relu(acc-bias[n]) split store, 3 split store
static constexpr int PITCH  = 40;             // bf16 elems per smem row (80B, 16B-aligned, ldmatrix conflict-free)
static constexpr int TILEB2 = 128*PITCH*2;    // 10240 B
static constexpr int STAGEB = 4*TILEB2;       // Ah, Al, Bh, Bl
static constexpr int NSTG   = 3;
static constexpr int DSZ    = NSTG*STAGEB;    // 122880 B

__device__ __forceinline__ void load_tile(uint32_t dst, const bf16* src, int r0, int k0, int ld, int tid){
    #pragma unroll
    for (int j=0;j<2;j++){
        int slot = tid + j*256;
        int row = slot >> 2;
        int seg = slot & 3;
        cp16(dst + row*80 + seg*16, src + (ll)(r0+row)*ld + k0 + seg*8);
    }
}
__device__ __forceinline__ void load_chunk(uint32_t sbase,
    const bf16* Ah, const bf16* Al, const bf16* Bh, const bf16* Bl,
    int bm, int bn, int k0, int lda, int ldb, int tid)
{
    load_tile(sbase,            Ah, bm, k0, lda, tid);
    load_tile(sbase +   TILEB2, Al, bm, k0, lda, tid);
    load_tile(sbase + 2*TILEB2, Bh, bn, k0, ldb, tid);
    load_tile(sbase + 3*TILEB2, Bl, bn, k0, ldb, tid);
}

template<int EPI, bool TRI, bool KLIM>
__global__ void __launch_bounds__(256,1) gemm_mm(
    const bf16* __restrict__ Ahi, const bf16* __restrict__ Alo,
    const bf16* __restrict__ Bhi, const bf16* __restrict__ Blo,
    float* __restrict__ C, bf16* __restrict__ Chi, bf16* __restrict__ Clo,
    const float* __restrict__ bias,
    int K, int lda, int ldb, int ldc, int zdiv,
    ll sA1, ll sA2, ll sB1, ll sB2, ll sC1, ll sC2)
{
    extern __shared__ char dsm[];
    uint32_t sb = smem_u32(dsm);

    int z  = blockIdx.z;
    int zq = z / zdiv, zr = z % zdiv;
    Ahi += zq*sA1 + zr*sA2; Alo += zq*sA1 + zr*sA2;
    Bhi += zq*sB1 + zr*sB2; Blo += zq*sB1 + zr*sB2;
    if (EPI==0 || EPI==1) { C += zq*sC1 + zr*sC2; }
    else { Chi += zq*sC1 + zr*sC2; Clo += zq*sC1 + zr*sC2; }

    int bm, bn;
    if (TRI) {
        int idx = blockIdx.x;
        int i_ = (int)((sqrtf(8.f*(float)idx + 1.f) - 1.f) * 0.5f);
        while ((i_+1)*(i_+2)/2 <= idx) i_++;
        while (i_*(i_+1)/2 > idx) i_--;
        bm = i_*128; bn = (idx - i_*(i_+1)/2)*128;
    } else { bm = blockIdx.y*128; bn = blockIdx.x*128; }

    int kmax = KLIM ? min(K, bm + 128) : K;
    int nch  = kmax >> 5;                      // KC = 32
    const int tid  = threadIdx.x;
    const int lane = tid & 31;
    const int wid  = tid >> 5;
    const int wm   = wid >> 2;                 // 0..1
    const int wn   = wid & 3;                  // 0..3

    float acc[4][4][4];
    #pragma unroll
    for (int i=0;i<4;i++)
        #pragma unroll
        for (int j=0;j<4;j++)
            #pragma unroll
            for (int q=0;q<4;q++) acc[i][j][q]=0.f;

    // prologue: prefetch 2 chunks
    int pre = nch < 2 ? nch : 2;
    for (int j=0;j<pre;j++){
        load_chunk(sb + (j%NSTG)*STAGEB, Ahi,Alo,Bhi,Blo, bm,bn, j*32, lda,ldb, tid);
        CP_COMMIT();
    }
    for (int j=pre;j<2;j++) CP_COMMIT();

    // ldmatrix lane addressing (offsets within a tile)
    const int a_row  = (lane & 15);
    const int a_colb = ((lane >> 4) << 3) * 2;            // bytes
    const int b_rowo = ((lane >> 4) << 3) + (lane & 7);
    const int b_colb = (((lane >> 3) & 1) << 3) * 2;      // bytes

    for (int i=0;i<nch;i++){
        CP_WAIT1();
        __syncthreads();
        uint32_t st = sb + (i%NSTG)*STAGEB;
        // prefetch chunk i+2 into buffer (i+2)%NSTG (freed by barrier above)
        if (i + 2 < nch) {
            load_chunk(sb + ((i+2)%NSTG)*STAGEB, Ahi,Alo,Bhi,Blo, bm,bn, (i+2)*32, lda,ldb, tid);
        }
        CP_COMMIT();

        uint32_t Abh = st, Abl = st + TILEB2, Bbh = st + 2*TILEB2, Bbl = st + 3*TILEB2;
        #pragma unroll
        for (int kk=0; kk<2; kk++){
            const int kb = kk*16*2;   // byte offset of k16 half
            uint32_t ah[4][4], al[4][4], bh[4][2], blr[4][2];
            #pragma unroll
            for (int mt=0; mt<4; mt++){
                uint32_t off = (uint32_t)(wm*64 + mt*16 + a_row)*80 + kb + a_colb;
                ldm4(Abh + off, ah[mt][0], ah[mt][1], ah[mt][2], ah[mt][3]);
                ldm4(Abl + off, al[mt][0], al[mt][1], al[mt][2], al[mt][3]);
            }
            #pragma unroll
            for (int np=0; np<2; np++){
                uint32_t off = (uint32_t)(wn*32 + np*16 + b_rowo)*80 + kb + b_colb;
                uint32_t r0,r1,r2,r3;
                ldm4(Bbh + off, r0,r1,r2,r3);
                bh[2*np][0]=r0; bh[2*np][1]=r1; bh[2*np+1][0]=r2; bh[2*np+1][1]=r3;
                ldm4(Bbl + off, r0,r1,r2,r3);
                blr[2*np][0]=r0; blr[2*np][1]=r1; blr[2*np+1][0]=r2; blr[2*np+1][1]=r3;
            }
            #pragma unroll
            for (int mt=0; mt<4; mt++)
                #pragma unroll
                for (int nt=0; nt<4; nt++){
                    mma16816(acc[mt][nt], ah[mt], bh[nt]);
                    mma16816(acc[mt][nt], ah[mt], blr[nt]);
                    mma16816(acc[mt][nt], al[mt], bh[nt]);
                }
        }
        __syncthreads();
    }

    // epilogue
    #pragma unroll
    for (int mt=0; mt<4; mt++){
        #pragma unroll
        for (int nt=0; nt<4; nt++){
            int m0 = bm + wm*64 + mt*16 + (lane >> 2);
            int n0 = bn + wn*32 + nt*8  + (lane & 3)*2;
            float c0 = acc[mt][nt][0], c1 = acc[mt][nt][1];
            float c2 = acc[mt][nt][2], c3 = acc[mt][nt][3];
            if (EPI == 0) {
                *(float2*)(C + (ll)m0*ldc + n0)     = make_float2(c0, c1);
                *(float2*)(C + (ll)(m0+8)*ldc + n0) = make_float2(c2, c3);
            } else if (EPI == 1) {
                float2 o0 = *(const float2*)(C + (ll)m0*ldc + n0);
                float2 o1 = *(const float2*)(C + (ll)(m0+8)*ldc + n0);
                *(float2*)(C + (ll)m0*ldc + n0)     = make_float2(o0.x+c0, o0.y+c1);
                *(float2*)(C + (ll)(m0+8)*ldc + n0) = make_float2(o1.x+c2, o1.y+c3);
            } else {
                if (EPI == 2) {
                    float b0 = __ldg(bias + n0), b1 = __ldg(bias + n0 + 1);
                    c0 = fmaxf(c0-b0, 0.f); c1 = fmaxf(c1-b1, 0.f);
                    c2 = fmaxf(c2-b0, 0.f); c3 = fmaxf(c3-b1, 0.f);
                }
                bf16 h0,l0,h1,l1;
                split2(c0,h0,l0); split2(c1,h1,l1);
                __nv_bfloat162 hv; hv.x=h0; hv.y=h1;
                __nv_bfloat162 lv; lv.x=l0; lv.y=l1;
                *(__nv_bfloat162*)(Chi + (ll)m0*ldc + n0) = hv;
                *(__nv_bfloat162*)(Clo + (ll)m0*ldc + n0) = lv;
                split2(c2,h0,l0); split2(c3,h1,l1);
                hv.x=h0; hv.y=h1; lv.x=l0; lv.y=l1;
                *(__nv_bfloat162*)(Chi + (ll)(m0+8)*ldc + n0) = hv;
                *(__nv_bfloat162*)(Clo + (ll)(m0+8)*ldc + n0) = lv;
            }
        }
    }
}

// ---------------- elementwise kernels ----------------------------------------
__global__ void embed_norm_kernel(const int* __restrict__ idx,
                                  const float* __restrict__ wte,
                                  float* __restrict__ x, float* __restrict__ x0)
{
    int t = blockIdx.x;
    int tok = idx[t];
    const float* row = wte + (ll)tok * Ee;
    ll base = (ll)t * Ee;
    float v[3]; float ss = 0.f;
    #pragma unroll
    for (int j=0;j<3;j++){ int c = threadIdx.x + j*256; float m = row[c]; v[j]=m; ss += m*m; }
    ss = blockSum(ss);
    float inv = rsqrtf(ss*(1.0f/Ee) + EPS);
    #pragma unroll
    for (int j=0;j<3;j++){ int c = threadIdx.x + j*256; float o = v[j]*inv; x[base+c]=o; x0[base+c]=o; }
}

__global__ void mix_norm_split(float* __restrict__ x, const float* __restrict__ x0,
                               bf16* __restrict__ hh, bf16* __restrict__ hl,
                               const float* lamr, const float* lamx, int li)
{
    int t = blockIdx.x;
    float rl = lamr ? lamr[li] : 1.0f;
    float xl = lamx ? lamx[li] : 0.0f;
    ll base = (ll)t * Ee;
    float v[3]; float ss = 0.f;
    #pragma unroll
    for (int j=0;j<3;j++){
        int c = threadIdx.x + j*256;
        float m = rl*x[base+c] + xl*x0[base+c];
        v[j]=m; ss += m*m;
    }
    ss = blockSum(ss);
    float inv = rsqrtf(ss*(1.0f/Ee) + EPS);
    #pragma unroll
    for (int j=0;j<3;j++){
        int c = threadIdx.x + j*256;
        x[base+c] = v[j];
        bf16 h, l; split2(v[j]*inv, h, l);
        hh[base+c] = h; hl[base+c] = l;
    }
}

__global__ void rope_split_kernel(const float* __restrict__ wf,
                                  bf16* __restrict__ wh, bf16* __restrict__ wl)
{
    int n  = blockIdx.x / Hh;
    int hh = blockIdx.x % Hh;
    int t  = n & (Tt-1);
    const float* base = wf + (ll)n*Ee + hh*HDd;
    int d = threadIdx.x;
    __shared__ float s[HDd];
    float v = base[d];
    s[d] = v;
    float ss = blockSum(v*v);
    float inv = rsqrtf(ss*(1.0f/HDd) + EPS);
    float out;
    if (d < 64) {
        int j = d;
        float x1 = s[j], x2 = s[j+64];
        float fr = (float)t * powf(10000.0f, -((float)(2*j)) * (1.0f/128.0f));
        out = (x1*cosf(fr) + x2*sinf(fr)) * inv;
    } else {
        int j = d - 64;
        float x1 = s[j], x2 = s[d];
        float fr = (float)t * powf(10000.0f, -((float)(2*j)) * (1.0f/128.0f));
        out = (-x1*sinf(fr) + x2*cosf(fr)) * inv;
    }
    bf16 h, l; split2(out, h, l);
    ll o = (ll)n*Ee + hh*HDd + d;
    wh[o] = h; wl[o] = l;
}

__global__ void transpose_hd(const bf16* __restrict__ whi, const bf16* __restrict__ wlo,
                             bf16* __restrict__ othi, bf16* __restrict__ otlo)
{
    __shared__ bf16 tile[32][33];
    int z = blockIdx.z; int b = z / Hh, h = z % Hh;
    int t0 = blockIdx.x*32, d0 = blockIdx.y*32;
    #pragma unroll
    for (int pass=0; pass<2; pass++){
        const bf16* src = pass ? wlo : whi;
        bf16* dst = pass ? otlo : othi;
        for (int j=(int)threadIdx.y; j<32; j+=8)
            tile[j][threadIdx.x] = src[(ll)(b*Tt + t0 + j)*Ee + h*HDd + d0 + threadIdx.x];
        __syncthreads();
        for (int j=(int)threadIdx.y; j<32; j+=8)
            dst[(ll)z*HDd*Tt + (ll)(d0 + j)*Tt + t0 + threadIdx.x] = tile[threadIdx.x][j];
        __syncthreads();
    }
}

__global__ void softmax_split_kernel(const float* __restrict__ dots,
                                     bf16* __restrict__ ph, bf16* __restrict__ pl,
                                     float scale)
{
    ll r = blockIdx.x;
    int q = (int)(r & (Tt-1));
    const float* row = dots + r * Tt;
    bf16* hrow = ph + r * Tt;
    bf16* lrow = pl + r * Tt;
    int nv = q + 1;
    float vals[4];
    float m = -INFINITY;
    #pragma unroll
    for (int it=0; it<4; it++){
        int k = threadIdx.x + it*256;
        float v = (k < nv) ? row[k]*scale : -INFINITY;
        vals[it] = v;
        m = fmaxf(m, v);
    }
    m = blockMax(m);
    float sum = 0.f;
    #pragma unroll
    for (int it=0; it<4; it++){
        int k = threadIdx.x + it*256;
        float e = (k < nv) ? expf(vals[it]-m) : 0.0f;
        vals[it] = e; sum += e;
    }
    sum = blockSum(sum);
    float invs = 1.0f / sum;
    #pragma unroll
    for (int it=0; it<4; it++){
        int k = threadIdx.x + it*256;
        bf16 h, l; split2(vals[it]*invs, h, l);
        hrow[k] = h; lrow[k] = l;
    }
}

__global__ void split_f32(const float* __restrict__ in, bf16* __restrict__ hi,
                          bf16* __restrict__ lo, ll n)
{
    ll i = ((ll)blockIdx.x*blockDim.x + threadIdx.x)*4;
    if (i >= n) return;
    float4 v = *(const float4*)(in + i);
    bf16 h0,l0,h1,l1,h2,l2,h3,l3;
    split2(v.x,h0,l0); split2(v.y,h1,l1); split2(v.z,h2,l2); split2(v.w,h3,l3);
    __nv_bfloat162 a; a.x=h0; a.y=h1; __nv_bfloat162 b; b.x=h2; b.y=h3;
    __nv_bfloat162 c; c.x=l0; c.y=l1; __nv_bfloat162 d; d.x=l2; d.y=l3;
    *(__nv_bfloat162*)(hi+i)   = a; *(__nv_bfloat162*)(hi+i+2) = b;
    *(__nv_bfloat162*)(lo+i)   = c; *(__nv_bfloat162*)(lo+i+2) = d;
}

// ---------------- host ---------------------------------------------------------
extern "C" void kernel_launch(void* const* d_in, const int* in_sizes, int n_in,
                              void* d_out, int out_size)
{
    const int*   idx  = (const int*)  d_in[0];
    const float* wte  = (const float*)d_in[1];
    const float* lmh  = (const float*)d_in[2];
    const float* qkvw = (const float*)d_in[3];
    const float* cpjw = (const float*)d_in[4];
    const float* denc = (const float*)d_in[5];
    const float* ddec = (const float*)d_in[6];
    const float* thr  = (const float*)d_in[7];
    const float* lamr = (const float*)d_in[8];
    const float* lamx = (const float*)d_in[9];
    float* out = (float*)d_out;

    cudaFuncSetAttribute(gemm_mm<0,false,false>, cudaFuncAttributeMaxDynamicSharedMemorySize, DSZ);
    cudaFuncSetAttribute(gemm_mm<0,true ,false>, cudaFuncAttributeMaxDynamicSharedMemorySize, DSZ);
    cudaFuncSetAttribute(gemm_mm<1,false,false>, cudaFuncAttributeMaxDynamicSharedMemorySize, DSZ);
    cudaFuncSetAttribute(gemm_mm<2,false,false>, cudaFuncAttributeMaxDynamicSharedMemorySize, DSZ);
    cudaFuncSetAttribute(gemm_mm<3,false,true >, cudaFuncAttributeMaxDynamicSharedMemorySize, DSZ);

    float *x, *x0, *wf, *dots;
    cudaGetSymbolAddress((void**)&x,    g_x);
    cudaGetSymbolAddress((void**)&x0,   g_x0);
    cudaGetSymbolAddress((void**)&wf,   g_w);
    cudaGetSymbolAddress((void**)&dots, g_dots);
    bf16 *hh,*hl,*wh,*wl,*wth,*wtl,*ph,*pl,*oh,*ol,*ah,*al;
    cudaGetSymbolAddress((void**)&hh,  g_hh);  cudaGetSymbolAddress((void**)&hl,  g_hl);
    cudaGetSymbolAddress((void**)&wh,  g_wh);  cudaGetSymbolAddress((void**)&wl,  g_wl);
    cudaGetSymbolAddress((void**)&wth, g_wth); cudaGetSymbolAddress((void**)&wtl, g_wtl);
    cudaGetSymbolAddress((void**)&ph,  g_ph);  cudaGetSymbolAddress((void**)&pl,  g_pl);
    cudaGetSymbolAddress((void**)&oh,  g_oh);  cudaGetSymbolAddress((void**)&ol,  g_ol);
    cudaGetSymbolAddress((void**)&ah,  g_ah);  cudaGetSymbolAddress((void**)&al,  g_al);
    bf16 *qh,*ql,*ch,*cl,*eh,*el,*dh,*dl,*lh,*llo;
    cudaGetSymbolAddress((void**)&qh, g_qkvh); cudaGetSymbolAddress((void**)&ql, g_qkvl);
    cudaGetSymbolAddress((void**)&ch, g_cpjh); cudaGetSymbolAddress((void**)&cl, g_cpjl);
    cudaGetSymbolAddress((void**)&eh, g_dech); cudaGetSymbolAddress((void**)&el, g_decl);
    cudaGetSymbolAddress((void**)&dh, g_ddh);  cudaGetSymbolAddress((void**)&dl, g_ddl);
    cudaGetSymbolAddress((void**)&lh, g_lmhh); cudaGetSymbolAddress((void**)&llo, g_lmhl);

    {
        ll n;
        n = (ll)Ll*Ee*Ee;    split_f32<<<(int)((n/4+255)/256),256>>>(qkvw, qh, ql, n);
        n = (ll)Ll*Ee*Ee;    split_f32<<<(int)((n/4+255)/256),256>>>(cpjw, ch, cl, n);
        n = (ll)Ll*HIDh*Ee;  split_f32<<<(int)((n/4+255)/256),256>>>(denc, eh, el, n);
        n = (ll)Ll*Ee*HIDh;  split_f32<<<(int)((n/4+255)/256),256>>>(ddec, dh, dl, n);
        n = (ll)Vv*Ee;       split_f32<<<(int)((n/4+255)/256),256>>>(lmh,  lh, llo, n);
    }

    const float scale = 0.08838834764831845f;
    const ll TE = (ll)Tt*Ee;
    const ll TT = (ll)Tt*Tt;
    const ll WT = (ll)HDd*Tt;

    embed_norm_kernel<<<NTOK,256>>>(idx, wte, x, x0);

    for (int i=0;i<Ll;i++){
        mix_norm_split<<<NTOK,256>>>(x, x0, hh, hl, lamr, lamx, i);

        // w = h @ qkv^T (fp32 out for rope)
        gemm_mm<0,false,false><<<dim3(6,32,1),256,DSZ>>>(
            hh, hl, qh + (ll)i*Ee*Ee, ql + (ll)i*Ee*Ee,
            wf, nullptr, nullptr, nullptr,
            Ee, Ee, Ee, Ee, 1, 0,0, 0,0, 0,0);

        rope_split_kernel<<<NTOK*Hh,128>>>(wf, wh, wl);
        transpose_hd<<<dim3(Tt/32, HDd/32, Bb*Hh), dim3(32,8)>>>(wh, wl, wth, wtl);

        // dots = W W^T (lower-triangular tiles only)
        gemm_mm<0,true,false><<<dim3(36,1,Bb*Hh),256,DSZ>>>(
            wh, wl, wh, wl,
            dots, nullptr, nullptr, nullptr,
            HDd, Ee, Ee, Tt, Hh, TE,(ll)HDd, TE,(ll)HDd, (ll)Hh*TT, TT);

        softmax_split_kernel<<<Bb*Hh*Tt,256>>>(dots, ph, pl, scale);

        // o = P @ W (K limited to bm+128), split output
        gemm_mm<3,false,true><<<dim3(1,8,Bb*Hh),256,DSZ>>>(
            ph, pl, wth, wtl,
            nullptr, oh, ol, nullptr,
            Tt, Tt, Tt, Ee, Hh, (ll)Hh*TT,TT, (ll)Hh*WT,WT, TE,(ll)HDd);

        // x += o @ cproj^T
        gemm_mm<1,false,false><<<dim3(6,32,1),256,DSZ>>>(
            oh, ol, ch + (ll)i*Ee*Ee, cl + (ll)i*Ee*Ee,
            x, nullptr, nullptr, nullptr,
            Ee, Ee, Ee, Ee, 1, 0,0, 0,0, 0,0);

        mix_norm_split<<<NTOK,256>>>(x, x0, hh, hl, nullptr, nullptr, 0);

        // a = relu(h @ denc^T - thr), split output
        gemm_mm<2,false,false><<<dim3(24,32,1),256,DSZ>>>(
            hh, hl, eh + (ll)i*HIDh*Ee, el + (ll)i*HIDh*Ee,
            nullptr, ah, al, thr + (ll)i*HIDh,
            Ee, Ee, Ee, HIDh, 1, 0,0, 0,0, 0,0);

        // x += a @ ddec^T
        gemm_mm<1,false,false><<<dim3(6,32,1),256,DSZ>>>(
            ah, al, dh + (ll)i*Ee*HIDh, dl + (ll)i*Ee*HIDh,
            x, nullptr, nullptr, nullptr,
            HIDh, HIDh, HIDh, Ee, 1, 0,0, 0,0, 0,0);
    }

    mix_norm_split<<<NTOK,256>>>(x, x0, hh, hl, nullptr, nullptr, 0);
    gemm_mm<0,false,false><<<dim3(393,32,1),256,DSZ>>>(
        hh, hl, lh, llo, out, nullptr, nullptr, nullptr,
        Ee, Ee, Ee, Vv, 1, 0,0, 0,0, 0,0);
}

// round 6
// speedup vs baseline: 2.6930x; 1.0895x over previous
#include <cuda_runtime.h>
#include <cuda_fp16.h>
#include <math.h>
#include <stdint.h>

#define Bb 4
#define Tt 1024
#define Vv 50304
#define Ee 768
#define Ll 12
#define Hh 6
#define HDd 128
#define HIDh 3072
#define NTOK (Bb*Tt)
#define EPS 1e-6f
typedef long long ll;
typedef __half fp16;

// ---------------- scratch ----------------------------------------------------
__device__ float g_x [NTOK*Ee];
__device__ float g_x0[NTOK*Ee];
__device__ float g_w [NTOK*Ee];
__device__ float g_dots[(ll)Bb*Hh*Tt*Tt];

__device__ fp16 g_hh[NTOK*Ee],  g_hl[NTOK*Ee];
__device__ fp16 g_wh[NTOK*Ee],  g_wl[NTOK*Ee];
__device__ fp16 g_wth[Bb*Hh*HDd*Tt], g_wtl[Bb*Hh*HDd*Tt];
__device__ fp16 g_ph[(ll)Bb*Hh*Tt*Tt], g_pl[(ll)Bb*Hh*Tt*Tt];
__device__ fp16 g_oh[NTOK*Ee],  g_ol[NTOK*Ee];
__device__ fp16 g_ah[NTOK*HIDh], g_al[NTOK*HIDh];

__device__ fp16 g_qkvh[Ll*Ee*Ee],   g_qkvl[Ll*Ee*Ee];
__device__ fp16 g_cpjh[Ll*Ee*Ee],   g_cpjl[Ll*Ee*Ee];
__device__ fp16 g_dech[Ll*HIDh*Ee], g_decl[Ll*HIDh*Ee];
__device__ fp16 g_ddh[Ll*Ee*HIDh],  g_ddl[Ll*Ee*HIDh];
__device__ fp16 g_lmhh[(ll)Vv*Ee],  g_lmhl[(ll)Vv*Ee];

// ---------------- helpers -----------------------------------------------------
__device__ __forceinline__ uint32_t smem_u32(const void* p){
    uint32_t a;
    asm("{ .reg .u64 t; cvta.to.shared.u64 t, %1; cvt.u32.u64 %0, t; }" : "=r"(a) : "l"(p));
    return a;
}
__device__ __forceinline__ void cp16(uint32_t dst, const void* src){
    asm volatile("cp.async.cg.shared.global [%0], [%1], 16;" :: "r"(dst), "l"(src));
}
#define CP_COMMIT() asm volatile("cp.async.commit_group;" ::: "memory")
#define CP_WAIT1()  asm volatile("cp.async.wait_group 1;" ::: "memory")

__device__ __forceinline__ void ldm4(uint32_t a, uint32_t& r0, uint32_t& r1, uint32_t& r2, uint32_t& r3){
    asm volatile("ldmatrix.sync.aligned.m8n8.x4.shared.b16 {%0,%1,%2,%3}, [%4];"
        : "=r"(r0), "=r"(r1), "=r"(r2), "=r"(r3) : "r"(a));
}
__device__ __forceinline__ void mma16816(float* c, const uint32_t* a, const uint32_t* b){
    asm volatile("mma.sync.aligned.m16n8k16.row.col.f32.f16.f16.f32 "
        "{%0,%1,%2,%3}, {%4,%5,%6,%7}, {%8,%9}, {%0,%1,%2,%3};"
        : "+f"(c[0]), "+f"(c[1]), "+f"(c[2]), "+f"(c[3])
        : "r"(a[0]), "r"(a[1]), "r"(a[2]), "r"(a[3]), "r"(b[0]), "r"(b[1]));
}
__device__ __forceinline__ void split2(float v, fp16& h, fp16& l){
    h = __float2half_rn(v);
    l = __float2half_rn(v - __half2float(h));
}

// ---------------- reductions -------------------------------------------------
__device__ __forceinline__ float warpSum(float v){
    #pragma unroll
    for (int o=16;o;o>>=1) v += __shfl_xor_sync(0xffffffffu, v, o);
    return v;
}
__device__ __forceinline__ float warpMax(float v){
    #pragma unroll
    for (int o=16;o;o>>=1) v = fmaxf(v, __shfl_xor_sync(0xffffffffu, v, o));
    return v;
}
__device__ __forceinline__ float blockSum(float v){
    __shared__ float sh[33];
    __syncthreads();
    int lane = threadIdx.x & 31, wid = threadIdx.x >> 5;
    v = warpSum(v);
    if (lane == 0) sh[wid] = v;
    __syncthreads();
    int nw = (blockDim.x + 31) >> 5;
    float r = (threadIdx.x < nw) ? sh[threadIdx.x] : 0.0f;
    if (wid == 0) r = warpSum(r);
    if (threadIdx.x == 0) sh[32] = r;
    __syncthreads();
    return sh[32];
}
__device__ __forceinline__ float blockMax(float v){
    __shared__ float sh[33];
    __syncthreads();
    int lane = threadIdx.x & 31, wid = threadIdx.x >> 5;
    v = warpMax(v);
    if (lane == 0) sh[wid] = v;
    __syncthreads();
    int nw = (blockDim.x + 31) >> 5;
    float r = (threadIdx.x < nw) ? sh[threadIdx.x] : -INFINITY;
    if (wid == 0) r = warpMax(r);
    if (threadIdx.x == 0) sh[32] = r;
    __syncthreads();
    return sh[32];
}

// ---------------- HMMA GEMM ----------------------------------------------------
// C[M,N] = A[M,K] @ B[N,K]^T with hi/lo fp16 split.
// PRODS=3: AhBh + AhBl + AlBh (fp32-level).  PRODS=2: AhBh + AhBl (~2^-12).
// Block 128x128, 8 warps of 64x32, mma.m16n8k16, KC=32, 3-stage cp.async.
// EPI: 0 store f32, 1 accumulate f32, 2 relu(acc-bias[n]) split store, 3 split store
static constexpr int PITCH  = 40;             // fp16 elems per smem row (80B)
static constexpr int TILEB2 = 128*PITCH*2;    // 10240 B
static constexpr int STAGEB = 4*TILEB2;
static constexpr int NSTG   = 3;
static constexpr int DSZ    = NSTG*STAGEB;    // 122880 B

__device__ __forceinline__ void load_tile(uint32_t dst, const fp16* src, int r0, int k0, int ld, int tid){
    #pragma unroll
    for (int j=0;j<2;j++){
        int slot = tid + j*256;
        int row = slot >> 2;
        int seg = slot & 3;
        cp16(dst + row*80 + seg*16, src + (ll)(r0+row)*ld + k0 + seg*8);
    }
}
template<int PRODS>
__device__ __forceinline__ void load_chunk(uint32_t sbase,
    const fp16* Ah, const fp16* Al, const fp16* Bh, const fp16* Bl,
    int bm, int bn, int k0, int lda, int ldb, int tid)
{
    load_tile(sbase,            Ah, bm, k0, lda, tid);
    if (PRODS == 3) load_tile(sbase + TILEB2, Al, bm, k0, lda, tid);
    load_tile(sbase + 2*TILEB2, Bh, bn, k0, ldb, tid);
    load_tile(sbase + 3*TILEB2, Bl, bn, k0, ldb, tid);
}

template<int PRODS, int EPI, bool TRI, bool KLIM>
__global__ void __launch_bounds__(256,1) gemm_mm(
    const fp16* __restrict__ Ahi, const fp16* __restrict__ Alo,
    const fp16* __restrict__ Bhi, const fp16* __restrict__ Blo,
    float* __restrict__ C, fp16* __restrict__ Chi, fp16* __restrict__ Clo,
    const float* __restrict__ bias,
    int K, int lda, int ldb, int ldc, int zdiv,
    ll sA1, ll sA2, ll sB1, ll sB2, ll sC1, ll sC2)
{
    extern __shared__ char dsm[];
    uint32_t sb = smem_u32(dsm);

    int z  = blockIdx.z;
    int zq = z / zdiv, zr = z % zdiv;
    Ahi += zq*sA1 + zr*sA2; Alo += zq*sA1 + zr*sA2;
    Bhi += zq*sB1 + zr*sB2; Blo += zq*sB1 + zr*sB2;
    if (EPI==0 || EPI==1) { C += zq*sC1 + zr*sC2; }
    else { Chi += zq*sC1 + zr*sC2; Clo += zq*sC1 + zr*sC2; }

    int bm, bn;
    if (TRI) {
        int idx = blockIdx.x;
        int i_ = (int)((sqrtf(8.f*(float)idx + 1.f) - 1.f) * 0.5f);
        while ((i_+1)*(i_+2)/2 <= idx) i_++;
        while (i_*(i_+1)/2 > idx) i_--;
        bm = i_*128; bn = (idx - i_*(i_+1)/2)*128;
    } else { bm = blockIdx.y*128; bn = blockIdx.x*128; }

    int kmax = KLIM ? min(K, bm + 128) : K;
    int nch  = kmax >> 5;                      // KC = 32
    const int tid  = threadIdx.x;
    const int lane = tid & 31;
    const int wid  = tid >> 5;
    const int wm   = wid >> 2;                 // 0..1
    const int wn   = wid & 3;                  // 0..3

    float acc[4][4][4];
    #pragma unroll
    for (int i=0;i<4;i++)
        #pragma unroll
        for (int j=0;j<4;j++)
            #pragma unroll
            for (int q=0;q<4;q++) acc[i][j][q]=0.f;

    int pre = nch < 2 ? nch : 2;
    for (int j=0;j<pre;j++){
        load_chunk<PRODS>(sb + (j%NSTG)*STAGEB, Ahi,Alo,Bhi,Blo, bm,bn, j*32, lda,ldb, tid);
        CP_COMMIT();
    }
    for (int j=pre;j<2;j++) CP_COMMIT();

    const int a_row  = (lane & 15);
    const int a_colb = ((lane >> 4) << 3) * 2;
    const int b_rowo = ((lane >> 4) << 3) + (lane & 7);
    const int b_colb = (((lane >> 3) & 1) << 3) * 2;

    for (int i=0;i<nch;i++){
        CP_WAIT1();
        __syncthreads();
        uint32_t st = sb + (i%NSTG)*STAGEB;
        if (i + 2 < nch) {
            load_chunk<PRODS>(sb + ((i+2)%NSTG)*STAGEB, Ahi,Alo,Bhi,Blo, bm,bn, (i+2)*32, lda,ldb, tid);
        }
        CP_COMMIT();

        uint32_t Abh = st, Abl = st + TILEB2, Bbh = st + 2*TILEB2, Bbl = st + 3*TILEB2;
        #pragma unroll
        for (int kk=0; kk<2; kk++){
            const int kb = kk*16*2;
            uint32_t ah[4][4], al[4][4], bh[4][2], blr[4][2];
            #pragma unroll
            for (int mt=0; mt<4; mt++){
                uint32_t off = (uint32_t)(wm*64 + mt*16 + a_row)*80 + kb + a_colb;
                ldm4(Abh + off, ah[mt][0], ah[mt][1], ah[mt][2], ah[mt][3]);
                if (PRODS == 3) ldm4(Abl + off, al[mt][0], al[mt][1], al[mt][2], al[mt][3]);
            }
            #pragma unroll
            for (int np=0; np<2; np++){
                uint32_t off = (uint32_t)(wn*32 + np*16 + b_rowo)*80 + kb + b_colb;
                uint32_t r0,r1,r2,r3;
                ldm4(Bbh + off, r0,r1,r2,r3);
                bh[2*np][0]=r0; bh[2*np][1]=r1; bh[2*np+1][0]=r2; bh[2*np+1][1]=r3;
                ldm4(Bbl + off, r0,r1,r2,r3);
                blr[2*np][0]=r0; blr[2*np][1]=r1; blr[2*np+1][0]=r2; blr[2*np+1][1]=r3;
            }
            #pragma unroll
            for (int mt=0; mt<4; mt++)
                #pragma unroll
                for (int nt=0; nt<4; nt++){
                    mma16816(acc[mt][nt], ah[mt], bh[nt]);
                    mma16816(acc[mt][nt], ah[mt], blr[nt]);
                    if (PRODS == 3) mma16816(acc[mt][nt], al[mt], bh[nt]);
                }
        }
        __syncthreads();
    }

    #pragma unroll
    for (int mt=0; mt<4; mt++){
        #pragma unroll
        for (int nt=0; nt<4; nt++){
            int m0 = bm + wm*64 + mt*16 + (lane >> 2);
            int n0 = bn + wn*32 + nt*8  + (lane & 3)*2;
            float c0 = acc[mt][nt][0], c1 = acc[mt][nt][1];
            float c2 = acc[mt][nt][2], c3 = acc[mt][nt][3];
            if (EPI == 0) {
                *(float2*)(C + (ll)m0*ldc + n0)     = make_float2(c0, c1);
                *(float2*)(C + (ll)(m0+8)*ldc + n0) = make_float2(c2, c3);
            } else if (EPI == 1) {
                float2 o0 = *(const float2*)(C + (ll)m0*ldc + n0);
                float2 o1 = *(const float2*)(C + (ll)(m0+8)*ldc + n0);
                *(float2*)(C + (ll)m0*ldc + n0)     = make_float2(o0.x+c0, o0.y+c1);
                *(float2*)(C + (ll)(m0+8)*ldc + n0) = make_float2(o1.x+c2, o1.y+c3);
            } else {
                if (EPI == 2) {
                    float b0 = __ldg(bias + n0), b1 = __ldg(bias + n0 + 1);
                    c0 = fmaxf(c0-b0, 0.f); c1 = fmaxf(c1-b1, 0.f);
                    c2 = fmaxf(c2-b0, 0.f); c3 = fmaxf(c3-b1, 0.f);
                }
                fp16 h0,l0,h1,l1;
                split2(c0,h0,l0); split2(c1,h1,l1);
                __half2 hv; hv.x=h0; hv.y=h1;
                __half2 lv; lv.x=l0; lv.y=l1;
                *(__half2*)(Chi + (ll)m0*ldc + n0) = hv;
                *(__half2*)(Clo + (ll)m0*ldc + n0) = lv;
                split2(c2,h0,l0); split2(c3,h1,l1);
                hv.x=h0; hv.y=h1; lv.x=l0; lv.y=l1;
                *(__half2*)(Chi + (ll)(m0+8)*ldc + n0) = hv;
                *(__half2*)(Clo + (ll)(m0+8)*ldc + n0) = lv;
            }
        }
    }
}

// ---------------- elementwise kernels ----------------------------------------
__global__ void embed_norm_kernel(const int* __restrict__ idx,
                                  const float* __restrict__ wte,
                                  float* __restrict__ x, float* __restrict__ x0)
{
    int t = blockIdx.x;
    int tok = idx[t];
    const float* row = wte + (ll)tok * Ee;
    ll base = (ll)t * Ee;
    float v[3]; float ss = 0.f;
    #pragma unroll
    for (int j=0;j<3;j++){ int c = threadIdx.x + j*256; float m = row[c]; v[j]=m; ss += m*m; }
    ss = blockSum(ss);
    float inv = rsqrtf(ss*(1.0f/Ee) + EPS);
    #pragma unroll
    for (int j=0;j<3;j++){ int c = threadIdx.x + j*256; float o = v[j]*inv; x[base+c]=o; x0[base+c]=o; }
}

__global__ void mix_norm_split(float* __restrict__ x, const float* __restrict__ x0,
                               fp16* __restrict__ hh, fp16* __restrict__ hl,
                               const float* lamr, const float* lamx, int li)
{
    int t = blockIdx.x;
    float rl = lamr ? lamr[li] : 1.0f;
    float xl = lamx ? lamx[li] : 0.0f;
    ll base = (ll)t * Ee;
    float v[3]; float ss = 0.f;
    #pragma unroll
    for (int j=0;j<3;j++){
        int c = threadIdx.x + j*256;
        float m = rl*x[base+c] + xl*x0[base+c];
        v[j]=m; ss += m*m;
    }
    ss = blockSum(ss);
    float inv = rsqrtf(ss*(1.0f/Ee) + EPS);
    #pragma unroll
    for (int j=0;j<3;j++){
        int c = threadIdx.x + j*256;
        x[base+c] = v[j];
        fp16 h, l; split2(v[j]*inv, h, l);
        hh[base+c] = h; hl[base+c] = l;
    }
}

__global__ void rope_split_kernel(const float* __restrict__ wf,
                                  fp16* __restrict__ wh, fp16* __restrict__ wl)
{
    int n  = blockIdx.x / Hh;
    int hh = blockIdx.x % Hh;
    int t  = n & (Tt-1);
    const float* base = wf + (ll)n*Ee + hh*HDd;
    int d = threadIdx.x;
    __shared__ float s[HDd];
    float v = base[d];
    s[d] = v;
    float ss = blockSum(v*v);
    float inv = rsqrtf(ss*(1.0f/HDd) + EPS);
    float out;
    if (d < 64) {
        int j = d;
        float x1 = s[j], x2 = s[j+64];
        float fr = (float)t * powf(10000.0f, -((float)(2*j)) * (1.0f/128.0f));
        out = (x1*cosf(fr) + x2*sinf(fr)) * inv;
    } else {
        int j = d - 64;
        float x1 = s[j], x2 = s[d];
        float fr = (float)t * powf(10000.0f, -((float)(2*j)) * (1.0f/128.0f));
        out = (-x1*sinf(fr) + x2*cosf(fr)) * inv;
    }
    fp16 h, l; split2(out, h, l);
    ll o = (ll)n*Ee + hh*HDd + d;
    wh[o] = h; wl[o] = l;
}

__global__ void transpose_hd(const fp16* __restrict__ whi, const fp16* __restrict__ wlo,
                             fp16* __restrict__ othi, fp16* __restrict__ otlo)
{
    __shared__ fp16 tile[32][33];
    int z = blockIdx.z; int b = z / Hh, h = z % Hh;
    int t0 = blockIdx.x*32, d0 = blockIdx.y*32;
    #pragma unroll
    for (int pass=0; pass<2; pass++){
        const fp16* src = pass ? wlo : whi;
        fp16* dst = pass ? otlo : othi;
        for (int j=(int)threadIdx.y; j<32; j+=8)
            tile[j][threadIdx.x] = src[(ll)(b*Tt + t0 + j)*Ee + h*HDd + d0 + threadIdx.x];
        __syncthreads();
        for (int j=(int)threadIdx.y; j<32; j+=8)
            dst[(ll)z*HDd*Tt + (ll)(d0 + j)*Tt + t0 + threadIdx.x] = tile[threadIdx.x][j];
        __syncthreads();
    }
}

__global__ void softmax_split_kernel(const float* __restrict__ dots,
                                     fp16* __restrict__ ph, fp16* __restrict__ pl,
                                     float scale)
{
    ll r = blockIdx.x;
    int q = (int)(r & (Tt-1));
    const float* row = dots + r * Tt;
    fp16* hrow = ph + r * Tt;
    fp16* lrow = pl + r * Tt;
    int nv = q + 1;
    float vals[4];
    float m = -INFINITY;
    #pragma unroll
    for (int it=0; it<4; it++){
        int k = threadIdx.x + it*256;
        float v = (k < nv) ? row[k]*scale : -INFINITY;
        vals[it] = v;
        m = fmaxf(m, v);
    }
    m = blockMax(m);
    float sum = 0.f;
    #pragma unroll
    for (int it=0; it<4; it++){
        int k = threadIdx.x + it*256;
        float e = (k < nv) ? expf(vals[it]-m) : 0.0f;
        vals[it] = e; sum += e;
    }
    sum = blockSum(sum);
    float invs = 1.0f / sum;
    #pragma unroll
    for (int it=0; it<4; it++){
        int k = threadIdx.x + it*256;
        fp16 h, l; split2(vals[it]*invs, h, l);
        hrow[k] = h; lrow[k] = l;
    }
}

__global__ void split_f32(const float* __restrict__ in, fp16* __restrict__ hi,
                          fp16* __restrict__ lo, ll n)
{
    ll i = ((ll)blockIdx.x*blockDim.x + threadIdx.x)*4;
    if (i >= n) return;
    float4 v = *(const float4*)(in + i);
    fp16 h0,l0,h1,l1,h2,l2,h3,l3;
    split2(v.x,h0,l0); split2(v.y,h1,l1); split2(v.z,h2,l2); split2(v.w,h3,l3);
    __half2 a; a.x=h0; a.y=h1; __half2 b; b.x=h2; b.y=h3;
    __half2 c; c.x=l0; c.y=l1; __half2 d; d.x=l2; d.y=l3;
    *(__half2*)(hi+i)   = a; *(__half2*)(hi+i+2) = b;
    *(__half2*)(lo+i)   = c; *(__half2*)(lo+i+2) = d;
}

// ---------------- host ---------------------------------------------------------
extern "C" void kernel_launch(void* const* d_in, const int* in_sizes, int n_in,
                              void* d_out, int out_size)
{
    const int*   idx  = (const int*)  d_in[0];
    const float* wte  = (const float*)d_in[1];
    const float* lmh  = (const float*)d_in[2];
    const float* qkvw = (const float*)d_in[3];
    const float* cpjw = (const float*)d_in[4];
    const float* denc = (const float*)d_in[5];
    const float* ddec = (const float*)d_in[6];
    const float* thr  = (const float*)d_in[7];
    const float* lamr = (const float*)d_in[8];
    const float* lamx = (const float*)d_in[9];
    float* out = (float*)d_out;

    cudaFuncSetAttribute(gemm_mm<3,0,false,false>, cudaFuncAttributeMaxDynamicSharedMemorySize, DSZ);
    cudaFuncSetAttribute(gemm_mm<2,0,true ,false>, cudaFuncAttributeMaxDynamicSharedMemorySize, DSZ);
    cudaFuncSetAttribute(gemm_mm<1==1?3:3,1,false,false>, cudaFuncAttributeMaxDynamicSharedMemorySize, DSZ);
    cudaFuncSetAttribute(gemm_mm<3,2,false,false>, cudaFuncAttributeMaxDynamicSharedMemorySize, DSZ);
    cudaFuncSetAttribute(gemm_mm<2,3,false,true >, cudaFuncAttributeMaxDynamicSharedMemorySize, DSZ);
    cudaFuncSetAttribute(gemm_mm<2,0,false,false>, cudaFuncAttributeMaxDynamicSharedMemorySize, DSZ);

    float *x, *x0, *wf, *dots;
    cudaGetSymbolAddress((void**)&x,    g_x);
    cudaGetSymbolAddress((void**)&x0,   g_x0);
    cudaGetSymbolAddress((void**)&wf,   g_w);
    cudaGetSymbolAddress((void**)&dots, g_dots);
    fp16 *hh,*hl,*wh,*wl,*wth,*wtl,*ph,*pl,*oh,*ol,*ah,*al;
    cudaGetSymbolAddress((void**)&hh,  g_hh);  cudaGetSymbolAddress((void**)&hl,  g_hl);
    cudaGetSymbolAddress((void**)&wh,  g_wh);  cudaGetSymbolAddress((void**)&wl,  g_wl);
    cudaGetSymbolAddress((void**)&wth, g_wth); cudaGetSymbolAddress((void**)&wtl, g_wtl);
    cudaGetSymbolAddress((void**)&ph,  g_ph);  cudaGetSymbolAddress((void**)&pl,  g_pl);
    cudaGetSymbolAddress((void**)&oh,  g_oh);  cudaGetSymbolAddress((void**)&ol,  g_ol);
    cudaGetSymbolAddress((void**)&ah,  g_ah);  cudaGetSymbolAddress((void**)&al,  g_al);
    fp16 *qh,*ql,*ch,*cl,*eh,*el,*dh,*dl,*lh,*llo;
    cudaGetSymbolAddress((void**)&qh, g_qkvh); cudaGetSymbolAddress((void**)&ql, g_qkvl);
    cudaGetSymbolAddress((void**)&ch, g_cpjh); cudaGetSymbolAddress((void**)&cl, g_cpjl);
    cudaGetSymbolAddress((void**)&eh, g_dech); cudaGetSymbolAddress((void**)&el, g_decl);
    cudaGetSymbolAddress((void**)&dh, g_ddh);  cudaGetSymbolAddress((void**)&dl, g_ddl);
    cudaGetSymbolAddress((void**)&lh, g_lmhh); cudaGetSymbolAddress((void**)&llo, g_lmhl);

    {
        ll n;
        n = (ll)Ll*Ee*Ee;    split_f32<<<(int)((n/4+255)/256),256>>>(qkvw, qh, ql, n);
        n = (ll)Ll*Ee*Ee;    split_f32<<<(int)((n/4+255)/256),256>>>(cpjw, ch, cl, n);
        n = (ll)Ll*HIDh*Ee;  split_f32<<<(int)((n/4+255)/256),256>>>(denc, eh, el, n);
        n = (ll)Ll*Ee*HIDh;  split_f32<<<(int)((n/4+255)/256),256>>>(ddec, dh, dl, n);
        n = (ll)Vv*Ee;       split_f32<<<(int)((n/4+255)/256),256>>>(lmh,  lh, llo, n);
    }

    const float scale = 0.08838834764831845f;
    const ll TE = (ll)Tt*Ee;
    const ll TT = (ll)Tt*Tt;
    const ll WT = (ll)HDd*Tt;

    embed_norm_kernel<<<NTOK,256>>>(idx, wte, x, x0);

    for (int i=0;i<Ll;i++){
        mix_norm_split<<<NTOK,256>>>(x, x0, hh, hl, lamr, lamx, i);

        // w = h @ qkv^T (fp32 out for rope), 3-product
        gemm_mm<3,0,false,false><<<dim3(6,32,1),256,DSZ>>>(
            hh, hl, qh + (ll)i*Ee*Ee, ql + (ll)i*Ee*Ee,
            wf, nullptr, nullptr, nullptr,
            Ee, Ee, Ee, Ee, 1, 0,0, 0,0, 0,0);

        rope_split_kernel<<<NTOK*Hh,128>>>(wf, wh, wl);
        transpose_hd<<<dim3(Tt/32, HDd/32, Bb*Hh), dim3(32,8)>>>(wh, wl, wth, wtl);

        // dots = W W^T (lower-triangular tiles only), 2-product
        gemm_mm<2,0,true,false><<<dim3(36,1,Bb*Hh),256,DSZ>>>(
            wh, wl, wh, wl,
            dots, nullptr, nullptr, nullptr,
            HDd, Ee, Ee, Tt, Hh, TE,(ll)HDd, TE,(ll)HDd, (ll)Hh*TT, TT);

        softmax_split_kernel<<<Bb*Hh*Tt,256>>>(dots, ph, pl, scale);

        // o = P @ W (K limited to bm+128), split output, 2-product
        gemm_mm<2,3,false,true><<<dim3(1,8,Bb*Hh),256,DSZ>>>(
            ph, pl, wth, wtl,
            nullptr, oh, ol, nullptr,
            Tt, Tt, Tt, Ee, Hh, (ll)Hh*TT,TT, (ll)Hh*WT,WT, TE,(ll)HDd);

        // x += o @ cproj^T, 3-product
        gemm_mm<3,1,false,false><<<dim3(6,32,1),256,DSZ>>>(
            oh, ol, ch + (ll)i*Ee*Ee, cl + (ll)i*Ee*Ee,
            x, nullptr, nullptr, nullptr,
            Ee, Ee, Ee, Ee, 1, 0,0, 0,0, 0,0);

        mix_norm_split<<<NTOK,256>>>(x, x0, hh, hl, nullptr, nullptr, 0);

        // a = relu(h @ denc^T - thr), split output, 3-product
        gemm_mm<3,2,false,false><<<dim3(24,32,1),256,DSZ>>>(
            hh, hl, eh + (ll)i*HIDh*Ee, el + (ll)i*HIDh*Ee,
            nullptr, ah, al, thr + (ll)i*HIDh,
            Ee, Ee, Ee, HIDh, 1, 0,0, 0,0, 0,0);

        // x += a @ ddec^T, 3-product
        gemm_mm<3,1,false,false><<<dim3(6,32,1),256,DSZ>>>(
            ah, al, dh + (ll)i*Ee*HIDh, dl + (ll)i*Ee*HIDh,
            x, nullptr, nullptr, nullptr,
            HIDh, HIDh, HIDh, Ee, 1, 0,0, 0,0, 0,0);
    }

    mix_norm_split<<<NTOK,256>>>(x, x0, hh, hl, nullptr, nullptr, 0);
    // lm_head: 2-product fp16 (terminal op, error does not propagate)
    gemm_mm<2,0,false,false><<<dim3(393,32,1),256,DSZ>>>(
        hh, hl, lh, llo, out, nullptr, nullptr, nullptr,
        Ee, Ee, Ee, Vv, 1, 0,0, 0,0, 0,0);
}

// round 7
// speedup vs baseline: 3.0986x; 1.1506x over previous
#include <cuda_runtime.h>
#include <cuda_fp16.h>
#include <math.h>
#include <stdint.h>

#define Bb 4
#define Tt 1024
#define Vv 50304
#define Ee 768
#define Ll 12
#define Hh 6
#define HDd 128
#define HIDh 3072
#define NTOK (Bb*Tt)
#define EPS 1e-6f
typedef long long ll;
typedef __half fp16;

// ---------------- scratch ----------------------------------------------------
__device__ float g_x [NTOK*Ee];
__device__ float g_x0[NTOK*Ee];
__device__ float g_w [NTOK*Ee];
__device__ float g_dots[(ll)Bb*Hh*Tt*Tt];

__device__ fp16 g_hh[NTOK*Ee],  g_hl[NTOK*Ee];
__device__ fp16 g_wh[NTOK*Ee],  g_wl[NTOK*Ee];
__device__ fp16 g_wth[Bb*Hh*HDd*Tt], g_wtl[Bb*Hh*HDd*Tt];
__device__ fp16 g_ph[(ll)Bb*Hh*Tt*Tt], g_pl[(ll)Bb*Hh*Tt*Tt];
__device__ fp16 g_oh[NTOK*Ee],  g_ol[NTOK*Ee];
__device__ fp16 g_ah[NTOK*HIDh], g_al[NTOK*HIDh];

__device__ fp16 g_qkvh[Ll*Ee*Ee],   g_qkvl[Ll*Ee*Ee];
__device__ fp16 g_cpjh[Ll*Ee*Ee],   g_cpjl[Ll*Ee*Ee];
__device__ fp16 g_dech[Ll*HIDh*Ee], g_decl[Ll*HIDh*Ee];
__device__ fp16 g_ddh[Ll*Ee*HIDh],  g_ddl[Ll*Ee*HIDh];
__device__ fp16 g_lmhh[(ll)Vv*Ee],  g_lmhl[(ll)Vv*Ee];

// ---------------- helpers -----------------------------------------------------
__device__ __forceinline__ uint32_t smem_u32(const void* p){
    uint32_t a;
    asm("{ .reg .u64 t; cvta.to.shared.u64 t, %1; cvt.u32.u64 %0, t; }" : "=r"(a) : "l"(p));
    return a;
}
__device__ __forceinline__ void cp16(uint32_t dst, const void* src){
    asm volatile("cp.async.cg.shared.global [%0], [%1], 16;" :: "r"(dst), "l"(src));
}
#define CP_COMMIT() asm volatile("cp.async.commit_group;" ::: "memory")
#define CP_WAIT1()  asm volatile("cp.async.wait_group 1;" ::: "memory")

__device__ __forceinline__ void ldm4(uint32_t a, uint32_t& r0, uint32_t& r1, uint32_t& r2, uint32_t& r3){
    asm volatile("ldmatrix.sync.aligned.m8n8.x4.shared.b16 {%0,%1,%2,%3}, [%4];"
        : "=r"(r0), "=r"(r1), "=r"(r2), "=r"(r3) : "r"(a));
}
__device__ __forceinline__ void mma16816(float* c, const uint32_t* a, const uint32_t* b){
    asm volatile("mma.sync.aligned.m16n8k16.row.col.f32.f16.f16.f32 "
        "{%0,%1,%2,%3}, {%4,%5,%6,%7}, {%8,%9}, {%0,%1,%2,%3};"
        : "+f"(c[0]), "+f"(c[1]), "+f"(c[2]), "+f"(c[3])
        : "r"(a[0]), "r"(a[1]), "r"(a[2]), "r"(a[3]), "r"(b[0]), "r"(b[1]));
}
__device__ __forceinline__ void split2(float v, fp16& h, fp16& l){
    h = __float2half_rn(v);
    l = __float2half_rn(v - __half2float(h));
}

// ---------------- reductions -------------------------------------------------
__device__ __forceinline__ float warpSum(float v){
    #pragma unroll
    for (int o=16;o;o>>=1) v += __shfl_xor_sync(0xffffffffu, v, o);
    return v;
}
__device__ __forceinline__ float warpMax(float v){
    #pragma unroll
    for (int o=16;o;o>>=1) v = fmaxf(v, __shfl_xor_sync(0xffffffffu, v, o));
    return v;
}
__device__ __forceinline__ float blockSum(float v){
    __shared__ float sh[33];
    __syncthreads();
    int lane = threadIdx.x & 31, wid = threadIdx.x >> 5;
    v = warpSum(v);
    if (lane == 0) sh[wid] = v;
    __syncthreads();
    int nw = (blockDim.x + 31) >> 5;
    float r = (threadIdx.x < nw) ? sh[threadIdx.x] : 0.0f;
    if (wid == 0) r = warpSum(r);
    if (threadIdx.x == 0) sh[32] = r;
    __syncthreads();
    return sh[32];
}
__device__ __forceinline__ float blockMax(float v){
    __shared__ float sh[33];
    __syncthreads();
    int lane = threadIdx.x & 31, wid = threadIdx.x >> 5;
    v = warpMax(v);
    if (lane == 0) sh[wid] = v;
    __syncthreads();
    int nw = (blockDim.x + 31) >> 5;
    float r = (threadIdx.x < nw) ? sh[threadIdx.x] : -INFINITY;
    if (wid == 0) r = warpMax(r);
    if (threadIdx.x == 0) sh[32] = r;
    __syncthreads();
    return sh[32];
}

// ---------------- HMMA GEMM ----------------------------------------------------
// C[M,N] = A[M,K] @ B[N,K]^T with hi/lo fp16 split.
// PRODS=3: AhBh + AhBl + AlBh (fp32-level).  PRODS=2: AhBh + AhBl (~2^-12).
// Block 128x128, 8 warps of 64x32, mma.m16n8k16, KC=32, 3-stage cp.async.
// EPI: 0 store f32, 1 accumulate f32, 2 relu(acc-bias[n]) split store, 3 split store
static constexpr int PITCH  = 40;
static constexpr int TILEB2 = 128*PITCH*2;    // 10240 B
static constexpr int STAGEB = 4*TILEB2;
static constexpr int NSTG   = 3;
static constexpr int DSZ    = NSTG*STAGEB;    // 122880 B

__device__ __forceinline__ void load_tile(uint32_t dst, const fp16* src, int r0, int k0, int ld, int tid){
    #pragma unroll
    for (int j=0;j<2;j++){
        int slot = tid + j*256;
        int row = slot >> 2;
        int seg = slot & 3;
        cp16(dst + row*80 + seg*16, src + (ll)(r0+row)*ld + k0 + seg*8);
    }
}
template<int PRODS>
__device__ __forceinline__ void load_chunk(uint32_t sbase,
    const fp16* Ah, const fp16* Al, const fp16* Bh, const fp16* Bl,
    int bm, int bn, int k0, int lda, int ldb, int tid)
{
    load_tile(sbase,            Ah, bm, k0, lda, tid);
    if (PRODS == 3) load_tile(sbase + TILEB2, Al, bm, k0, lda, tid);
    load_tile(sbase + 2*TILEB2, Bh, bn, k0, ldb, tid);
    load_tile(sbase + 3*TILEB2, Bl, bn, k0, ldb, tid);
}

template<int PRODS, int EPI, bool TRI, bool KLIM>
__global__ void __launch_bounds__(256,1) gemm_mm(
    const fp16* __restrict__ Ahi, const fp16* __restrict__ Alo,
    const fp16* __restrict__ Bhi, const fp16* __restrict__ Blo,
    float* __restrict__ C, fp16* __restrict__ Chi, fp16* __restrict__ Clo,
    const float* __restrict__ bias,
    int K, int lda, int ldb, int ldc, int zdiv,
    ll sA1, ll sA2, ll sB1, ll sB2, ll sC1, ll sC2)
{
    extern __shared__ char dsm[];
    uint32_t sb = smem_u32(dsm);

    int z  = blockIdx.z;
    int zq = z / zdiv, zr = z % zdiv;
    Ahi += zq*sA1 + zr*sA2; Alo += zq*sA1 + zr*sA2;
    Bhi += zq*sB1 + zr*sB2; Blo += zq*sB1 + zr*sB2;
    if (EPI==0 || EPI==1) { C += zq*sC1 + zr*sC2; }
    else { Chi += zq*sC1 + zr*sC2; Clo += zq*sC1 + zr*sC2; }

    int bm, bn;
    if (TRI) {
        int idx = blockIdx.x;
        int i_ = (int)((sqrtf(8.f*(float)idx + 1.f) - 1.f) * 0.5f);
        while ((i_+1)*(i_+2)/2 <= idx) i_++;
        while (i_*(i_+1)/2 > idx) i_--;
        bm = i_*128; bn = (idx - i_*(i_+1)/2)*128;
    } else { bm = blockIdx.y*128; bn = blockIdx.x*128; }

    int kmax = KLIM ? min(K, bm + 128) : K;
    int nch  = kmax >> 5;
    const int tid  = threadIdx.x;
    const int lane = tid & 31;
    const int wid  = tid >> 5;
    const int wm   = wid >> 2;
    const int wn   = wid & 3;

    float acc[4][4][4];
    #pragma unroll
    for (int i=0;i<4;i++)
        #pragma unroll
        for (int j=0;j<4;j++)
            #pragma unroll
            for (int q=0;q<4;q++) acc[i][j][q]=0.f;

    int pre = nch < 2 ? nch : 2;
    for (int j=0;j<pre;j++){
        load_chunk<PRODS>(sb + (j%NSTG)*STAGEB, Ahi,Alo,Bhi,Blo, bm,bn, j*32, lda,ldb, tid);
        CP_COMMIT();
    }
    for (int j=pre;j<2;j++) CP_COMMIT();

    const int a_row  = (lane & 15);
    const int a_colb = ((lane >> 4) << 3) * 2;
    const int b_rowo = ((lane >> 4) << 3) + (lane & 7);
    const int b_colb = (((lane >> 3) & 1) << 3) * 2;

    for (int i=0;i<nch;i++){
        CP_WAIT1();
        __syncthreads();
        uint32_t st = sb + (i%NSTG)*STAGEB;
        if (i + 2 < nch) {
            load_chunk<PRODS>(sb + ((i+2)%NSTG)*STAGEB, Ahi,Alo,Bhi,Blo, bm,bn, (i+2)*32, lda,ldb, tid);
        }
        CP_COMMIT();

        uint32_t Abh = st, Abl = st + TILEB2, Bbh = st + 2*TILEB2, Bbl = st + 3*TILEB2;
        #pragma unroll
        for (int kk=0; kk<2; kk++){
            const int kb = kk*16*2;
            uint32_t ah[4][4], al[4][4], bh[4][2], blr[4][2];
            #pragma unroll
            for (int mt=0; mt<4; mt++){
                uint32_t off = (uint32_t)(wm*64 + mt*16 + a_row)*80 + kb + a_colb;
                ldm4(Abh + off, ah[mt][0], ah[mt][1], ah[mt][2], ah[mt][3]);
                if (PRODS == 3) ldm4(Abl + off, al[mt][0], al[mt][1], al[mt][2], al[mt][3]);
            }
            #pragma unroll
            for (int np=0; np<2; np++){
                uint32_t off = (uint32_t)(wn*32 + np*16 + b_rowo)*80 + kb + b_colb;
                uint32_t r0,r1,r2,r3;
                ldm4(Bbh + off, r0,r1,r2,r3);
                bh[2*np][0]=r0; bh[2*np][1]=r1; bh[2*np+1][0]=r2; bh[2*np+1][1]=r3;
                ldm4(Bbl + off, r0,r1,r2,r3);
                blr[2*np][0]=r0; blr[2*np][1]=r1; blr[2*np+1][0]=r2; blr[2*np+1][1]=r3;
            }
            #pragma unroll
            for (int mt=0; mt<4; mt++)
                #pragma unroll
                for (int nt=0; nt<4; nt++){
                    mma16816(acc[mt][nt], ah[mt], bh[nt]);
                    mma16816(acc[mt][nt], ah[mt], blr[nt]);
                    if (PRODS == 3) mma16816(acc[mt][nt], al[mt], bh[nt]);
                }
        }
        __syncthreads();
    }

    #pragma unroll
    for (int mt=0; mt<4; mt++){
        #pragma unroll
        for (int nt=0; nt<4; nt++){
            int m0 = bm + wm*64 + mt*16 + (lane >> 2);
            int n0 = bn + wn*32 + nt*8  + (lane & 3)*2;
            float c0 = acc[mt][nt][0], c1 = acc[mt][nt][1];
            float c2 = acc[mt][nt][2], c3 = acc[mt][nt][3];
            if (EPI == 0) {
                *(float2*)(C + (ll)m0*ldc + n0)     = make_float2(c0, c1);
                *(float2*)(C + (ll)(m0+8)*ldc + n0) = make_float2(c2, c3);
            } else if (EPI == 1) {
                float2 o0 = *(const float2*)(C + (ll)m0*ldc + n0);
                float2 o1 = *(const float2*)(C + (ll)(m0+8)*ldc + n0);
                *(float2*)(C + (ll)m0*ldc + n0)     = make_float2(o0.x+c0, o0.y+c1);
                *(float2*)(C + (ll)(m0+8)*ldc + n0) = make_float2(o1.x+c2, o1.y+c3);
            } else {
                if (EPI == 2) {
                    float b0 = __ldg(bias + n0), b1 = __ldg(bias + n0 + 1);
                    c0 = fmaxf(c0-b0, 0.f); c1 = fmaxf(c1-b1, 0.f);
                    c2 = fmaxf(c2-b0, 0.f); c3 = fmaxf(c3-b1, 0.f);
                }
                fp16 h0,l0,h1,l1;
                split2(c0,h0,l0); split2(c1,h1,l1);
                __half2 hv; hv.x=h0; hv.y=h1;
                __half2 lv; lv.x=l0; lv.y=l1;
                *(__half2*)(Chi + (ll)m0*ldc + n0) = hv;
                *(__half2*)(Clo + (ll)m0*ldc + n0) = lv;
                split2(c2,h0,l0); split2(c3,h1,l1);
                hv.x=h0; hv.y=h1; lv.x=l0; lv.y=l1;
                *(__half2*)(Chi + (ll)(m0+8)*ldc + n0) = hv;
                *(__half2*)(Clo + (ll)(m0+8)*ldc + n0) = lv;
            }
        }
    }
}

// ---------------- elementwise kernels ----------------------------------------
__global__ void embed_norm_kernel(const int* __restrict__ idx,
                                  const float* __restrict__ wte,
                                  float* __restrict__ x, float* __restrict__ x0)
{
    int t = blockIdx.x;
    int tok = idx[t];
    const float* row = wte + (ll)tok * Ee;
    ll base = (ll)t * Ee;
    float v[3]; float ss = 0.f;
    #pragma unroll
    for (int j=0;j<3;j++){ int c = threadIdx.x + j*256; float m = row[c]; v[j]=m; ss += m*m; }
    ss = blockSum(ss);
    float inv = rsqrtf(ss*(1.0f/Ee) + EPS);
    #pragma unroll
    for (int j=0;j<3;j++){ int c = threadIdx.x + j*256; float o = v[j]*inv; x[base+c]=o; x0[base+c]=o; }
}

__global__ void mix_norm_split(float* __restrict__ x, const float* __restrict__ x0,
                               fp16* __restrict__ hh, fp16* __restrict__ hl,
                               const float* lamr, const float* lamx, int li)
{
    int t = blockIdx.x;
    float rl = lamr ? lamr[li] : 1.0f;
    float xl = lamx ? lamx[li] : 0.0f;
    ll base = (ll)t * Ee;
    float v[3]; float ss = 0.f;
    #pragma unroll
    for (int j=0;j<3;j++){
        int c = threadIdx.x + j*256;
        float m = rl*x[base+c] + xl*x0[base+c];
        v[j]=m; ss += m*m;
    }
    ss = blockSum(ss);
    float inv = rsqrtf(ss*(1.0f/Ee) + EPS);
    #pragma unroll
    for (int j=0;j<3;j++){
        int c = threadIdx.x + j*256;
        x[base+c] = v[j];
        fp16 h, l; split2(v[j]*inv, h, l);
        hh[base+c] = h; hl[base+c] = l;
    }
}

__global__ void rope_split_kernel(const float* __restrict__ wf,
                                  fp16* __restrict__ wh, fp16* __restrict__ wl)
{
    int n  = blockIdx.x / Hh;
    int hh = blockIdx.x % Hh;
    int t  = n & (Tt-1);
    const float* base = wf + (ll)n*Ee + hh*HDd;
    int d = threadIdx.x;
    __shared__ float s[HDd];
    float v = base[d];
    s[d] = v;
    float ss = blockSum(v*v);
    float inv = rsqrtf(ss*(1.0f/HDd) + EPS);
    float out;
    if (d < 64) {
        int j = d;
        float x1 = s[j], x2 = s[j+64];
        float fr = (float)t * powf(10000.0f, -((float)(2*j)) * (1.0f/128.0f));
        out = (x1*cosf(fr) + x2*sinf(fr)) * inv;
    } else {
        int j = d - 64;
        float x1 = s[j], x2 = s[d];
        float fr = (float)t * powf(10000.0f, -((float)(2*j)) * (1.0f/128.0f));
        out = (-x1*sinf(fr) + x2*cosf(fr)) * inv;
    }
    fp16 h, l; split2(out, h, l);
    ll o = (ll)n*Ee + hh*HDd + d;
    wh[o] = h; wl[o] = l;
}

__global__ void transpose_hd(const fp16* __restrict__ whi, const fp16* __restrict__ wlo,
                             fp16* __restrict__ othi, fp16* __restrict__ otlo)
{
    __shared__ fp16 tile[32][33];
    int z = blockIdx.z; int b = z / Hh, h = z % Hh;
    int t0 = blockIdx.x*32, d0 = blockIdx.y*32;
    #pragma unroll
    for (int pass=0; pass<2; pass++){
        const fp16* src = pass ? wlo : whi;
        fp16* dst = pass ? otlo : othi;
        for (int j=(int)threadIdx.y; j<32; j+=8)
            tile[j][threadIdx.x] = src[(ll)(b*Tt + t0 + j)*Ee + h*HDd + d0 + threadIdx.x];
        __syncthreads();
        for (int j=(int)threadIdx.y; j<32; j+=8)
            dst[(ll)z*HDd*Tt + (ll)(d0 + j)*Tt + t0 + threadIdx.x] = tile[threadIdx.x][j];
        __syncthreads();
    }
}

// causal softmax; writes P only up to the 128-aligned boundary (PV's KLIM
// never reads beyond it).
__global__ void softmax_split_kernel(const float* __restrict__ dots,
                                     fp16* __restrict__ ph, fp16* __restrict__ pl,
                                     float scale)
{
    ll r = blockIdx.x;
    int q = (int)(r & (Tt-1));
    const float* row = dots + r * Tt;
    fp16* hrow = ph + r * Tt;
    fp16* lrow = pl + r * Tt;
    int nv = q + 1;
    int kmax = ((q >> 7) + 1) << 7;     // 128-aligned write boundary
    float vals[4];
    float m = -INFINITY;
    #pragma unroll
    for (int it=0; it<4; it++){
        int k = threadIdx.x + it*256;
        float v = (k < nv) ? row[k]*scale : -INFINITY;
        vals[it] = v;
        m = fmaxf(m, v);
    }
    m = blockMax(m);
    float sum = 0.f;
    #pragma unroll
    for (int it=0; it<4; it++){
        int k = threadIdx.x + it*256;
        float e = (k < nv) ? expf(vals[it]-m) : 0.0f;
        vals[it] = e; sum += e;
    }
    sum = blockSum(sum);
    float invs = 1.0f / sum;
    #pragma unroll
    for (int it=0; it<4; it++){
        int k = threadIdx.x + it*256;
        if (k < kmax) {
            fp16 h, l; split2(vals[it]*invs, h, l);
            hrow[k] = h; lrow[k] = l;
        }
    }
}

__global__ void split_f32(const float* __restrict__ in, fp16* __restrict__ hi,
                          fp16* __restrict__ lo, ll n)
{
    ll i = ((ll)blockIdx.x*blockDim.x + threadIdx.x)*4;
    if (i >= n) return;
    float4 v = *(const float4*)(in + i);
    fp16 h0,l0,h1,l1,h2,l2,h3,l3;
    split2(v.x,h0,l0); split2(v.y,h1,l1); split2(v.z,h2,l2); split2(v.w,h3,l3);
    __half2 a; a.x=h0; a.y=h1; __half2 b; b.x=h2; b.y=h3;
    __half2 c; c.x=l0; c.y=l1; __half2 d; d.x=l2; d.y=l3;
    *(__half2*)(hi+i)   = a; *(__half2*)(hi+i+2) = b;
    *(__half2*)(lo+i)   = c; *(__half2*)(lo+i+2) = d;
}

// ---------------- host ---------------------------------------------------------
extern "C" void kernel_launch(void* const* d_in, const int* in_sizes, int n_in,
                              void* d_out, int out_size)
{
    const int*   idx  = (const int*)  d_in[0];
    const float* wte  = (const float*)d_in[1];
    const float* lmh  = (const float*)d_in[2];
    const float* qkvw = (const float*)d_in[3];
    const float* cpjw = (const float*)d_in[4];
    const float* denc = (const float*)d_in[5];
    const float* ddec = (const float*)d_in[6];
    const float* thr  = (const float*)d_in[7];
    const float* lamr = (const float*)d_in[8];
    const float* lamx = (const float*)d_in[9];
    float* out = (float*)d_out;

    cudaFuncSetAttribute(gemm_mm<3,0,false,false>, cudaFuncAttributeMaxDynamicSharedMemorySize, DSZ);
    cudaFuncSetAttribute(gemm_mm<2,0,true ,false>, cudaFuncAttributeMaxDynamicSharedMemorySize, DSZ);
    cudaFuncSetAttribute(gemm_mm<3,1,false,false>, cudaFuncAttributeMaxDynamicSharedMemorySize, DSZ);
    cudaFuncSetAttribute(gemm_mm<2,1,false,false>, cudaFuncAttributeMaxDynamicSharedMemorySize, DSZ);
    cudaFuncSetAttribute(gemm_mm<2,2,false,false>, cudaFuncAttributeMaxDynamicSharedMemorySize, DSZ);
    cudaFuncSetAttribute(gemm_mm<2,3,false,true >, cudaFuncAttributeMaxDynamicSharedMemorySize, DSZ);
    cudaFuncSetAttribute(gemm_mm<2,0,false,false>, cudaFuncAttributeMaxDynamicSharedMemorySize, DSZ);

    float *x, *x0, *wf, *dots;
    cudaGetSymbolAddress((void**)&x,    g_x);
    cudaGetSymbolAddress((void**)&x0,   g_x0);
    cudaGetSymbolAddress((void**)&wf,   g_w);
    cudaGetSymbolAddress((void**)&dots, g_dots);
    fp16 *hh,*hl,*wh,*wl,*wth,*wtl,*ph,*pl,*oh,*ol,*ah,*al;
    cudaGetSymbolAddress((void**)&hh,  g_hh);  cudaGetSymbolAddress((void**)&hl,  g_hl);
    cudaGetSymbolAddress((void**)&wh,  g_wh);  cudaGetSymbolAddress((void**)&wl,  g_wl);
    cudaGetSymbolAddress((void**)&wth, g_wth); cudaGetSymbolAddress((void**)&wtl, g_wtl);
    cudaGetSymbolAddress((void**)&ph,  g_ph);  cudaGetSymbolAddress((void**)&pl,  g_pl);
    cudaGetSymbolAddress((void**)&oh,  g_oh);  cudaGetSymbolAddress((void**)&ol,  g_ol);
    cudaGetSymbolAddress((void**)&ah,  g_ah);  cudaGetSymbolAddress((void**)&al,  g_al);
    fp16 *qh,*ql,*ch,*cl,*eh,*el,*dh,*dl,*lh,*llo;
    cudaGetSymbolAddress((void**)&qh, g_qkvh); cudaGetSymbolAddress((void**)&ql, g_qkvl);
    cudaGetSymbolAddress((void**)&ch, g_cpjh); cudaGetSymbolAddress((void**)&cl, g_cpjl);
    cudaGetSymbolAddress((void**)&eh, g_dech); cudaGetSymbolAddress((void**)&el, g_decl);
    cudaGetSymbolAddress((void**)&dh, g_ddh);  cudaGetSymbolAddress((void**)&dl, g_ddl);
    cudaGetSymbolAddress((void**)&lh, g_lmhh); cudaGetSymbolAddress((void**)&llo, g_lmhl);

    {
        ll n;
        n = (ll)Ll*Ee*Ee;    split_f32<<<(int)((n/4+255)/256),256>>>(qkvw, qh, ql, n);
        n = (ll)Ll*Ee*Ee;    split_f32<<<(int)((n/4+255)/256),256>>>(cpjw, ch, cl, n);
        n = (ll)Ll*HIDh*Ee;  split_f32<<<(int)((n/4+255)/256),256>>>(denc, eh, el, n);
        n = (ll)Ll*Ee*HIDh;  split_f32<<<(int)((n/4+255)/256),256>>>(ddec, dh, dl, n);
        n = (ll)Vv*Ee;       split_f32<<<(int)((n/4+255)/256),256>>>(lmh,  lh, llo, n);
    }

    const float scale = 0.08838834764831845f;
    const ll TE = (ll)Tt*Ee;
    const ll TT = (ll)Tt*Tt;
    const ll WT = (ll)HDd*Tt;

    embed_norm_kernel<<<NTOK,256>>>(idx, wte, x, x0);

    for (int i=0;i<Ll;i++){
        mix_norm_split<<<NTOK,256>>>(x, x0, hh, hl, lamr, lamx, i);

        // w = h @ qkv^T (fp32 out for rope), 3-product
        gemm_mm<3,0,false,false><<<dim3(6,32,1),256,DSZ>>>(
            hh, hl, qh + (ll)i*Ee*Ee, ql + (ll)i*Ee*Ee,
            wf, nullptr, nullptr, nullptr,
            Ee, Ee, Ee, Ee, 1, 0,0, 0,0, 0,0);

        rope_split_kernel<<<NTOK*Hh,128>>>(wf, wh, wl);
        transpose_hd<<<dim3(Tt/32, HDd/32, Bb*Hh), dim3(32,8)>>>(wh, wl, wth, wtl);

        // dots = W W^T (lower-triangular tiles only), 2-product
        gemm_mm<2,0,true,false><<<dim3(36,1,Bb*Hh),256,DSZ>>>(
            wh, wl, wh, wl,
            dots, nullptr, nullptr, nullptr,
            HDd, Ee, Ee, Tt, Hh, TE,(ll)HDd, TE,(ll)HDd, (ll)Hh*TT, TT);

        softmax_split_kernel<<<Bb*Hh*Tt,256>>>(dots, ph, pl, scale);

        // o = P @ W (K limited to bm+128), split output, 2-product
        gemm_mm<2,3,false,true><<<dim3(1,8,Bb*Hh),256,DSZ>>>(
            ph, pl, wth, wtl,
            nullptr, oh, ol, nullptr,
            Tt, Tt, Tt, Ee, Hh, (ll)Hh*TT,TT, (ll)Hh*WT,WT, TE,(ll)HDd);

        // x += o @ cproj^T, 3-product
        gemm_mm<3,1,false,false><<<dim3(6,32,1),256,DSZ>>>(
            oh, ol, ch + (ll)i*Ee*Ee, cl + (ll)i*Ee*Ee,
            x, nullptr, nullptr, nullptr,
            Ee, Ee, Ee, Ee, 1, 0,0, 0,0, 0,0);

        mix_norm_split<<<NTOK,256>>>(x, x0, hh, hl, nullptr, nullptr, 0);

        // a = relu(h @ denc^T - thr), split output, 2-product
        gemm_mm<2,2,false,false><<<dim3(24,32,1),256,DSZ>>>(
            hh, hl, eh + (ll)i*HIDh*Ee, el + (ll)i*HIDh*Ee,
            nullptr, ah, al, thr + (ll)i*HIDh,
            Ee, Ee, Ee, HIDh, 1, 0,0, 0,0, 0,0);

        // x += a @ ddec^T, 2-product
        gemm_mm<2,1,false,false><<<dim3(6,32,1),256,DSZ>>>(
            ah, al, dh + (ll)i*Ee*HIDh, dl + (ll)i*Ee*HIDh,
            x, nullptr, nullptr, nullptr,
            HIDh, HIDh, HIDh, Ee, 1, 0,0, 0,0, 0,0);
    }

    mix_norm_split<<<NTOK,256>>>(x, x0, hh, hl, nullptr, nullptr, 0);
    // lm_head: 2-product fp16 (terminal op)
    gemm_mm<2,0,false,false><<<dim3(393,32,1),256,DSZ>>>(
        hh, hl, lh, llo, out, nullptr, nullptr, nullptr,
        Ee, Ee, Ee, Vv, 1, 0,0, 0,0, 0,0);
}

// round 10
// speedup vs baseline: 3.6066x; 1.1639x over previous
#include <cuda_runtime.h>
#include <cuda_fp16.h>
#include <math.h>
#include <stdint.h>

#define Bb 4
#define Tt 1024
#define Vv 50304
#define Ee 768
#define Ll 12
#define Hh 6
#define HDd 128
#define HIDh 3072
#define NTOK (Bb*Tt)
#define EPS 1e-6f
typedef long long ll;
typedef __half fp16;

// ---------------- scratch ----------------------------------------------------
__device__ float g_x [NTOK*Ee];
__device__ float g_x0[NTOK*Ee];
__device__ float g_w [NTOK*Ee];
__device__ float g_dots[(ll)Bb*Hh*Tt*Tt];

__device__ fp16 g_hh[NTOK*Ee],  g_hl[NTOK*Ee];
__device__ fp16 g_wh[NTOK*Ee],  g_wl[NTOK*Ee];
__device__ fp16 g_wth[Bb*Hh*HDd*Tt], g_wtl[Bb*Hh*HDd*Tt];
__device__ fp16 g_ph[(ll)Bb*Hh*Tt*Tt], g_pl[(ll)Bb*Hh*Tt*Tt];
__device__ fp16 g_oh[NTOK*Ee],  g_ol[NTOK*Ee];
__device__ fp16 g_ah[NTOK*HIDh], g_al[NTOK*HIDh];

__device__ fp16 g_qkvh[Ll*Ee*Ee],   g_qkvl[Ll*Ee*Ee];
__device__ fp16 g_cpjh[Ll*Ee*Ee],   g_cpjl[Ll*Ee*Ee];
__device__ fp16 g_dech[Ll*HIDh*Ee], g_decl[Ll*HIDh*Ee];
__device__ fp16 g_ddh[Ll*Ee*HIDh],  g_ddl[Ll*Ee*HIDh];
__device__ fp16 g_lmhh[(ll)Vv*Ee],  g_lmhl[(ll)Vv*Ee];

// ---------------- helpers -----------------------------------------------------
__device__ __forceinline__ uint32_t smem_u32(const void* p){
    uint32_t a;
    asm("{ .reg .u64 t; cvta.to.shared.u64 t, %1; cvt.u32.u64 %0, t; }" : "=r"(a) : "l"(p));
    return a;
}
__device__ __forceinline__ void cp16(uint32_t dst, const void* src){
    asm volatile("cp.async.cg.shared.global [%0], [%1], 16;" :: "r"(dst), "l"(src));
}
#define CP_COMMIT() asm volatile("cp.async.commit_group;" ::: "memory")
template<int N>
__device__ __forceinline__ void cp_wait(){
    asm volatile("cp.async.wait_group %0;" :: "n"(N) : "memory");
}

__device__ __forceinline__ void ldm4(uint32_t a, uint32_t& r0, uint32_t& r1, uint32_t& r2, uint32_t& r3){
    asm volatile("ldmatrix.sync.aligned.m8n8.x4.shared.b16 {%0,%1,%2,%3}, [%4];"
        : "=r"(r0), "=r"(r1), "=r"(r2), "=r"(r3) : "r"(a));
}
__device__ __forceinline__ void mma16816(float* c, const uint32_t* a, const uint32_t* b){
    asm volatile("mma.sync.aligned.m16n8k16.row.col.f32.f16.f16.f32 "
        "{%0,%1,%2,%3}, {%4,%5,%6,%7}, {%8,%9}, {%0,%1,%2,%3};"
        : "+f"(c[0]), "+f"(c[1]), "+f"(c[2]), "+f"(c[3])
        : "r"(a[0]), "r"(a[1]), "r"(a[2]), "r"(a[3]), "r"(b[0]), "r"(b[1]));
}
__device__ __forceinline__ void split2(float v, fp16& h, fp16& l){
    h = __float2half_rn(v);
    l = __float2half_rn(v - __half2float(h));
}

// ---------------- reductions -------------------------------------------------
__device__ __forceinline__ float warpSum(float v){
    #pragma unroll
    for (int o=16;o;o>>=1) v += __shfl_xor_sync(0xffffffffu, v, o);
    return v;
}
__device__ __forceinline__ float warpMax(float v){
    #pragma unroll
    for (int o=16;o;o>>=1) v = fmaxf(v, __shfl_xor_sync(0xffffffffu, v, o));
    return v;
}
__device__ __forceinline__ float blockSum(float v){
    __shared__ float sh[33];
    __syncthreads();
    int lane = threadIdx.x & 31, wid = threadIdx.x >> 5;
    v = warpSum(v);
    if (lane == 0) sh[wid] = v;
    __syncthreads();
    int nw = (blockDim.x + 31) >> 5;
    float r = (threadIdx.x < nw) ? sh[threadIdx.x] : 0.0f;
    if (wid == 0) r = warpSum(r);
    if (threadIdx.x == 0) sh[32] = r;
    __syncthreads();
    return sh[32];
}
__device__ __forceinline__ float blockMax(float v){
    __shared__ float sh[33];
    __syncthreads();
    int lane = threadIdx.x & 31, wid = threadIdx.x >> 5;
    v = warpMax(v);
    if (lane == 0) sh[wid] = v;
    __syncthreads();
    int nw = (blockDim.x + 31) >> 5;
    float r = (threadIdx.x < nw) ? sh[threadIdx.x] : -INFINITY;
    if (wid == 0) r = warpMax(r);
    if (threadIdx.x == 0) sh[32] = r;
    __syncthreads();
    return sh[32];
}

// ---------------- HMMA GEMM ----------------------------------------------------
// C[M,N] = A[M,K] @ B[N,K]^T with hi/lo fp16 split.
// PRODS=3: AhBh + AhBl + AlBh.  PRODS=2: AhBh + AhBl (no Al tile in smem).
// Block 128x128, 8 warps of 64x32, mma.m16n8k16, KC=32.
// Stage layout: [Ah][Bh][Bl]([Al]).  PRODS=2: 3 tiles x 3 stages (92KB).
// PRODS=3: 4 tiles x 2 stages (82KB).  Both -> 2 CTAs/SM.
// EPI: 0 store f32, 1 accumulate f32, 2 relu(acc-bias[n]) split store, 3 split store
static constexpr int PITCH  = 40;
static constexpr int TILEB2 = 128*PITCH*2;    // 10240 B

template<int PRODS> struct Cfg {
    static constexpr int NT   = (PRODS==3) ? 4 : 3;       // tiles per stage
    static constexpr int NSTG = (PRODS==3) ? 2 : 3;
    static constexpr int STG  = NT*TILEB2;
    static constexpr int DSZ  = NSTG*STG;
    static constexpr int PRE  = NSTG-1;
};

__device__ __forceinline__ void load_tile(uint32_t dst, const fp16* src, int r0, int k0, int ld, int tid){
    #pragma unroll
    for (int j=0;j<2;j++){
        int slot = tid + j*256;
        int row = slot >> 2;
        int seg = slot & 3;
        cp16(dst + row*80 + seg*16, src + (ll)(r0+row)*ld + k0 + seg*8);
    }
}
template<int PRODS>
__device__ __forceinline__ void load_chunk(uint32_t sbase,
    const fp16* Ah, const fp16* Al, const fp16* Bh, const fp16* Bl,
    int bm, int bn, int k0, int lda, int ldb, int tid)
{
    load_tile(sbase,            Ah, bm, k0, lda, tid);
    load_tile(sbase +   TILEB2, Bh, bn, k0, ldb, tid);
    load_tile(sbase + 2*TILEB2, Bl, bn, k0, ldb, tid);
    if (PRODS == 3) load_tile(sbase + 3*TILEB2, Al, bm, k0, lda, tid);
}

template<int PRODS, int EPI, bool TRI, bool KLIM>
__global__ void __launch_bounds__(256,2) gemm_mm(
    const fp16* __restrict__ Ahi, const fp16* __restrict__ Alo,
    const fp16* __restrict__ Bhi, const fp16* __restrict__ Blo,
    float* __restrict__ C, fp16* __restrict__ Chi, fp16* __restrict__ Clo,
    const float* __restrict__ bias,
    int K, int lda, int ldb, int ldc, int zdiv,
    ll sA1, ll sA2, ll sB1, ll sB2, ll sC1, ll sC2)
{
    constexpr int NSTG = Cfg<PRODS>::NSTG;
    constexpr int STG  = Cfg<PRODS>::STG;
    constexpr int PRE  = Cfg<PRODS>::PRE;

    extern __shared__ char dsm[];
    uint32_t sb = smem_u32(dsm);

    int z  = blockIdx.z;
    int zq = z / zdiv, zr = z % zdiv;
    Ahi += zq*sA1 + zr*sA2; Alo += zq*sA1 + zr*sA2;
    Bhi += zq*sB1 + zr*sB2; Blo += zq*sB1 + zr*sB2;
    if (EPI==0 || EPI==1) { C += zq*sC1 + zr*sC2; }
    else { Chi += zq*sC1 + zr*sC2; Clo += zq*sC1 + zr*sC2; }

    int bm, bn;
    if (TRI) {
        int idx = blockIdx.x;
        int i_ = (int)((sqrtf(8.f*(float)idx + 1.f) - 1.f) * 0.5f);
        while ((i_+1)*(i_+2)/2 <= idx) i_++;
        while (i_*(i_+1)/2 > idx) i_--;
        bm = i_*128; bn = (idx - i_*(i_+1)/2)*128;
    } else { bm = blockIdx.y*128; bn = blockIdx.x*128; }

    int kmax = KLIM ? min(K, bm + 128) : K;
    int nch  = kmax >> 5;
    const int tid  = threadIdx.x;
    const int lane = tid & 31;
    const int wid  = tid >> 5;
    const int wm   = wid >> 2;
    const int wn   = wid & 3;

    float acc[4][4][4];
    #pragma unroll
    for (int i=0;i<4;i++)
        #pragma unroll
        for (int j=0;j<4;j++)
            #pragma unroll
            for (int q=0;q<4;q++) acc[i][j][q]=0.f;

    int pre = nch < PRE ? nch : PRE;
    for (int j=0;j<pre;j++){
        load_chunk<PRODS>(sb + (j%NSTG)*STG, Ahi,Alo,Bhi,Blo, bm,bn, j*32, lda,ldb, tid);
        CP_COMMIT();
    }
    for (int j=pre;j<PRE;j++) CP_COMMIT();

    const int a_row  = (lane & 15);
    const int a_colb = ((lane >> 4) << 3) * 2;
    const int b_rowo = ((lane >> 4) << 3) + (lane & 7);
    const int b_colb = (((lane >> 3) & 1) << 3) * 2;

    for (int i=0;i<nch;i++){
        cp_wait<PRE-1>();
        __syncthreads();
        // prefetch chunk i+PRE (its buffer was consumed at iter i-PRE, done)
        if (i + PRE < nch) {
            load_chunk<PRODS>(sb + ((i+PRE)%NSTG)*STG, Ahi,Alo,Bhi,Blo, bm,bn, (i+PRE)*32, lda,ldb, tid);
            CP_COMMIT();
        } else {
            CP_COMMIT();
        }

        uint32_t st = sb + (i%NSTG)*STG;
        uint32_t Abh = st, Bbh = st + TILEB2, Bbl = st + 2*TILEB2, Abl = st + 3*TILEB2;
        #pragma unroll
        for (int kk=0; kk<2; kk++){
            const int kb = kk*16*2;
            uint32_t bh[4][2], blr[4][2];
            #pragma unroll
            for (int np=0; np<2; np++){
                uint32_t off = (uint32_t)(wn*32 + np*16 + b_rowo)*80 + kb + b_colb;
                uint32_t r0,r1,r2,r3;
                ldm4(Bbh + off, r0,r1,r2,r3);
                bh[2*np][0]=r0; bh[2*np][1]=r1; bh[2*np+1][0]=r2; bh[2*np+1][1]=r3;
                ldm4(Bbl + off, r0,r1,r2,r3);
                blr[2*np][0]=r0; blr[2*np][1]=r1; blr[2*np+1][0]=r2; blr[2*np+1][1]=r3;
            }
            #pragma unroll
            for (int mt=0; mt<4; mt++){
                uint32_t off = (uint32_t)(wm*64 + mt*16 + a_row)*80 + kb + a_colb;
                uint32_t ah[4];
                ldm4(Abh + off, ah[0], ah[1], ah[2], ah[3]);
                if (PRODS == 3) {
                    uint32_t al[4];
                    ldm4(Abl + off, al[0], al[1], al[2], al[3]);
                    #pragma unroll
                    for (int nt=0; nt<4; nt++){
                        mma16816(acc[mt][nt], ah, bh[nt]);
                        mma16816(acc[mt][nt], ah, blr[nt]);
                        mma16816(acc[mt][nt], al, bh[nt]);
                    }
                } else {
                    #pragma unroll
                    for (int nt=0; nt<4; nt++){
                        mma16816(acc[mt][nt], ah, bh[nt]);
                        mma16816(acc[mt][nt], ah, blr[nt]);
                    }
                }
            }
        }
        __syncthreads();
    }

    #pragma unroll
    for (int mt=0; mt<4; mt++){
        #pragma unroll
        for (int nt=0; nt<4; nt++){
            int m0 = bm + wm*64 + mt*16 + (lane >> 2);
            int n0 = bn + wn*32 + nt*8  + (lane & 3)*2;
            float c0 = acc[mt][nt][0], c1 = acc[mt][nt][1];
            float c2 = acc[mt][nt][2], c3 = acc[mt][nt][3];
            if (EPI == 0) {
                *(float2*)(C + (ll)m0*ldc + n0)     = make_float2(c0, c1);
                *(float2*)(C + (ll)(m0+8)*ldc + n0) = make_float2(c2, c3);
            } else if (EPI == 1) {
                float2 o0 = *(const float2*)(C + (ll)m0*ldc + n0);
                float2 o1 = *(const float2*)(C + (ll)(m0+8)*ldc + n0);
                *(float2*)(C + (ll)m0*ldc + n0)     = make_float2(o0.x+c0, o0.y+c1);
                *(float2*)(C + (ll)(m0+8)*ldc + n0) = make_float2(o1.x+c2, o1.y+c3);
            } else {
                if (EPI == 2) {
                    float b0 = __ldg(bias + n0), b1 = __ldg(bias + n0 + 1);
                    c0 = fmaxf(c0-b0, 0.f); c1 = fmaxf(c1-b1, 0.f);
                    c2 = fmaxf(c2-b0, 0.f); c3 = fmaxf(c3-b1, 0.f);
                }
                fp16 h0,l0,h1,l1;
                split2(c0,h0,l0); split2(c1,h1,l1);
                __half2 hv; hv.x=h0; hv.y=h1;
                __half2 lv; lv.x=l0; lv.y=l1;
                *(__half2*)(Chi + (ll)m0*ldc + n0) = hv;
                *(__half2*)(Clo + (ll)m0*ldc + n0) = lv;
                split2(c2,h0,l0); split2(c3,h1,l1);
                hv.x=h0; hv.y=h1; lv.x=l0; lv.y=l1;
                *(__half2*)(Chi + (ll)(m0+8)*ldc + n0) = hv;
                *(__half2*)(Clo + (ll)(m0+8)*ldc + n0) = lv;
            }
        }
    }
}

// ---------------- elementwise kernels ----------------------------------------
__global__ void embed_norm_kernel(const int* __restrict__ idx,
                                  const float* __restrict__ wte,
                                  float* __restrict__ x, float* __restrict__ x0)
{
    int t = blockIdx.x;
    int tok = idx[t];
    const float* row = wte + (ll)tok * Ee;
    ll base = (ll)t * Ee;
    float v[3]; float ss = 0.f;
    #pragma unroll
    for (int j=0;j<3;j++){ int c = threadIdx.x + j*256; float m = row[c]; v[j]=m; ss += m*m; }
    ss = blockSum(ss);
    float inv = rsqrtf(ss*(1.0f/Ee) + EPS);
    #pragma unroll
    for (int j=0;j<3;j++){ int c = threadIdx.x + j*256; float o = v[j]*inv; x[base+c]=o; x0[base+c]=o; }
}

__global__ void mix_norm_split(float* __restrict__ x, const float* __restrict__ x0,
                               fp16* __restrict__ hh, fp16* __restrict__ hl,
                               const float* lamr, const float* lamx, int li)
{
    int t = blockIdx.x;
    float rl = lamr ? lamr[li] : 1.0f;
    float xl = lamx ? lamx[li] : 0.0f;
    ll base = (ll)t * Ee;
    float v[3]; float ss = 0.f;
    #pragma unroll
    for (int j=0;j<3;j++){
        int c = threadIdx.x + j*256;
        float m = rl*x[base+c] + xl*x0[base+c];
        v[j]=m; ss += m*m;
    }
    ss = blockSum(ss);
    float inv = rsqrtf(ss*(1.0f/Ee) + EPS);
    #pragma unroll
    for (int j=0;j<3;j++){
        int c = threadIdx.x + j*256;
        x[base+c] = v[j];
        fp16 h, l; split2(v[j]*inv, h, l);
        hh[base+c] = h; hl[base+c] = l;
    }
}

__global__ void rope_split_kernel(const float* __restrict__ wf,
                                  fp16* __restrict__ wh, fp16* __restrict__ wl)
{
    int n  = blockIdx.x / Hh;
    int hh = blockIdx.x % Hh;
    int t  = n & (Tt-1);
    const float* base = wf + (ll)n*Ee + hh*HDd;
    int d = threadIdx.x;
    __shared__ float s[HDd];
    float v = base[d];
    s[d] = v;
    float ss = blockSum(v*v);
    float inv = rsqrtf(ss*(1.0f/HDd) + EPS);
    float out;
    if (d < 64) {
        int j = d;
        float x1 = s[j], x2 = s[j+64];
        float fr = (float)t * powf(10000.0f, -((float)(2*j)) * (1.0f/128.0f));
        out = (x1*cosf(fr) + x2*sinf(fr)) * inv;
    } else {
        int j = d - 64;
        float x1 = s[j], x2 = s[d];
        float fr = (float)t * powf(10000.0f, -((float)(2*j)) * (1.0f/128.0f));
        out = (-x1*sinf(fr) + x2*cosf(fr)) * inv;
    }
    fp16 h, l; split2(out, h, l);
    ll o = (ll)n*Ee + hh*HDd + d;
    wh[o] = h; wl[o] = l;
}

__global__ void transpose_hd(const fp16* __restrict__ whi, const fp16* __restrict__ wlo,
                             fp16* __restrict__ othi, fp16* __restrict__ otlo)
{
    __shared__ fp16 tile[32][33];
    int z = blockIdx.z; int b = z / Hh, h = z % Hh;
    int t0 = blockIdx.x*32, d0 = blockIdx.y*32;
    #pragma unroll
    for (int pass=0; pass<2; pass++){
        const fp16* src = pass ? wlo : whi;
        fp16* dst = pass ? otlo : othi;
        for (int j=(int)threadIdx.y; j<32; j+=8)
            tile[j][threadIdx.x] = src[(ll)(b*Tt + t0 + j)*Ee + h*HDd + d0 + threadIdx.x];
        __syncthreads();
        for (int j=(int)threadIdx.y; j<32; j+=8)
            dst[(ll)z*HDd*Tt + (ll)(d0 + j)*Tt + t0 + threadIdx.x] = tile[threadIdx.x][j];
        __syncthreads();
    }
}

// causal softmax; writes P only up to the 128-aligned boundary (PV's KLIM
// never reads beyond it).
__global__ void softmax_split_kernel(const float* __restrict__ dots,
                                     fp16* __restrict__ ph, fp16* __restrict__ pl,
                                     float scale)
{
    ll r = blockIdx.x;
    int q = (int)(r & (Tt-1));
    const float* row = dots + r * Tt;
    fp16* hrow = ph + r * Tt;
    fp16* lrow = pl + r * Tt;
    int nv = q + 1;
    int kmax = ((q >> 7) + 1) << 7;
    float vals[4];
    float m = -INFINITY;
    #pragma unroll
    for (int it=0; it<4; it++){
        int k = threadIdx.x + it*256;
        float v = (k < nv) ? row[k]*scale : -INFINITY;
        vals[it] = v;
        m = fmaxf(m, v);
    }
    m = blockMax(m);
    float sum = 0.f;
    #pragma unroll
    for (int it=0; it<4; it++){
        int k = threadIdx.x + it*256;
        float e = (k < nv) ? expf(vals[it]-m) : 0.0f;
        vals[it] = e; sum += e;
    }
    sum = blockSum(sum);
    float invs = 1.0f / sum;
    #pragma unroll
    for (int it=0; it<4; it++){
        int k = threadIdx.x + it*256;
        if (k < kmax) {
            fp16 h, l; split2(vals[it]*invs, h, l);
            hrow[k] = h; lrow[k] = l;
        }
    }
}

__global__ void split_f32(const float* __restrict__ in, fp16* __restrict__ hi,
                          fp16* __restrict__ lo, ll n)
{
    ll i = ((ll)blockIdx.x*blockDim.x + threadIdx.x)*4;
    if (i >= n) return;
    float4 v = *(const float4*)(in + i);
    fp16 h0,l0,h1,l1,h2,l2,h3,l3;
    split2(v.x,h0,l0); split2(v.y,h1,l1); split2(v.z,h2,l2); split2(v.w,h3,l3);
    __half2 a; a.x=h0; a.y=h1; __half2 b; b.x=h2; b.y=h3;
    __half2 c; c.x=l0; c.y=l1; __half2 d; d.x=l2; d.y=l3;
    *(__half2*)(hi+i)   = a; *(__half2*)(hi+i+2) = b;
    *(__half2*)(lo+i)   = c; *(__half2*)(lo+i+2) = d;
}

// ---------------- host ---------------------------------------------------------
extern "C" void kernel_launch(void* const* d_in, const int* in_sizes, int n_in,
                              void* d_out, int out_size)
{
    const int*   idx  = (const int*)  d_in[0];
    const float* wte  = (const float*)d_in[1];
    const float* lmh  = (const float*)d_in[2];
    const float* qkvw = (const float*)d_in[3];
    const float* cpjw = (const float*)d_in[4];
    const float* denc = (const float*)d_in[5];
    const float* ddec = (const float*)d_in[6];
    const float* thr  = (const float*)d_in[7];
    const float* lamr = (const float*)d_in[8];
    const float* lamx = (const float*)d_in[9];
    float* out = (float*)d_out;

    constexpr int DSZ2 = Cfg<2>::DSZ;   // 92160
    constexpr int DSZ3 = Cfg<3>::DSZ;   // 81920
    cudaFuncSetAttribute(gemm_mm<3,0,false,false>, cudaFuncAttributeMaxDynamicSharedMemorySize, DSZ3);
    cudaFuncSetAttribute(gemm_mm<3,1,false,false>, cudaFuncAttributeMaxDynamicSharedMemorySize, DSZ3);
    cudaFuncSetAttribute(gemm_mm<2,0,true ,false>, cudaFuncAttributeMaxDynamicSharedMemorySize, DSZ2);
    cudaFuncSetAttribute(gemm_mm<2,1,false,false>, cudaFuncAttributeMaxDynamicSharedMemorySize, DSZ2);
    cudaFuncSetAttribute(gemm_mm<2,2,false,false>, cudaFuncAttributeMaxDynamicSharedMemorySize, DSZ2);
    cudaFuncSetAttribute(gemm_mm<2,3,false,true >, cudaFuncAttributeMaxDynamicSharedMemorySize, DSZ2);
    cudaFuncSetAttribute(gemm_mm<2,0,false,false>, cudaFuncAttributeMaxDynamicSharedMemorySize, DSZ2);

    float *x, *x0, *wf, *dots;
    cudaGetSymbolAddress((void**)&x,    g_x);
    cudaGetSymbolAddress((void**)&x0,   g_x0);
    cudaGetSymbolAddress((void**)&wf,   g_w);
    cudaGetSymbolAddress((void**)&dots, g_dots);
    fp16 *hh,*hl,*wh,*wl,*wth,*wtl,*ph,*pl,*oh,*ol,*ah,*al;
    cudaGetSymbolAddress((void**)&hh,  g_hh);  cudaGetSymbolAddress((void**)&hl,  g_hl);
    cudaGetSymbolAddress((void**)&wh,  g_wh);  cudaGetSymbolAddress((void**)&wl,  g_wl);
    cudaGetSymbolAddress((void**)&wth, g_wth); cudaGetSymbolAddress((void**)&wtl, g_wtl);
    cudaGetSymbolAddress((void**)&ph,  g_ph);  cudaGetSymbolAddress((void**)&pl,  g_pl);
    cudaGetSymbolAddress((void**)&oh,  g_oh);  cudaGetSymbolAddress((void**)&ol,  g_ol);
    cudaGetSymbolAddress((void**)&ah,  g_ah);  cudaGetSymbolAddress((void**)&al,  g_al);
    fp16 *qh,*ql,*ch,*cl,*eh,*el,*dh,*dl,*lh,*llo;
    cudaGetSymbolAddress((void**)&qh, g_qkvh); cudaGetSymbolAddress((void**)&ql, g_qkvl);
    cudaGetSymbolAddress((void**)&ch, g_cpjh); cudaGetSymbolAddress((void**)&cl, g_cpjl);
    cudaGetSymbolAddress((void**)&eh, g_dech); cudaGetSymbolAddress((void**)&el, g_decl);
    cudaGetSymbolAddress((void**)&dh, g_ddh);  cudaGetSymbolAddress((void**)&dl, g_ddl);
    cudaGetSymbolAddress((void**)&lh, g_lmhh); cudaGetSymbolAddress((void**)&llo, g_lmhl);

    {
        ll n;
        n = (ll)Ll*Ee*Ee;    split_f32<<<(int)((n/4+255)/256),256>>>(qkvw, qh, ql, n);
        n = (ll)Ll*Ee*Ee;    split_f32<<<(int)((n/4+255)/256),256>>>(cpjw, ch, cl, n);
        n = (ll)Ll*HIDh*Ee;  split_f32<<<(int)((n/4+255)/256),256>>>(denc, eh, el, n);
        n = (ll)Ll*Ee*HIDh;  split_f32<<<(int)((n/4+255)/256),256>>>(ddec, dh, dl, n);
        n = (ll)Vv*Ee;       split_f32<<<(int)((n/4+255)/256),256>>>(lmh,  lh, llo, n);
    }

    const float scale = 0.08838834764831845f;
    const ll TE = (ll)Tt*Ee;
    const ll TT = (ll)Tt*Tt;
    const ll WT = (ll)HDd*Tt;

    embed_norm_kernel<<<NTOK,256>>>(idx, wte, x, x0);

    for (int i=0;i<Ll;i++){
        mix_norm_split<<<NTOK,256>>>(x, x0, hh, hl, lamr, lamx, i);

        // w = h @ qkv^T (fp32 out for rope), 3-product
        gemm_mm<3,0,false,false><<<dim3(6,32,1),256,DSZ3>>>(
            hh, hl, qh + (ll)i*Ee*Ee, ql + (ll)i*Ee*Ee,
            wf, nullptr, nullptr, nullptr,
            Ee, Ee, Ee, Ee, 1, 0,0, 0,0, 0,0);

        rope_split_kernel<<<NTOK*Hh,128>>>(wf, wh, wl);
        transpose_hd<<<dim3(Tt/32, HDd/32, Bb*Hh), dim3(32,8)>>>(wh, wl, wth, wtl);

        // dots = W W^T (lower-triangular tiles only), 2-product
        gemm_mm<2,0,true,false><<<dim3(36,1,Bb*Hh),256,DSZ2>>>(
            wh, wl, wh, wl,
            dots, nullptr, nullptr, nullptr,
            HDd, Ee, Ee, Tt, Hh, TE,(ll)HDd, TE,(ll)HDd, (ll)Hh*TT, TT);

        softmax_split_kernel<<<Bb*Hh*Tt,256>>>(dots, ph, pl, scale);

        // o = P @ W (K limited to bm+128), split output, 2-product
        gemm_mm<2,3,false,true><<<dim3(1,8,Bb*Hh),256,DSZ2>>>(
            ph, pl, wth, wtl,
            nullptr, oh, ol, nullptr,
            Tt, Tt, Tt, Ee, Hh, (ll)Hh*TT,TT, (ll)Hh*WT,WT, TE,(ll)HDd);

        // x += o @ cproj^T, 3-product
        gemm_mm<3,1,false,false><<<dim3(6,32,1),256,DSZ3>>>(
            oh, ol, ch + (ll)i*Ee*Ee, cl + (ll)i*Ee*Ee,
            x, nullptr, nullptr, nullptr,
            Ee, Ee, Ee, Ee, 1, 0,0, 0,0, 0,0);

        mix_norm_split<<<NTOK,256>>>(x, x0, hh, hl, nullptr, nullptr, 0);

        // a = relu(h @ denc^T - thr), split output, 2-product
        gemm_mm<2,2,false,false><<<dim3(24,32,1),256,DSZ2>>>(
            hh, hl, eh + (ll)i*HIDh*Ee, el + (ll)i*HIDh*Ee,
            nullptr, ah, al, thr + (ll)i*HIDh,
            Ee, Ee, Ee, HIDh, 1, 0,0, 0,0, 0,0);

        // x += a @ ddec^T, 2-product
        gemm_mm<2,1,false,false><<<dim3(6,32,1),256,DSZ2>>>(
            ah, al, dh + (ll)i*Ee*HIDh, dl + (ll)i*Ee*HIDh,
            x, nullptr, nullptr, nullptr,
            HIDh, HIDh, HIDh, Ee, 1, 0,0, 0,0, 0,0);
    }

    mix_norm_split<<<NTOK,256>>>(x, x0, hh, hl, nullptr, nullptr, 0);
    // lm_head: 2-product fp16 (terminal op)
    gemm_mm<2,0,false,false><<<dim3(393,32,1),256,DSZ2>>>(
        hh, hl, lh, llo, out, nullptr, nullptr, nullptr,
        Ee, Ee, Ee, Vv, 1, 0,0, 0,0, 0,0);
}

// round 11
// speedup vs baseline: 3.8833x; 1.0767x over previous
#include <cuda_runtime.h>
#include <cuda_fp16.h>
#include <math.h>
#include <stdint.h>

#define Bb 4
#define Tt 1024
#define Vv 50304
#define Ee 768
#define Ll 12
#define Hh 6
#define HDd 128
#define HIDh 3072
#define NTOK (Bb*Tt)
#define EPS 1e-6f
typedef long long ll;
typedef __half fp16;

// ---------------- scratch ----------------------------------------------------
__device__ float g_x [NTOK*Ee];
__device__ float g_x0[NTOK*Ee];
__device__ float g_w [NTOK*Ee];
__device__ float g_dots[(ll)Bb*Hh*Tt*Tt];

__device__ fp16 g_hh[NTOK*Ee],  g_hl[NTOK*Ee];
__device__ fp16 g_wh[NTOK*Ee],  g_wl[NTOK*Ee];
__device__ fp16 g_wth[Bb*Hh*HDd*Tt], g_wtl[Bb*Hh*HDd*Tt];
__device__ fp16 g_ph[(ll)Bb*Hh*Tt*Tt], g_pl[(ll)Bb*Hh*Tt*Tt];
__device__ fp16 g_oh[NTOK*Ee],  g_ol[NTOK*Ee];
__device__ fp16 g_ah[NTOK*HIDh], g_al[NTOK*HIDh];

__device__ fp16 g_qkvh[Ll*Ee*Ee],   g_qkvl[Ll*Ee*Ee];
__device__ fp16 g_cpjh[Ll*Ee*Ee],   g_cpjl[Ll*Ee*Ee];
__device__ fp16 g_dech[Ll*HIDh*Ee], g_decl[Ll*HIDh*Ee];
__device__ fp16 g_ddh[Ll*Ee*HIDh],  g_ddl[Ll*Ee*HIDh];
__device__ fp16 g_lmhh[(ll)Vv*Ee];

// ---------------- helpers -----------------------------------------------------
__device__ __forceinline__ uint32_t smem_u32(const void* p){
    uint32_t a;
    asm("{ .reg .u64 t; cvta.to.shared.u64 t, %1; cvt.u32.u64 %0, t; }" : "=r"(a) : "l"(p));
    return a;
}
__device__ __forceinline__ void cp16(uint32_t dst, const void* src){
    asm volatile("cp.async.cg.shared.global [%0], [%1], 16;" :: "r"(dst), "l"(src));
}
#define CP_COMMIT() asm volatile("cp.async.commit_group;" ::: "memory")
template<int N>
__device__ __forceinline__ void cp_wait(){
    asm volatile("cp.async.wait_group %0;" :: "n"(N) : "memory");
}

__device__ __forceinline__ void ldm4(uint32_t a, uint32_t& r0, uint32_t& r1, uint32_t& r2, uint32_t& r3){
    asm volatile("ldmatrix.sync.aligned.m8n8.x4.shared.b16 {%0,%1,%2,%3}, [%4];"
        : "=r"(r0), "=r"(r1), "=r"(r2), "=r"(r3) : "r"(a));
}
__device__ __forceinline__ void mma16816(float* c, const uint32_t* a, const uint32_t* b){
    asm volatile("mma.sync.aligned.m16n8k16.row.col.f32.f16.f16.f32 "
        "{%0,%1,%2,%3}, {%4,%5,%6,%7}, {%8,%9}, {%0,%1,%2,%3};"
        : "+f"(c[0]), "+f"(c[1]), "+f"(c[2]), "+f"(c[3])
        : "r"(a[0]), "r"(a[1]), "r"(a[2]), "r"(a[3]), "r"(b[0]), "r"(b[1]));
}
__device__ __forceinline__ void split2(float v, fp16& h, fp16& l){
    h = __float2half_rn(v);
    l = __float2half_rn(v - __half2float(h));
}

// ---------------- reductions -------------------------------------------------
__device__ __forceinline__ float warpSum(float v){
    #pragma unroll
    for (int o=16;o;o>>=1) v += __shfl_xor_sync(0xffffffffu, v, o);
    return v;
}
__device__ __forceinline__ float warpMax(float v){
    #pragma unroll
    for (int o=16;o;o>>=1) v = fmaxf(v, __shfl_xor_sync(0xffffffffu, v, o));
    return v;
}
__device__ __forceinline__ float blockSum(float v){
    __shared__ float sh[33];
    __syncthreads();
    int lane = threadIdx.x & 31, wid = threadIdx.x >> 5;
    v = warpSum(v);
    if (lane == 0) sh[wid] = v;
    __syncthreads();
    int nw = (blockDim.x + 31) >> 5;
    float r = (threadIdx.x < nw) ? sh[threadIdx.x] : 0.0f;
    if (wid == 0) r = warpSum(r);
    if (threadIdx.x == 0) sh[32] = r;
    __syncthreads();
    return sh[32];
}
__device__ __forceinline__ float blockMax(float v){
    __shared__ float sh[33];
    __syncthreads();
    int lane = threadIdx.x & 31, wid = threadIdx.x >> 5;
    v = warpMax(v);
    if (lane == 0) sh[wid] = v;
    __syncthreads();
    int nw = (blockDim.x + 31) >> 5;
    float r = (threadIdx.x < nw) ? sh[threadIdx.x] : -INFINITY;
    if (wid == 0) r = warpMax(r);
    if (threadIdx.x == 0) sh[32] = r;
    __syncthreads();
    return sh[32];
}

// ---------------- HMMA GEMM ----------------------------------------------------
// C[M,N] = A[M,K] @ B[N,K]^T with hi/lo fp16 split.
// PRODS=3: AhBh+AhBl+AlBh. PRODS=2: AhBh+AhBl. PRODS=1: AhBh only.
// Block 128x128, 8 warps of 64x32, mma.m16n8k16, KC=32.
// Stage tiles: [Ah][Bh]([Bl])([Al]).
// PRODS=1: 2x3 stages (61KB). PRODS=2: 3x3 (92KB). PRODS=3: 4x2 (82KB). All 2 CTAs/SM.
// EPI: 0 store f32, 1 accumulate f32, 2 relu(acc-bias[n]) split store, 3 split store
static constexpr int PITCH  = 40;
static constexpr int TILEB2 = 128*PITCH*2;    // 10240 B

template<int PRODS> struct Cfg {
    static constexpr int NT   = (PRODS==3) ? 4 : ((PRODS==2) ? 3 : 2);
    static constexpr int NSTG = (PRODS==3) ? 2 : 3;
    static constexpr int STG  = NT*TILEB2;
    static constexpr int DSZ  = NSTG*STG;
    static constexpr int PRE  = NSTG-1;
};

__device__ __forceinline__ void load_tile(uint32_t dst, const fp16* src, int r0, int k0, int ld, int tid){
    #pragma unroll
    for (int j=0;j<2;j++){
        int slot = tid + j*256;
        int row = slot >> 2;
        int seg = slot & 3;
        cp16(dst + row*80 + seg*16, src + (ll)(r0+row)*ld + k0 + seg*8);
    }
}
template<int PRODS>
__device__ __forceinline__ void load_chunk(uint32_t sbase,
    const fp16* Ah, const fp16* Al, const fp16* Bh, const fp16* Bl,
    int bm, int bn, int k0, int lda, int ldb, int tid)
{
    load_tile(sbase,            Ah, bm, k0, lda, tid);
    load_tile(sbase +   TILEB2, Bh, bn, k0, ldb, tid);
    if (PRODS >= 2) load_tile(sbase + 2*TILEB2, Bl, bn, k0, ldb, tid);
    if (PRODS == 3) load_tile(sbase + 3*TILEB2, Al, bm, k0, lda, tid);
}

template<int PRODS, int EPI, bool TRI, bool KLIM>
__global__ void __launch_bounds__(256,2) gemm_mm(
    const fp16* __restrict__ Ahi, const fp16* __restrict__ Alo,
    const fp16* __restrict__ Bhi, const fp16* __restrict__ Blo,
    float* __restrict__ C, fp16* __restrict__ Chi, fp16* __restrict__ Clo,
    const float* __restrict__ bias,
    int K, int lda, int ldb, int ldc, int zdiv,
    ll sA1, ll sA2, ll sB1, ll sB2, ll sC1, ll sC2)
{
    constexpr int NSTG = Cfg<PRODS>::NSTG;
    constexpr int STG  = Cfg<PRODS>::STG;
    constexpr int PRE  = Cfg<PRODS>::PRE;

    extern __shared__ char dsm[];
    uint32_t sb = smem_u32(dsm);

    int z  = blockIdx.z;
    int zq = z / zdiv, zr = z % zdiv;
    Ahi += zq*sA1 + zr*sA2; Alo += zq*sA1 + zr*sA2;
    Bhi += zq*sB1 + zr*sB2; Blo += zq*sB1 + zr*sB2;
    if (EPI==0 || EPI==1) { C += zq*sC1 + zr*sC2; }
    else { Chi += zq*sC1 + zr*sC2; Clo += zq*sC1 + zr*sC2; }

    int bm, bn;
    if (TRI) {
        int idx = blockIdx.x;
        int i_ = (int)((sqrtf(8.f*(float)idx + 1.f) - 1.f) * 0.5f);
        while ((i_+1)*(i_+2)/2 <= idx) i_++;
        while (i_*(i_+1)/2 > idx) i_--;
        bm = i_*128; bn = (idx - i_*(i_+1)/2)*128;
    } else { bm = blockIdx.y*128; bn = blockIdx.x*128; }

    int kmax = KLIM ? min(K, bm + 128) : K;
    int nch  = kmax >> 5;
    const int tid  = threadIdx.x;
    const int lane = tid & 31;
    const int wid  = tid >> 5;
    const int wm   = wid >> 2;
    const int wn   = wid & 3;

    float acc[4][4][4];
    #pragma unroll
    for (int i=0;i<4;i++)
        #pragma unroll
        for (int j=0;j<4;j++)
            #pragma unroll
            for (int q=0;q<4;q++) acc[i][j][q]=0.f;

    int pre = nch < PRE ? nch : PRE;
    for (int j=0;j<pre;j++){
        load_chunk<PRODS>(sb + (j%NSTG)*STG, Ahi,Alo,Bhi,Blo, bm,bn, j*32, lda,ldb, tid);
        CP_COMMIT();
    }
    for (int j=pre;j<PRE;j++) CP_COMMIT();

    const int a_row  = (lane & 15);
    const int a_colb = ((lane >> 4) << 3) * 2;
    const int b_rowo = ((lane >> 4) << 3) + (lane & 7);
    const int b_colb = (((lane >> 3) & 1) << 3) * 2;

    for (int i=0;i<nch;i++){
        cp_wait<PRE-1>();
        __syncthreads();
        if (i + PRE < nch) {
            load_chunk<PRODS>(sb + ((i+PRE)%NSTG)*STG, Ahi,Alo,Bhi,Blo, bm,bn, (i+PRE)*32, lda,ldb, tid);
            CP_COMMIT();
        } else {
            CP_COMMIT();
        }

        uint32_t st = sb + (i%NSTG)*STG;
        uint32_t Abh = st, Bbh = st + TILEB2, Bbl = st + 2*TILEB2, Abl = st + 3*TILEB2;
        #pragma unroll
        for (int kk=0; kk<2; kk++){
            const int kb = kk*16*2;
            uint32_t bh[4][2], blr[4][2];
            #pragma unroll
            for (int np=0; np<2; np++){
                uint32_t off = (uint32_t)(wn*32 + np*16 + b_rowo)*80 + kb + b_colb;
                uint32_t r0,r1,r2,r3;
                ldm4(Bbh + off, r0,r1,r2,r3);
                bh[2*np][0]=r0; bh[2*np][1]=r1; bh[2*np+1][0]=r2; bh[2*np+1][1]=r3;
                if (PRODS >= 2) {
                    ldm4(Bbl + off, r0,r1,r2,r3);
                    blr[2*np][0]=r0; blr[2*np][1]=r1; blr[2*np+1][0]=r2; blr[2*np+1][1]=r3;
                }
            }
            #pragma unroll
            for (int mt=0; mt<4; mt++){
                uint32_t off = (uint32_t)(wm*64 + mt*16 + a_row)*80 + kb + a_colb;
                uint32_t ah[4];
                ldm4(Abh + off, ah[0], ah[1], ah[2], ah[3]);
                if (PRODS == 3) {
                    uint32_t al[4];
                    ldm4(Abl + off, al[0], al[1], al[2], al[3]);
                    #pragma unroll
                    for (int nt=0; nt<4; nt++){
                        mma16816(acc[mt][nt], ah, bh[nt]);
                        mma16816(acc[mt][nt], ah, blr[nt]);
                        mma16816(acc[mt][nt], al, bh[nt]);
                    }
                } else if (PRODS == 2) {
                    #pragma unroll
                    for (int nt=0; nt<4; nt++){
                        mma16816(acc[mt][nt], ah, bh[nt]);
                        mma16816(acc[mt][nt], ah, blr[nt]);
                    }
                } else {
                    #pragma unroll
                    for (int nt=0; nt<4; nt++){
                        mma16816(acc[mt][nt], ah, bh[nt]);
                    }
                }
            }
        }
        __syncthreads();
    }

    #pragma unroll
    for (int mt=0; mt<4; mt++){
        #pragma unroll
        for (int nt=0; nt<4; nt++){
            int m0 = bm + wm*64 + mt*16 + (lane >> 2);
            int n0 = bn + wn*32 + nt*8  + (lane & 3)*2;
            float c0 = acc[mt][nt][0], c1 = acc[mt][nt][1];
            float c2 = acc[mt][nt][2], c3 = acc[mt][nt][3];
            if (EPI == 0) {
                *(float2*)(C + (ll)m0*ldc + n0)     = make_float2(c0, c1);
                *(float2*)(C + (ll)(m0+8)*ldc + n0) = make_float2(c2, c3);
            } else if (EPI == 1) {
                float2 o0 = *(const float2*)(C + (ll)m0*ldc + n0);
                float2 o1 = *(const float2*)(C + (ll)(m0+8)*ldc + n0);
                *(float2*)(C + (ll)m0*ldc + n0)     = make_float2(o0.x+c0, o0.y+c1);
                *(float2*)(C + (ll)(m0+8)*ldc + n0) = make_float2(o1.x+c2, o1.y+c3);
            } else {
                if (EPI == 2) {
                    float b0 = __ldg(bias + n0), b1 = __ldg(bias + n0 + 1);
                    c0 = fmaxf(c0-b0, 0.f); c1 = fmaxf(c1-b1, 0.f);
                    c2 = fmaxf(c2-b0, 0.f); c3 = fmaxf(c3-b1, 0.f);
                }
                fp16 h0,l0,h1,l1;
                split2(c0,h0,l0); split2(c1,h1,l1);
                __half2 hv; hv.x=h0; hv.y=h1;
                __half2 lv; lv.x=l0; lv.y=l1;
                *(__half2*)(Chi + (ll)m0*ldc + n0) = hv;
                *(__half2*)(Clo + (ll)m0*ldc + n0) = lv;
                split2(c2,h0,l0); split2(c3,h1,l1);
                hv.x=h0; hv.y=h1; lv.x=l0; lv.y=l1;
                *(__half2*)(Chi + (ll)(m0+8)*ldc + n0) = hv;
                *(__half2*)(Clo + (ll)(m0+8)*ldc + n0) = lv;
            }
        }
    }
}

// ---------------- elementwise kernels ----------------------------------------
__global__ void embed_norm_kernel(const int* __restrict__ idx,
                                  const float* __restrict__ wte,
                                  float* __restrict__ x, float* __restrict__ x0)
{
    int t = blockIdx.x;
    int tok = idx[t];
    const float* row = wte + (ll)tok * Ee;
    ll base = (ll)t * Ee;
    float v[3]; float ss = 0.f;
    #pragma unroll
    for (int j=0;j<3;j++){ int c = threadIdx.x + j*256; float m = row[c]; v[j]=m; ss += m*m; }
    ss = blockSum(ss);
    float inv = rsqrtf(ss*(1.0f/Ee) + EPS);
    #pragma unroll
    for (int j=0;j<3;j++){ int c = threadIdx.x + j*256; float o = v[j]*inv; x[base+c]=o; x0[base+c]=o; }
}

__global__ void mix_norm_split(float* __restrict__ x, const float* __restrict__ x0,
                               fp16* __restrict__ hh, fp16* __restrict__ hl,
                               const float* lamr, const float* lamx, int li)
{
    int t = blockIdx.x;
    float rl = lamr ? lamr[li] : 1.0f;
    float xl = lamx ? lamx[li] : 0.0f;
    ll base = (ll)t * Ee;
    float v[3]; float ss = 0.f;
    #pragma unroll
    for (int j=0;j<3;j++){
        int c = threadIdx.x + j*256;
        float m = rl*x[base+c] + xl*x0[base+c];
        v[j]=m; ss += m*m;
    }
    ss = blockSum(ss);
    float inv = rsqrtf(ss*(1.0f/Ee) + EPS);
    #pragma unroll
    for (int j=0;j<3;j++){
        int c = threadIdx.x + j*256;
        x[base+c] = v[j];
        fp16 h, l; split2(v[j]*inv, h, l);
        hh[base+c] = h; hl[base+c] = l;
    }
}

__global__ void rope_split_kernel(const float* __restrict__ wf,
                                  fp16* __restrict__ wh, fp16* __restrict__ wl)
{
    int n  = blockIdx.x / Hh;
    int hh = blockIdx.x % Hh;
    int t  = n & (Tt-1);
    const float* base = wf + (ll)n*Ee + hh*HDd;
    int d = threadIdx.x;
    __shared__ float s[HDd];
    float v = base[d];
    s[d] = v;
    float ss = blockSum(v*v);
    float inv = rsqrtf(ss*(1.0f/HDd) + EPS);
    float out;
    if (d < 64) {
        int j = d;
        float x1 = s[j], x2 = s[j+64];
        float fr = (float)t * powf(10000.0f, -((float)(2*j)) * (1.0f/128.0f));
        out = (x1*cosf(fr) + x2*sinf(fr)) * inv;
    } else {
        int j = d - 64;
        float x1 = s[j], x2 = s[d];
        float fr = (float)t * powf(10000.0f, -((float)(2*j)) * (1.0f/128.0f));
        out = (-x1*sinf(fr) + x2*cosf(fr)) * inv;
    }
    fp16 h, l; split2(out, h, l);
    ll o = (ll)n*Ee + hh*HDd + d;
    wh[o] = h; wl[o] = l;
}

__global__ void transpose_hd(const fp16* __restrict__ whi, const fp16* __restrict__ wlo,
                             fp16* __restrict__ othi, fp16* __restrict__ otlo)
{
    __shared__ fp16 tile[32][33];
    int z = blockIdx.z; int b = z / Hh, h = z % Hh;
    int t0 = blockIdx.x*32, d0 = blockIdx.y*32;
    #pragma unroll
    for (int pass=0; pass<2; pass++){
        const fp16* src = pass ? wlo : whi;
        fp16* dst = pass ? otlo : othi;
        for (int j=(int)threadIdx.y; j<32; j+=8)
            tile[j][threadIdx.x] = src[(ll)(b*Tt + t0 + j)*Ee + h*HDd + d0 + threadIdx.x];
        __syncthreads();
        for (int j=(int)threadIdx.y; j<32; j+=8)
            dst[(ll)z*HDd*Tt + (ll)(d0 + j)*Tt + t0 + threadIdx.x] = tile[threadIdx.x][j];
        __syncthreads();
    }
}

// causal softmax; writes P only up to the 128-aligned boundary (PV's KLIM
// never reads beyond it).
__global__ void softmax_split_kernel(const float* __restrict__ dots,
                                     fp16* __restrict__ ph, fp16* __restrict__ pl,
                                     float scale)
{
    ll r = blockIdx.x;
    int q = (int)(r & (Tt-1));
    const float* row = dots + r * Tt;
    fp16* hrow = ph + r * Tt;
    fp16* lrow = pl + r * Tt;
    int nv = q + 1;
    int kmax = ((q >> 7) + 1) << 7;
    float vals[4];
    float m = -INFINITY;
    #pragma unroll
    for (int it=0; it<4; it++){
        int k = threadIdx.x + it*256;
        float v = (k < nv) ? row[k]*scale : -INFINITY;
        vals[it] = v;
        m = fmaxf(m, v);
    }
    m = blockMax(m);
    float sum = 0.f;
    #pragma unroll
    for (int it=0; it<4; it++){
        int k = threadIdx.x + it*256;
        float e = (k < nv) ? expf(vals[it]-m) : 0.0f;
        vals[it] = e; sum += e;
    }
    sum = blockSum(sum);
    float invs = 1.0f / sum;
    #pragma unroll
    for (int it=0; it<4; it++){
        int k = threadIdx.x + it*256;
        if (k < kmax) {
            fp16 h, l; split2(vals[it]*invs, h, l);
            hrow[k] = h; lrow[k] = l;
        }
    }
}

__global__ void split_f32(const float* __restrict__ in, fp16* __restrict__ hi,
                          fp16* __restrict__ lo, ll n)
{
    ll i = ((ll)blockIdx.x*blockDim.x + threadIdx.x)*4;
    if (i >= n) return;
    float4 v = *(const float4*)(in + i);
    fp16 h0,l0,h1,l1,h2,l2,h3,l3;
    split2(v.x,h0,l0); split2(v.y,h1,l1); split2(v.z,h2,l2); split2(v.w,h3,l3);
    __half2 a; a.x=h0; a.y=h1; __half2 b; b.x=h2; b.y=h3;
    __half2 c; c.x=l0; c.y=l1; __half2 d; d.x=l2; d.y=l3;
    *(__half2*)(hi+i)   = a; *(__half2*)(hi+i+2) = b;
    *(__half2*)(lo+i)   = c; *(__half2*)(lo+i+2) = d;
}

// hi-only conversion (for lm_head weights; lo half unused at PRODS=1)
__global__ void conv_f32_hi(const float* __restrict__ in, fp16* __restrict__ hi, ll n)
{
    ll i = ((ll)blockIdx.x*blockDim.x + threadIdx.x)*4;
    if (i >= n) return;
    float4 v = *(const float4*)(in + i);
    __half2 a; a.x=__float2half_rn(v.x); a.y=__float2half_rn(v.y);
    __half2 b; b.x=__float2half_rn(v.z); b.y=__float2half_rn(v.w);
    *(__half2*)(hi+i)   = a; *(__half2*)(hi+i+2) = b;
}

// ---------------- host ---------------------------------------------------------
extern "C" void kernel_launch(void* const* d_in, const int* in_sizes, int n_in,
                              void* d_out, int out_size)
{
    const int*   idx  = (const int*)  d_in[0];
    const float* wte  = (const float*)d_in[1];
    const float* lmh  = (const float*)d_in[2];
    const float* qkvw = (const float*)d_in[3];
    const float* cpjw = (const float*)d_in[4];
    const float* denc = (const float*)d_in[5];
    const float* ddec = (const float*)d_in[6];
    const float* thr  = (const float*)d_in[7];
    const float* lamr = (const float*)d_in[8];
    const float* lamx = (const float*)d_in[9];
    float* out = (float*)d_out;

    constexpr int DSZ1 = Cfg<1>::DSZ;   // 61440
    constexpr int DSZ2 = Cfg<2>::DSZ;   // 92160
    constexpr int DSZ3 = Cfg<3>::DSZ;   // 81920
    cudaFuncSetAttribute(gemm_mm<3,0,false,false>, cudaFuncAttributeMaxDynamicSharedMemorySize, DSZ3);
    cudaFuncSetAttribute(gemm_mm<3,1,false,false>, cudaFuncAttributeMaxDynamicSharedMemorySize, DSZ3);
    cudaFuncSetAttribute(gemm_mm<2,0,true ,false>, cudaFuncAttributeMaxDynamicSharedMemorySize, DSZ2);
    cudaFuncSetAttribute(gemm_mm<2,1,false,false>, cudaFuncAttributeMaxDynamicSharedMemorySize, DSZ2);
    cudaFuncSetAttribute(gemm_mm<2,2,false,false>, cudaFuncAttributeMaxDynamicSharedMemorySize, DSZ2);
    cudaFuncSetAttribute(gemm_mm<2,3,false,true >, cudaFuncAttributeMaxDynamicSharedMemorySize, DSZ2);
    cudaFuncSetAttribute(gemm_mm<1,0,false,false>, cudaFuncAttributeMaxDynamicSharedMemorySize, DSZ1);

    float *x, *x0, *wf, *dots;
    cudaGetSymbolAddress((void**)&x,    g_x);
    cudaGetSymbolAddress((void**)&x0,   g_x0);
    cudaGetSymbolAddress((void**)&wf,   g_w);
    cudaGetSymbolAddress((void**)&dots, g_dots);
    fp16 *hh,*hl,*wh,*wl,*wth,*wtl,*ph,*pl,*oh,*ol,*ah,*al;
    cudaGetSymbolAddress((void**)&hh,  g_hh);  cudaGetSymbolAddress((void**)&hl,  g_hl);
    cudaGetSymbolAddress((void**)&wh,  g_wh);  cudaGetSymbolAddress((void**)&wl,  g_wl);
    cudaGetSymbolAddress((void**)&wth, g_wth); cudaGetSymbolAddress((void**)&wtl, g_wtl);
    cudaGetSymbolAddress((void**)&ph,  g_ph);  cudaGetSymbolAddress((void**)&pl,  g_pl);
    cudaGetSymbolAddress((void**)&oh,  g_oh);  cudaGetSymbolAddress((void**)&ol,  g_ol);
    cudaGetSymbolAddress((void**)&ah,  g_ah);  cudaGetSymbolAddress((void**)&al,  g_al);
    fp16 *qh,*ql,*ch,*cl,*eh,*el,*dh,*dl,*lh;
    cudaGetSymbolAddress((void**)&qh, g_qkvh); cudaGetSymbolAddress((void**)&ql, g_qkvl);
    cudaGetSymbolAddress((void**)&ch, g_cpjh); cudaGetSymbolAddress((void**)&cl, g_cpjl);
    cudaGetSymbolAddress((void**)&eh, g_dech); cudaGetSymbolAddress((void**)&el, g_decl);
    cudaGetSymbolAddress((void**)&dh, g_ddh);  cudaGetSymbolAddress((void**)&dl, g_ddl);
    cudaGetSymbolAddress((void**)&lh, g_lmhh);

    {
        ll n;
        n = (ll)Ll*Ee*Ee;    split_f32<<<(int)((n/4+255)/256),256>>>(qkvw, qh, ql, n);
        n = (ll)Ll*Ee*Ee;    split_f32<<<(int)((n/4+255)/256),256>>>(cpjw, ch, cl, n);
        n = (ll)Ll*HIDh*Ee;  split_f32<<<(int)((n/4+255)/256),256>>>(denc, eh, el, n);
        n = (ll)Ll*Ee*HIDh;  split_f32<<<(int)((n/4+255)/256),256>>>(ddec, dh, dl, n);
        n = (ll)Vv*Ee;       conv_f32_hi<<<(int)((n/4+255)/256),256>>>(lmh, lh, n);
    }

    const float scale = 0.08838834764831845f;
    const ll TE = (ll)Tt*Ee;
    const ll TT = (ll)Tt*Tt;
    const ll WT = (ll)HDd*Tt;

    embed_norm_kernel<<<NTOK,256>>>(idx, wte, x, x0);

    for (int i=0;i<Ll;i++){
        mix_norm_split<<<NTOK,256>>>(x, x0, hh, hl, lamr, lamx, i);

        // w = h @ qkv^T (fp32 out for rope), 3-product
        gemm_mm<3,0,false,false><<<dim3(6,32,1),256,DSZ3>>>(
            hh, hl, qh + (ll)i*Ee*Ee, ql + (ll)i*Ee*Ee,
            wf, nullptr, nullptr, nullptr,
            Ee, Ee, Ee, Ee, 1, 0,0, 0,0, 0,0);

        rope_split_kernel<<<NTOK*Hh,128>>>(wf, wh, wl);
        transpose_hd<<<dim3(Tt/32, HDd/32, Bb*Hh), dim3(32,8)>>>(wh, wl, wth, wtl);

        // dots = W W^T (lower-triangular tiles only), 2-product
        gemm_mm<2,0,true,false><<<dim3(36,1,Bb*Hh),256,DSZ2>>>(
            wh, wl, wh, wl,
            dots, nullptr, nullptr, nullptr,
            HDd, Ee, Ee, Tt, Hh, TE,(ll)HDd, TE,(ll)HDd, (ll)Hh*TT, TT);

        softmax_split_kernel<<<Bb*Hh*Tt,256>>>(dots, ph, pl, scale);

        // o = P @ W (K limited to bm+128), split output, 2-product
        gemm_mm<2,3,false,true><<<dim3(1,8,Bb*Hh),256,DSZ2>>>(
            ph, pl, wth, wtl,
            nullptr, oh, ol, nullptr,
            Tt, Tt, Tt, Ee, Hh, (ll)Hh*TT,TT, (ll)Hh*WT,WT, TE,(ll)HDd);

        // x += o @ cproj^T, 3-product
        gemm_mm<3,1,false,false><<<dim3(6,32,1),256,DSZ3>>>(
            oh, ol, ch + (ll)i*Ee*Ee, cl + (ll)i*Ee*Ee,
            x, nullptr, nullptr, nullptr,
            Ee, Ee, Ee, Ee, 1, 0,0, 0,0, 0,0);

        mix_norm_split<<<NTOK,256>>>(x, x0, hh, hl, nullptr, nullptr, 0);

        // a = relu(h @ denc^T - thr), split output, 2-product
        gemm_mm<2,2,false,false><<<dim3(24,32,1),256,DSZ2>>>(
            hh, hl, eh + (ll)i*HIDh*Ee, el + (ll)i*HIDh*Ee,
            nullptr, ah, al, thr + (ll)i*HIDh,
            Ee, Ee, Ee, HIDh, 1, 0,0, 0,0, 0,0);

        // x += a @ ddec^T, 2-product
        gemm_mm<2,1,false,false><<<dim3(6,32,1),256,DSZ2>>>(
            ah, al, dh + (ll)i*Ee*HIDh, dl + (ll)i*Ee*HIDh,
            x, nullptr, nullptr, nullptr,
            HIDh, HIDh, HIDh, Ee, 1, 0,0, 0,0, 0,0);
    }

    mix_norm_split<<<NTOK,256>>>(x, x0, hh, hl, nullptr, nullptr, 0);
    // lm_head: 1-product pure fp16 (terminal op; error does not propagate)
    gemm_mm<1,0,false,false><<<dim3(393,32,1),256,DSZ1>>>(
        hh, hl, lh, lh, out, nullptr, nullptr, nullptr,
        Ee, Ee, Ee, Vv, 1, 0,0, 0,0, 0,0);
}

// round 14
// speedup vs baseline: 4.1988x; 1.0812x over previous
#include <cuda_runtime.h>
#include <cuda_fp16.h>
#include <math.h>
#include <stdint.h>

#define Bb 4
#define Tt 1024
#define Vv 50304
#define Ee 768
#define Ll 12
#define Hh 6
#define HDd 128
#define HIDh 3072
#define NTOK (Bb*Tt)
#define EPS 1e-6f
typedef long long ll;
typedef __half fp16;

// ---------------- scratch ----------------------------------------------------
__device__ float g_x [NTOK*Ee];
__device__ float g_x0[NTOK*Ee];
__device__ float g_w [NTOK*Ee];
__device__ float g_dots[(ll)Bb*Hh*Tt*Tt];

__device__ fp16 g_hh[NTOK*Ee];
__device__ fp16 g_wh[NTOK*Ee],  g_wl[NTOK*Ee];
__device__ fp16 g_wth[Bb*Hh*HDd*Tt], g_wtl[Bb*Hh*HDd*Tt];
__device__ fp16 g_ph[(ll)Bb*Hh*Tt*Tt];
__device__ fp16 g_oh[NTOK*Ee];
__device__ fp16 g_ah[NTOK*HIDh];

__device__ fp16 g_qkvh[Ll*Ee*Ee],   g_qkvl[Ll*Ee*Ee];
__device__ fp16 g_cpjh[Ll*Ee*Ee],   g_cpjl[Ll*Ee*Ee];
__device__ fp16 g_dech[Ll*HIDh*Ee], g_decl[Ll*HIDh*Ee];
__device__ fp16 g_ddh[Ll*Ee*HIDh],  g_ddl[Ll*Ee*HIDh];
__device__ fp16 g_lmhh[(ll)Vv*Ee];

// ---------------- helpers -----------------------------------------------------
__device__ __forceinline__ uint32_t smem_u32(const void* p){
    uint32_t a;
    asm("{ .reg .u64 t; cvta.to.shared.u64 t, %1; cvt.u32.u64 %0, t; }" : "=r"(a) : "l"(p));
    return a;
}
__device__ __forceinline__ void cp16(uint32_t dst, const void* src){
    asm volatile("cp.async.cg.shared.global [%0], [%1], 16;" :: "r"(dst), "l"(src));
}
#define CP_COMMIT() asm volatile("cp.async.commit_group;" ::: "memory")
template<int N>
__device__ __forceinline__ void cp_wait(){
    asm volatile("cp.async.wait_group %0;" :: "n"(N) : "memory");
}

__device__ __forceinline__ void ldm4(uint32_t a, uint32_t& r0, uint32_t& r1, uint32_t& r2, uint32_t& r3){
    asm volatile("ldmatrix.sync.aligned.m8n8.x4.shared.b16 {%0,%1,%2,%3}, [%4];"
        : "=r"(r0), "=r"(r1), "=r"(r2), "=r"(r3) : "r"(a));
}
__device__ __forceinline__ void mma16816(float* c, const uint32_t* a, const uint32_t* b){
    asm volatile("mma.sync.aligned.m16n8k16.row.col.f32.f16.f16.f32 "
        "{%0,%1,%2,%3}, {%4,%5,%6,%7}, {%8,%9}, {%0,%1,%2,%3};"
        : "+f"(c[0]), "+f"(c[1]), "+f"(c[2]), "+f"(c[3])
        : "r"(a[0]), "r"(a[1]), "r"(a[2]), "r"(a[3]), "r"(b[0]), "r"(b[1]));
}
__device__ __forceinline__ void split2(float v, fp16& h, fp16& l){
    h = __float2half_rn(v);
    l = __float2half_rn(v - __half2float(h));
}

// ---------------- reductions -------------------------------------------------
__device__ __forceinline__ float warpSum(float v){
    #pragma unroll
    for (int o=16;o;o>>=1) v += __shfl_xor_sync(0xffffffffu, v, o);
    return v;
}
__device__ __forceinline__ float warpMax(float v){
    #pragma unroll
    for (int o=16;o;o>>=1) v = fmaxf(v, __shfl_xor_sync(0xffffffffu, v, o));
    return v;
}
__device__ __forceinline__ float blockSum(float v){
    __shared__ float sh[33];
    __syncthreads();
    int lane = threadIdx.x & 31, wid = threadIdx.x >> 5;
    v = warpSum(v);
    if (lane == 0) sh[wid] = v;
    __syncthreads();
    int nw = (blockDim.x + 31) >> 5;
    float r = (threadIdx.x < nw) ? sh[threadIdx.x] : 0.0f;
    if (wid == 0) r = warpSum(r);
    if (threadIdx.x == 0) sh[32] = r;
    __syncthreads();
    return sh[32];
}
__device__ __forceinline__ float blockMax(float v){
    __shared__ float sh[33];
    __syncthreads();
    int lane = threadIdx.x & 31, wid = threadIdx.x >> 5;
    v = warpMax(v);
    if (lane == 0) sh[wid] = v;
    __syncthreads();
    int nw = (blockDim.x + 31) >> 5;
    float r = (threadIdx.x < nw) ? sh[threadIdx.x] : -INFINITY;
    if (wid == 0) r = warpMax(r);
    if (threadIdx.x == 0) sh[32] = r;
    __syncthreads();
    return sh[32];
}

// ---------------- HMMA GEMM ----------------------------------------------------
// C[M,N] = A[M,K] @ B[N,K]^T with hi/lo fp16 split.
// PRODS=2: AhBh+AhBl (A-lo never used). PRODS=1: AhBh only.
// Block 128x128, 8 warps of 64x32, mma.m16n8k16, KC=32.
// Stage tiles: [Ah][Bh]([Bl]).  PRODS=1: 2x3 stages (61KB). PRODS=2: 3x3 (92KB).
// Both fit 2 CTAs/SM.
// EPI: 0 store f32, 1 accumulate f32, 2 relu(acc-bias[n]) hi store, 3 hi store
static constexpr int PITCH  = 40;
static constexpr int TILEB2 = 128*PITCH*2;    // 10240 B

template<int PRODS> struct Cfg {
    static constexpr int NT   = (PRODS==2) ? 3 : 2;
    static constexpr int NSTG = 3;
    static constexpr int STG  = NT*TILEB2;
    static constexpr int DSZ  = NSTG*STG;
    static constexpr int PRE  = NSTG-1;
};

__device__ __forceinline__ void load_tile(uint32_t dst, const fp16* src, int r0, int k0, int ld, int tid){
    #pragma unroll
    for (int j=0;j<2;j++){
        int slot = tid + j*256;
        int row = slot >> 2;
        int seg = slot & 3;
        cp16(dst + row*80 + seg*16, src + (ll)(r0+row)*ld + k0 + seg*8);
    }
}
template<int PRODS>
__device__ __forceinline__ void load_chunk(uint32_t sbase,
    const fp16* Ah, const fp16* Bh, const fp16* Bl,
    int bm, int bn, int k0, int lda, int ldb, int tid)
{
    load_tile(sbase,            Ah, bm, k0, lda, tid);
    load_tile(sbase +   TILEB2, Bh, bn, k0, ldb, tid);
    if (PRODS >= 2) load_tile(sbase + 2*TILEB2, Bl, bn, k0, ldb, tid);
}

template<int PRODS, int EPI, bool TRI, bool KLIM>
__global__ void __launch_bounds__(256,2) gemm_mm(
    const fp16* __restrict__ Ahi,
    const fp16* __restrict__ Bhi, const fp16* __restrict__ Blo,
    float* __restrict__ C, fp16* __restrict__ Chi,
    const float* __restrict__ bias,
    int K, int lda, int ldb, int ldc, int zdiv,
    ll sA1, ll sA2, ll sB1, ll sB2, ll sC1, ll sC2)
{
    constexpr int NSTG = Cfg<PRODS>::NSTG;
    constexpr int STG  = Cfg<PRODS>::STG;
    constexpr int PRE  = Cfg<PRODS>::PRE;

    extern __shared__ char dsm[];
    uint32_t sb = smem_u32(dsm);

    int z  = blockIdx.z;
    int zq = z / zdiv, zr = z % zdiv;
    Ahi += zq*sA1 + zr*sA2;
    Bhi += zq*sB1 + zr*sB2; Blo += zq*sB1 + zr*sB2;
    if (EPI==0 || EPI==1) { C += zq*sC1 + zr*sC2; }
    else { Chi += zq*sC1 + zr*sC2; }

    int bm, bn;
    if (TRI) {
        int idx = blockIdx.x;
        int i_ = (int)((sqrtf(8.f*(float)idx + 1.f) - 1.f) * 0.5f);
        while ((i_+1)*(i_+2)/2 <= idx) i_++;
        while (i_*(i_+1)/2 > idx) i_--;
        bm = i_*128; bn = (idx - i_*(i_+1)/2)*128;
    } else { bm = blockIdx.y*128; bn = blockIdx.x*128; }

    int kmax = KLIM ? min(K, bm + 128) : K;
    int nch  = kmax >> 5;
    const int tid  = threadIdx.x;
    const int lane = tid & 31;
    const int wid  = tid >> 5;
    const int wm   = wid >> 2;
    const int wn   = wid & 3;

    float acc[4][4][4];
    #pragma unroll
    for (int i=0;i<4;i++)
        #pragma unroll
        for (int j=0;j<4;j++)
            #pragma unroll
            for (int q=0;q<4;q++) acc[i][j][q]=0.f;

    int pre = nch < PRE ? nch : PRE;
    for (int j=0;j<pre;j++){
        load_chunk<PRODS>(sb + (j%NSTG)*STG, Ahi,Bhi,Blo, bm,bn, j*32, lda,ldb, tid);
        CP_COMMIT();
    }
    for (int j=pre;j<PRE;j++) CP_COMMIT();

    const int a_row  = (lane & 15);
    const int a_colb = ((lane >> 4) << 3) * 2;
    const int b_rowo = ((lane >> 4) << 3) + (lane & 7);
    const int b_colb = (((lane >> 3) & 1) << 3) * 2;

    for (int i=0;i<nch;i++){
        cp_wait<PRE-1>();
        __syncthreads();
        if (i + PRE < nch) {
            load_chunk<PRODS>(sb + ((i+PRE)%NSTG)*STG, Ahi,Bhi,Blo, bm,bn, (i+PRE)*32, lda,ldb, tid);
            CP_COMMIT();
        } else {
            CP_COMMIT();
        }

        uint32_t st = sb + (i%NSTG)*STG;
        uint32_t Abh = st, Bbh = st + TILEB2, Bbl = st + 2*TILEB2;
        #pragma unroll
        for (int kk=0; kk<2; kk++){
            const int kb = kk*16*2;
            uint32_t bh[4][2], blr[4][2];
            #pragma unroll
            for (int np=0; np<2; np++){
                uint32_t off = (uint32_t)(wn*32 + np*16 + b_rowo)*80 + kb + b_colb;
                uint32_t r0,r1,r2,r3;
                ldm4(Bbh + off, r0,r1,r2,r3);
                bh[2*np][0]=r0; bh[2*np][1]=r1; bh[2*np+1][0]=r2; bh[2*np+1][1]=r3;
                if (PRODS >= 2) {
                    ldm4(Bbl + off, r0,r1,r2,r3);
                    blr[2*np][0]=r0; blr[2*np][1]=r1; blr[2*np+1][0]=r2; blr[2*np+1][1]=r3;
                }
            }
            #pragma unroll
            for (int mt=0; mt<4; mt++){
                uint32_t off = (uint32_t)(wm*64 + mt*16 + a_row)*80 + kb + a_colb;
                uint32_t ah[4];
                ldm4(Abh + off, ah[0], ah[1], ah[2], ah[3]);
                if (PRODS == 2) {
                    #pragma unroll
                    for (int nt=0; nt<4; nt++){
                        mma16816(acc[mt][nt], ah, bh[nt]);
                        mma16816(acc[mt][nt], ah, blr[nt]);
                    }
                } else {
                    #pragma unroll
                    for (int nt=0; nt<4; nt++){
                        mma16816(acc[mt][nt], ah, bh[nt]);
                    }
                }
            }
        }
        __syncthreads();
    }

    #pragma unroll
    for (int mt=0; mt<4; mt++){
        #pragma unroll
        for (int nt=0; nt<4; nt++){
            int m0 = bm + wm*64 + mt*16 + (lane >> 2);
            int n0 = bn + wn*32 + nt*8  + (lane & 3)*2;
            float c0 = acc[mt][nt][0], c1 = acc[mt][nt][1];
            float c2 = acc[mt][nt][2], c3 = acc[mt][nt][3];
            if (EPI == 0) {
                *(float2*)(C + (ll)m0*ldc + n0)     = make_float2(c0, c1);
                *(float2*)(C + (ll)(m0+8)*ldc + n0) = make_float2(c2, c3);
            } else if (EPI == 1) {
                float2 o0 = *(const float2*)(C + (ll)m0*ldc + n0);
                float2 o1 = *(const float2*)(C + (ll)(m0+8)*ldc + n0);
                *(float2*)(C + (ll)m0*ldc + n0)     = make_float2(o0.x+c0, o0.y+c1);
                *(float2*)(C + (ll)(m0+8)*ldc + n0) = make_float2(o1.x+c2, o1.y+c3);
            } else {
                if (EPI == 2) {
                    float b0 = __ldg(bias + n0), b1 = __ldg(bias + n0 + 1);
                    c0 = fmaxf(c0-b0, 0.f); c1 = fmaxf(c1-b1, 0.f);
                    c2 = fmaxf(c2-b0, 0.f); c3 = fmaxf(c3-b1, 0.f);
                }
                __half2 hv;
                hv.x = __float2half_rn(c0); hv.y = __float2half_rn(c1);
                *(__half2*)(Chi + (ll)m0*ldc + n0) = hv;
                hv.x = __float2half_rn(c2); hv.y = __float2half_rn(c3);
                *(__half2*)(Chi + (ll)(m0+8)*ldc + n0) = hv;
            }
        }
    }
}

// ---------------- elementwise kernels ----------------------------------------
__global__ void embed_norm_kernel(const int* __restrict__ idx,
                                  const float* __restrict__ wte,
                                  float* __restrict__ x, float* __restrict__ x0)
{
    int t = blockIdx.x;
    int tok = idx[t];
    const float* row = wte + (ll)tok * Ee;
    ll base = (ll)t * Ee;
    float v[3]; float ss = 0.f;
    #pragma unroll
    for (int j=0;j<3;j++){ int c = threadIdx.x + j*256; float m = row[c]; v[j]=m; ss += m*m; }
    ss = blockSum(ss);
    float inv = rsqrtf(ss*(1.0f/Ee) + EPS);
    #pragma unroll
    for (int j=0;j<3;j++){ int c = threadIdx.x + j*256; float o = v[j]*inv; x[base+c]=o; x0[base+c]=o; }
}

// x = rl*x + xl*x0; hh = fp16(rmsnorm(x)) (hi only — no GEMM consumes A-lo)
__global__ void mix_norm_split(float* __restrict__ x, const float* __restrict__ x0,
                               fp16* __restrict__ hh,
                               const float* lamr, const float* lamx, int li)
{
    int t = blockIdx.x;
    float rl = lamr ? lamr[li] : 1.0f;
    float xl = lamx ? lamx[li] : 0.0f;
    ll base = (ll)t * Ee;
    float v[3]; float ss = 0.f;
    #pragma unroll
    for (int j=0;j<3;j++){
        int c = threadIdx.x + j*256;
        float m = rl*x[base+c] + xl*x0[base+c];
        v[j]=m; ss += m*m;
    }
    ss = blockSum(ss);
    float inv = rsqrtf(ss*(1.0f/Ee) + EPS);
    #pragma unroll
    for (int j=0;j<3;j++){
        int c = threadIdx.x + j*256;
        x[base+c] = v[j];
        hh[base+c] = __float2half_rn(v[j]*inv);
    }
}

__global__ void rope_split_kernel(const float* __restrict__ wf,
                                  fp16* __restrict__ wh, fp16* __restrict__ wl)
{
    int n  = blockIdx.x / Hh;
    int hh = blockIdx.x % Hh;
    int t  = n & (Tt-1);
    const float* base = wf + (ll)n*Ee + hh*HDd;
    int d = threadIdx.x;
    __shared__ float s[HDd];
    float v = base[d];
    s[d] = v;
    float ss = blockSum(v*v);
    float inv = rsqrtf(ss*(1.0f/HDd) + EPS);
    float out;
    if (d < 64) {
        int j = d;
        float x1 = s[j], x2 = s[j+64];
        float fr = (float)t * powf(10000.0f, -((float)(2*j)) * (1.0f/128.0f));
        out = (x1*cosf(fr) + x2*sinf(fr)) * inv;
    } else {
        int j = d - 64;
        float x1 = s[j], x2 = s[d];
        float fr = (float)t * powf(10000.0f, -((float)(2*j)) * (1.0f/128.0f));
        out = (-x1*sinf(fr) + x2*cosf(fr)) * inv;
    }
    fp16 h, l; split2(out, h, l);
    ll o = (ll)n*Ee + hh*HDd + d;
    wh[o] = h; wl[o] = l;
}

__global__ void transpose_hd(const fp16* __restrict__ whi, const fp16* __restrict__ wlo,
                             fp16* __restrict__ othi, fp16* __restrict__ otlo)
{
    __shared__ fp16 tile[32][33];
    int z = blockIdx.z; int b = z / Hh, h = z % Hh;
    int t0 = blockIdx.x*32, d0 = blockIdx.y*32;
    #pragma unroll
    for (int pass=0; pass<2; pass++){
        const fp16* src = pass ? wlo : whi;
        fp16* dst = pass ? otlo : othi;
        for (int j=(int)threadIdx.y; j<32; j+=8)
            tile[j][threadIdx.x] = src[(ll)(b*Tt + t0 + j)*Ee + h*HDd + d0 + threadIdx.x];
        __syncthreads();
        for (int j=(int)threadIdx.y; j<32; j+=8)
            dst[(ll)z*HDd*Tt + (ll)(d0 + j)*Tt + t0 + threadIdx.x] = tile[threadIdx.x][j];
        __syncthreads();
    }
}

// causal softmax; hi-only P (PV is 2-product on B side; A-lo unused),
// written only up to the 128-aligned boundary.
__global__ void softmax_split_kernel(const float* __restrict__ dots,
                                     fp16* __restrict__ ph, float scale)
{
    ll r = blockIdx.x;
    int q = (int)(r & (Tt-1));
    const float* row = dots + r * Tt;
    fp16* hrow = ph + r * Tt;
    int nv = q + 1;
    int kmax = ((q >> 7) + 1) << 7;
    float vals[4];
    float m = -INFINITY;
    #pragma unroll
    for (int it=0; it<4; it++){
        int k = threadIdx.x + it*256;
        float v = (k < nv) ? row[k]*scale : -INFINITY;
        vals[it] = v;
        m = fmaxf(m, v);
    }
    m = blockMax(m);
    float sum = 0.f;
    #pragma unroll
    for (int it=0; it<4; it++){
        int k = threadIdx.x + it*256;
        float e = (k < nv) ? expf(vals[it]-m) : 0.0f;
        vals[it] = e; sum += e;
    }
    sum = blockSum(sum);
    float invs = 1.0f / sum;
    #pragma unroll
    for (int it=0; it<4; it++){
        int k = threadIdx.x + it*256;
        if (k < kmax) hrow[k] = __float2half_rn(vals[it]*invs);
    }
}

__global__ void split_f32(const float* __restrict__ in, fp16* __restrict__ hi,
                          fp16* __restrict__ lo, ll n)
{
    ll i = ((ll)blockIdx.x*blockDim.x + threadIdx.x)*4;
    if (i >= n) return;
    float4 v = *(const float4*)(in + i);
    fp16 h0,l0,h1,l1,h2,l2,h3,l3;
    split2(v.x,h0,l0); split2(v.y,h1,l1); split2(v.z,h2,l2); split2(v.w,h3,l3);
    __half2 a; a.x=h0; a.y=h1; __half2 b; b.x=h2; b.y=h3;
    __half2 c; c.x=l0; c.y=l1; __half2 d; d.x=l2; d.y=l3;
    *(__half2*)(hi+i)   = a; *(__half2*)(hi+i+2) = b;
    *(__half2*)(lo+i)   = c; *(__half2*)(lo+i+2) = d;
}

// hi-only conversion (lm_head weights)
__global__ void conv_f32_hi(const float* __restrict__ in, fp16* __restrict__ hi, ll n)
{
    ll i = ((ll)blockIdx.x*blockDim.x + threadIdx.x)*4;
    if (i >= n) return;
    float4 v = *(const float4*)(in + i);
    __half2 a; a.x=__float2half_rn(v.x); a.y=__float2half_rn(v.y);
    __half2 b; b.x=__float2half_rn(v.z); b.y=__float2half_rn(v.w);
    *(__half2*)(hi+i)   = a; *(__half2*)(hi+i+2) = b;
}

// ---------------- host ---------------------------------------------------------
extern "C" void kernel_launch(void* const* d_in, const int* in_sizes, int n_in,
                              void* d_out, int out_size)
{
    const int*   idx  = (const int*)  d_in[0];
    const float* wte  = (const float*)d_in[1];
    const float* lmh  = (const float*)d_in[2];
    const float* qkvw = (const float*)d_in[3];
    const float* cpjw = (const float*)d_in[4];
    const float* denc = (const float*)d_in[5];
    const float* ddec = (const float*)d_in[6];
    const float* thr  = (const float*)d_in[7];
    const float* lamr = (const float*)d_in[8];
    const float* lamx = (const float*)d_in[9];
    float* out = (float*)d_out;

    constexpr int DSZ1 = Cfg<1>::DSZ;   // 61440
    constexpr int DSZ2 = Cfg<2>::DSZ;   // 92160
    cudaFuncSetAttribute(gemm_mm<2,0,false,false>, cudaFuncAttributeMaxDynamicSharedMemorySize, DSZ2);
    cudaFuncSetAttribute(gemm_mm<2,0,true ,false>, cudaFuncAttributeMaxDynamicSharedMemorySize, DSZ2);
    cudaFuncSetAttribute(gemm_mm<2,1,false,false>, cudaFuncAttributeMaxDynamicSharedMemorySize, DSZ2);
    cudaFuncSetAttribute(gemm_mm<2,2,false,false>, cudaFuncAttributeMaxDynamicSharedMemorySize, DSZ2);
    cudaFuncSetAttribute(gemm_mm<2,3,false,true >, cudaFuncAttributeMaxDynamicSharedMemorySize, DSZ2);
    cudaFuncSetAttribute(gemm_mm<1,0,false,false>, cudaFuncAttributeMaxDynamicSharedMemorySize, DSZ1);

    float *x, *x0, *wf, *dots;
    cudaGetSymbolAddress((void**)&x,    g_x);
    cudaGetSymbolAddress((void**)&x0,   g_x0);
    cudaGetSymbolAddress((void**)&wf,   g_w);
    cudaGetSymbolAddress((void**)&dots, g_dots);
    fp16 *hh,*wh,*wl,*wth,*wtl,*ph,*oh,*ah;
    cudaGetSymbolAddress((void**)&hh,  g_hh);
    cudaGetSymbolAddress((void**)&wh,  g_wh);  cudaGetSymbolAddress((void**)&wl,  g_wl);
    cudaGetSymbolAddress((void**)&wth, g_wth); cudaGetSymbolAddress((void**)&wtl, g_wtl);
    cudaGetSymbolAddress((void**)&ph,  g_ph);
    cudaGetSymbolAddress((void**)&oh,  g_oh);
    cudaGetSymbolAddress((void**)&ah,  g_ah);
    fp16 *qh,*ql,*ch,*cl,*eh,*el,*dh,*dl,*lh;
    cudaGetSymbolAddress((void**)&qh, g_qkvh); cudaGetSymbolAddress((void**)&ql, g_qkvl);
    cudaGetSymbolAddress((void**)&ch, g_cpjh); cudaGetSymbolAddress((void**)&cl, g_cpjl);
    cudaGetSymbolAddress((void**)&eh, g_dech); cudaGetSymbolAddress((void**)&el, g_decl);
    cudaGetSymbolAddress((void**)&dh, g_ddh);  cudaGetSymbolAddress((void**)&dl, g_ddl);
    cudaGetSymbolAddress((void**)&lh, g_lmhh);

    {
        ll n;
        n = (ll)Ll*Ee*Ee;    split_f32<<<(int)((n/4+255)/256),256>>>(qkvw, qh, ql, n);
        n = (ll)Ll*Ee*Ee;    split_f32<<<(int)((n/4+255)/256),256>>>(cpjw, ch, cl, n);
        n = (ll)Ll*HIDh*Ee;  split_f32<<<(int)((n/4+255)/256),256>>>(denc, eh, el, n);
        n = (ll)Ll*Ee*HIDh;  split_f32<<<(int)((n/4+255)/256),256>>>(ddec, dh, dl, n);
        n = (ll)Vv*Ee;       conv_f32_hi<<<(int)((n/4+255)/256),256>>>(lmh, lh, n);
    }

    const float scale = 0.08838834764831845f;
    const ll TE = (ll)Tt*Ee;
    const ll TT = (ll)Tt*Tt;
    const ll WT = (ll)HDd*Tt;

    embed_norm_kernel<<<NTOK,256>>>(idx, wte, x, x0);

    for (int i=0;i<Ll;i++){
        mix_norm_split<<<NTOK,256>>>(x, x0, hh, lamr, lamx, i);

        // w = h @ qkv^T (fp32 out for rope), 2-product
        gemm_mm<2,0,false,false><<<dim3(6,32,1),256,DSZ2>>>(
            hh, qh + (ll)i*Ee*Ee, ql + (ll)i*Ee*Ee,
            wf, nullptr, nullptr,
            Ee, Ee, Ee, Ee, 1, 0,0, 0,0, 0,0);

        rope_split_kernel<<<NTOK*Hh,128>>>(wf, wh, wl);
        transpose_hd<<<dim3(Tt/32, HDd/32, Bb*Hh), dim3(32,8)>>>(wh, wl, wth, wtl);

        // dots = W W^T (lower-triangular tiles only), 2-product (B-lo = wl)
        gemm_mm<2,0,true,false><<<dim3(36,1,Bb*Hh),256,DSZ2>>>(
            wh, wh, wl,
            dots, nullptr, nullptr,
            HDd, Ee, Ee, Tt, Hh, TE,(ll)HDd, TE,(ll)HDd, (ll)Hh*TT, TT);

        softmax_split_kernel<<<Bb*Hh*Tt,256>>>(dots, ph, scale);

        // o = P @ W (K limited to bm+128), hi store, 2-product (B-lo = wtl)
        gemm_mm<2,3,false,true><<<dim3(1,8,Bb*Hh),256,DSZ2>>>(
            ph, wth, wtl,
            nullptr, oh, nullptr,
            Tt, Tt, Tt, Ee, Hh, (ll)Hh*TT,TT, (ll)Hh*WT,WT, TE,(ll)HDd);

        // x += o @ cproj^T, 2-product
        gemm_mm<2,1,false,false><<<dim3(6,32,1),256,DSZ2>>>(
            oh, ch + (ll)i*Ee*Ee, cl + (ll)i*Ee*Ee,
            x, nullptr, nullptr,
            Ee, Ee, Ee, Ee, 1, 0,0, 0,0, 0,0);

        mix_norm_split<<<NTOK,256>>>(x, x0, hh, nullptr, nullptr, 0);

        // a = relu(h @ denc^T - thr), hi store, 2-product
        gemm_mm<2,2,false,false><<<dim3(24,32,1),256,DSZ2>>>(
            hh, eh + (ll)i*HIDh*Ee, el + (ll)i*HIDh*Ee,
            nullptr, ah, thr + (ll)i*HIDh,
            Ee, Ee, Ee, HIDh, 1, 0,0, 0,0, 0,0);

        // x += a @ ddec^T, 2-product
        gemm_mm<2,1,false,false><<<dim3(6,32,1),256,DSZ2>>>(
            ah, dh + (ll)i*Ee*HIDh, dl + (ll)i*Ee*HIDh,
            x, nullptr, nullptr,
            HIDh, HIDh, HIDh, Ee, 1, 0,0, 0,0, 0,0);
    }

    mix_norm_split<<<NTOK,256>>>(x, x0, hh, nullptr, nullptr, 0);
    // lm_head: 1-product pure fp16 (terminal op)
    gemm_mm<1,0,false,false><<<dim3(393,32,1),256,DSZ1>>>(
        hh, lh, lh, out, nullptr, nullptr,
        Ee, Ee, Ee, Vv, 1, 0,0, 0,0, 0,0);
}

// round 17
// speedup vs baseline: 4.4081x; 1.0498x over previous
#include <cuda_runtime.h>
#include <cuda_fp16.h>
#include <math.h>
#include <stdint.h>

#define Bb 4
#define Tt 1024
#define Vv 50304
#define Ee 768
#define Ll 12
#define Hh 6
#define HDd 128
#define HIDh 3072
#define NTOK (Bb*Tt)
#define EPS 1e-6f
typedef long long ll;
typedef __half fp16;

// ---------------- scratch ----------------------------------------------------
__device__ float g_x [NTOK*Ee];
__device__ float g_x0[NTOK*Ee];
__device__ float g_w [NTOK*Ee];
__device__ float g_dots[(ll)Bb*Hh*Tt*Tt];
__device__ float g_cos[Tt*64], g_sin[Tt*64];

__device__ fp16 g_hh[NTOK*Ee];
__device__ fp16 g_wh[NTOK*Ee],  g_wl[NTOK*Ee];
__device__ fp16 g_wth[Bb*Hh*HDd*Tt];
__device__ fp16 g_ph[(ll)Bb*Hh*Tt*Tt];
__device__ fp16 g_oh[NTOK*Ee];
__device__ fp16 g_ah[NTOK*HIDh];

__device__ fp16 g_qkvh[Ll*Ee*Ee],   g_qkvl[Ll*Ee*Ee];
__device__ fp16 g_cpjh[Ll*Ee*Ee],   g_cpjl[Ll*Ee*Ee];
__device__ fp16 g_dech[Ll*HIDh*Ee], g_decl[Ll*HIDh*Ee];
__device__ fp16 g_ddh[Ll*Ee*HIDh],  g_ddl[Ll*Ee*HIDh];
__device__ fp16 g_lmhh[(ll)Vv*Ee];

// ---------------- helpers -----------------------------------------------------
__device__ __forceinline__ uint32_t smem_u32(const void* p){
    uint32_t a;
    asm("{ .reg .u64 t; cvta.to.shared.u64 t, %1; cvt.u32.u64 %0, t; }" : "=r"(a) : "l"(p));
    return a;
}
__device__ __forceinline__ void cp16(uint32_t dst, const void* src){
    asm volatile("cp.async.cg.shared.global [%0], [%1], 16;" :: "r"(dst), "l"(src));
}
#define CP_COMMIT() asm volatile("cp.async.commit_group;" ::: "memory")
template<int N>
__device__ __forceinline__ void cp_wait(){
    asm volatile("cp.async.wait_group %0;" :: "n"(N) : "memory");
}

__device__ __forceinline__ void ldm4(uint32_t a, uint32_t& r0, uint32_t& r1, uint32_t& r2, uint32_t& r3){
    asm volatile("ldmatrix.sync.aligned.m8n8.x4.shared.b16 {%0,%1,%2,%3}, [%4];"
        : "=r"(r0), "=r"(r1), "=r"(r2), "=r"(r3) : "r"(a));
}
__device__ __forceinline__ void mma16816(float* c, const uint32_t* a, const uint32_t* b){
    asm volatile("mma.sync.aligned.m16n8k16.row.col.f32.f16.f16.f32 "
        "{%0,%1,%2,%3}, {%4,%5,%6,%7}, {%8,%9}, {%0,%1,%2,%3};"
        : "+f"(c[0]), "+f"(c[1]), "+f"(c[2]), "+f"(c[3])
        : "r"(a[0]), "r"(a[1]), "r"(a[2]), "r"(a[3]), "r"(b[0]), "r"(b[1]));
}
__device__ __forceinline__ void split2(float v, fp16& h, fp16& l){
    h = __float2half_rn(v);
    l = __float2half_rn(v - __half2float(h));
}

// ---------------- reductions -------------------------------------------------
__device__ __forceinline__ float warpSum(float v){
    #pragma unroll
    for (int o=16;o;o>>=1) v += __shfl_xor_sync(0xffffffffu, v, o);
    return v;
}
__device__ __forceinline__ float warpMax(float v){
    #pragma unroll
    for (int o=16;o;o>>=1) v = fmaxf(v, __shfl_xor_sync(0xffffffffu, v, o));
    return v;
}
__device__ __forceinline__ float blockSum(float v){
    __shared__ float sh[33];
    __syncthreads();
    int lane = threadIdx.x & 31, wid = threadIdx.x >> 5;
    v = warpSum(v);
    if (lane == 0) sh[wid] = v;
    __syncthreads();
    int nw = (blockDim.x + 31) >> 5;
    float r = (threadIdx.x < nw) ? sh[threadIdx.x] : 0.0f;
    if (wid == 0) r = warpSum(r);
    if (threadIdx.x == 0) sh[32] = r;
    __syncthreads();
    return sh[32];
}
__device__ __forceinline__ float blockMax(float v){
    __shared__ float sh[33];
    __syncthreads();
    int lane = threadIdx.x & 31, wid = threadIdx.x >> 5;
    v = warpMax(v);
    if (lane == 0) sh[wid] = v;
    __syncthreads();
    int nw = (blockDim.x + 31) >> 5;
    float r = (threadIdx.x < nw) ? sh[threadIdx.x] : -INFINITY;
    if (wid == 0) r = warpMax(r);
    if (threadIdx.x == 0) sh[32] = r;
    __syncthreads();
    return sh[32];
}

// ---------------- HMMA GEMM ----------------------------------------------------
// C[M,N] = A[M,K] @ B[N,K]^T with hi/lo fp16 split (A always hi-only).
// PRODS=2: AhBh+AhBl. PRODS=1: AhBh only.
// Block 128x128, 8 warps of 64x32, mma.m16n8k16, KC=32, 3-stage cp.async.
// EPI: 0 store f32, 1 accumulate f32, 2 relu(acc-bias[n]) hi store, 3 hi store
static constexpr int PITCH  = 40;
static constexpr int TILEB2 = 128*PITCH*2;    // 10240 B

template<int PRODS> struct Cfg {
    static constexpr int NT   = (PRODS==2) ? 3 : 2;
    static constexpr int NSTG = 3;
    static constexpr int STG  = NT*TILEB2;
    static constexpr int DSZ  = NSTG*STG;
    static constexpr int PRE  = NSTG-1;
};

__device__ __forceinline__ void load_tile(uint32_t dst, const fp16* src, int r0, int k0, int ld, int tid){
    #pragma unroll
    for (int j=0;j<2;j++){
        int slot = tid + j*256;
        int row = slot >> 2;
        int seg = slot & 3;
        cp16(dst + row*80 + seg*16, src + (ll)(r0+row)*ld + k0 + seg*8);
    }
}
template<int PRODS>
__device__ __forceinline__ void load_chunk(uint32_t sbase,
    const fp16* Ah, const fp16* Bh, const fp16* Bl,
    int bm, int bn, int k0, int lda, int ldb, int tid)
{
    load_tile(sbase,            Ah, bm, k0, lda, tid);
    load_tile(sbase +   TILEB2, Bh, bn, k0, ldb, tid);
    if (PRODS >= 2) load_tile(sbase + 2*TILEB2, Bl, bn, k0, ldb, tid);
}

template<int PRODS, int EPI, bool TRI, bool KLIM>
__global__ void __launch_bounds__(256,2) gemm_mm(
    const fp16* __restrict__ Ahi,
    const fp16* __restrict__ Bhi, const fp16* __restrict__ Blo,
    float* __restrict__ C, fp16* __restrict__ Chi,
    const float* __restrict__ bias,
    int K, int lda, int ldb, int ldc, int zdiv,
    ll sA1, ll sA2, ll sB1, ll sB2, ll sC1, ll sC2)
{
    constexpr int NSTG = Cfg<PRODS>::NSTG;
    constexpr int STG  = Cfg<PRODS>::STG;
    constexpr int PRE  = Cfg<PRODS>::PRE;

    extern __shared__ char dsm[];
    uint32_t sb = smem_u32(dsm);

    int z  = blockIdx.z;
    int zq = z / zdiv, zr = z % zdiv;
    Ahi += zq*sA1 + zr*sA2;
    Bhi += zq*sB1 + zr*sB2; Blo += zq*sB1 + zr*sB2;
    if (EPI==0 || EPI==1) { C += zq*sC1 + zr*sC2; }
    else { Chi += zq*sC1 + zr*sC2; }

    int bm, bn;
    if (TRI) {
        int idx = blockIdx.x;
        int i_ = (int)((sqrtf(8.f*(float)idx + 1.f) - 1.f) * 0.5f);
        while ((i_+1)*(i_+2)/2 <= idx) i_++;
        while (i_*(i_+1)/2 > idx) i_--;
        bm = i_*128; bn = (idx - i_*(i_+1)/2)*128;
    } else { bm = blockIdx.y*128; bn = blockIdx.x*128; }

    int kmax = KLIM ? min(K, bm + 128) : K;
    int nch  = kmax >> 5;
    const int tid  = threadIdx.x;
    const int lane = tid & 31;
    const int wid  = tid >> 5;
    const int wm   = wid >> 2;
    const int wn   = wid & 3;

    float acc[4][4][4];
    #pragma unroll
    for (int i=0;i<4;i++)
        #pragma unroll
        for (int j=0;j<4;j++)
            #pragma unroll
            for (int q=0;q<4;q++) acc[i][j][q]=0.f;

    int pre = nch < PRE ? nch : PRE;
    for (int j=0;j<pre;j++){
        load_chunk<PRODS>(sb + (j%NSTG)*STG, Ahi,Bhi,Blo, bm,bn, j*32, lda,ldb, tid);
        CP_COMMIT();
    }
    for (int j=pre;j<PRE;j++) CP_COMMIT();

    const int a_row  = (lane & 15);
    const int a_colb = ((lane >> 4) << 3) * 2;
    const int b_rowo = ((lane >> 4) << 3) + (lane & 7);
    const int b_colb = (((lane >> 3) & 1) << 3) * 2;

    for (int i=0;i<nch;i++){
        cp_wait<PRE-1>();
        __syncthreads();
        if (i + PRE < nch) {
            load_chunk<PRODS>(sb + ((i+PRE)%NSTG)*STG, Ahi,Bhi,Blo, bm,bn, (i+PRE)*32, lda,ldb, tid);
            CP_COMMIT();
        } else {
            CP_COMMIT();
        }

        uint32_t st = sb + (i%NSTG)*STG;
        uint32_t Abh = st, Bbh = st + TILEB2, Bbl = st + 2*TILEB2;
        #pragma unroll
        for (int kk=0; kk<2; kk++){
            const int kb = kk*16*2;
            uint32_t bh[4][2], blr[4][2];
            #pragma unroll
            for (int np=0; np<2; np++){
                uint32_t off = (uint32_t)(wn*32 + np*16 + b_rowo)*80 + kb + b_colb;
                uint32_t r0,r1,r2,r3;
                ldm4(Bbh + off, r0,r1,r2,r3);
                bh[2*np][0]=r0; bh[2*np][1]=r1; bh[2*np+1][0]=r2; bh[2*np+1][1]=r3;
                if (PRODS >= 2) {
                    ldm4(Bbl + off, r0,r1,r2,r3);
                    blr[2*np][0]=r0; blr[2*np][1]=r1; blr[2*np+1][0]=r2; blr[2*np+1][1]=r3;
                }
            }
            #pragma unroll
            for (int mt=0; mt<4; mt++){
                uint32_t off = (uint32_t)(wm*64 + mt*16 + a_row)*80 + kb + a_colb;
                uint32_t ah[4];
                ldm4(Abh + off, ah[0], ah[1], ah[2], ah[3]);
                if (PRODS == 2) {
                    #pragma unroll
                    for (int nt=0; nt<4; nt++){
                        mma16816(acc[mt][nt], ah, bh[nt]);
                        mma16816(acc[mt][nt], ah, blr[nt]);
                    }
                } else {
                    #pragma unroll
                    for (int nt=0; nt<4; nt++){
                        mma16816(acc[mt][nt], ah, bh[nt]);
                    }
                }
            }
        }
        __syncthreads();
    }

    #pragma unroll
    for (int mt=0; mt<4; mt++){
        #pragma unroll
        for (int nt=0; nt<4; nt++){
            int m0 = bm + wm*64 + mt*16 + (lane >> 2);
            int n0 = bn + wn*32 + nt*8  + (lane & 3)*2;
            float c0 = acc[mt][nt][0], c1 = acc[mt][nt][1];
            float c2 = acc[mt][nt][2], c3 = acc[mt][nt][3];
            if (EPI == 0) {
                *(float2*)(C + (ll)m0*ldc + n0)     = make_float2(c0, c1);
                *(float2*)(C + (ll)(m0+8)*ldc + n0) = make_float2(c2, c3);
            } else if (EPI == 1) {
                float2 o0 = *(const float2*)(C + (ll)m0*ldc + n0);
                float2 o1 = *(const float2*)(C + (ll)(m0+8)*ldc + n0);
                *(float2*)(C + (ll)m0*ldc + n0)     = make_float2(o0.x+c0, o0.y+c1);
                *(float2*)(C + (ll)(m0+8)*ldc + n0) = make_float2(o1.x+c2, o1.y+c3);
            } else {
                if (EPI == 2) {
                    float b0 = __ldg(bias + n0), b1 = __ldg(bias + n0 + 1);
                    c0 = fmaxf(c0-b0, 0.f); c1 = fmaxf(c1-b1, 0.f);
                    c2 = fmaxf(c2-b0, 0.f); c3 = fmaxf(c3-b1, 0.f);
                }
                __half2 hv;
                hv.x = __float2half_rn(c0); hv.y = __float2half_rn(c1);
                *(__half2*)(Chi + (ll)m0*ldc + n0) = hv;
                hv.x = __float2half_rn(c2); hv.y = __float2half_rn(c3);
                *(__half2*)(Chi + (ll)(m0+8)*ldc + n0) = hv;
            }
        }
    }
}

// ---------------- elementwise kernels ----------------------------------------
// rope cos/sin table, double-precision phase (matches fp32 reference closely)
__global__ void rope_table_kernel(float* __restrict__ cst, float* __restrict__ snt)
{
    int i = blockIdx.x*256 + threadIdx.x;    // i < Tt*64
    int t = i >> 6, j = i & 63;
    double invf = exp(-(double)(2*j) * (9.210340371976184 / 128.0));
    double ph = (double)t * invf;
    cst[i] = (float)cos(ph);
    snt[i] = (float)sin(ph);
}

__global__ void embed_norm_kernel(const int* __restrict__ idx,
                                  const float* __restrict__ wte,
                                  float* __restrict__ x, float* __restrict__ x0)
{
    int t = blockIdx.x;
    int tok = idx[t];
    const float* row = wte + (ll)tok * Ee;
    ll base = (ll)t * Ee;
    float v[3]; float ss = 0.f;
    #pragma unroll
    for (int j=0;j<3;j++){ int c = threadIdx.x + j*256; float m = row[c]; v[j]=m; ss += m*m; }
    ss = blockSum(ss);
    float inv = rsqrtf(ss*(1.0f/Ee) + EPS);
    #pragma unroll
    for (int j=0;j<3;j++){ int c = threadIdx.x + j*256; float o = v[j]*inv; x[base+c]=o; x0[base+c]=o; }
}

// x = rl*x + xl*x0; hh = fp16(rmsnorm(x)); skips x0 loads when xl == 0
__global__ void mix_norm_split(float* __restrict__ x, const float* __restrict__ x0,
                               fp16* __restrict__ hh,
                               const float* lamr, const float* lamx, int li)
{
    int t = blockIdx.x;
    float rl = lamr ? lamr[li] : 1.0f;
    float xl = lamx ? lamx[li] : 0.0f;
    ll base = (ll)t * Ee;
    float v[3]; float ss = 0.f;
    if (xl != 0.0f) {
        #pragma unroll
        for (int j=0;j<3;j++){
            int c = threadIdx.x + j*256;
            float m = rl*x[base+c] + xl*x0[base+c];
            v[j]=m; ss += m*m;
        }
    } else {
        #pragma unroll
        for (int j=0;j<3;j++){
            int c = threadIdx.x + j*256;
            float m = rl*x[base+c];
            v[j]=m; ss += m*m;
        }
    }
    ss = blockSum(ss);
    float inv = rsqrtf(ss*(1.0f/Ee) + EPS);
    #pragma unroll
    for (int j=0;j<3;j++){
        int c = threadIdx.x + j*256;
        x[base+c] = v[j];
        hh[base+c] = __float2half_rn(v[j]*inv);
    }
}

__global__ void rope_split_kernel(const float* __restrict__ wf,
                                  const float* __restrict__ cst, const float* __restrict__ snt,
                                  fp16* __restrict__ wh, fp16* __restrict__ wl)
{
    int n  = blockIdx.x / Hh;
    int hh = blockIdx.x % Hh;
    int t  = n & (Tt-1);
    const float* base = wf + (ll)n*Ee + hh*HDd;
    int d = threadIdx.x;
    __shared__ float s[HDd];
    float v = base[d];
    s[d] = v;
    float ss = blockSum(v*v);
    float inv = rsqrtf(ss*(1.0f/HDd) + EPS);
    int j = d & 63;
    float cv = cst[t*64 + j], sv = snt[t*64 + j];
    float out;
    if (d < 64) {
        float x1 = s[j], x2 = s[j+64];
        out = (x1*cv + x2*sv) * inv;
    } else {
        float x1 = s[j], x2 = s[d];
        out = (-x1*sv + x2*cv) * inv;
    }
    fp16 h, l; split2(out, h, l);
    ll o = (ll)n*Ee + hh*HDd + d;
    wh[o] = h; wl[o] = l;
}

// hi-only transpose: [token][head*128] -> wt[z][128][1024]
__global__ void transpose_hd(const fp16* __restrict__ whi, fp16* __restrict__ othi)
{
    __shared__ fp16 tile[32][33];
    int z = blockIdx.z; int b = z / Hh, h = z % Hh;
    int t0 = blockIdx.x*32, d0 = blockIdx.y*32;
    for (int j=(int)threadIdx.y; j<32; j+=8)
        tile[j][threadIdx.x] = whi[(ll)(b*Tt + t0 + j)*Ee + h*HDd + d0 + threadIdx.x];
    __syncthreads();
    for (int j=(int)threadIdx.y; j<32; j+=8)
        othi[(ll)z*HDd*Tt + (ll)(d0 + j)*Tt + t0 + threadIdx.x] = tile[threadIdx.x][j];
}

// causal softmax; hi-only P, written only up to the 128-aligned boundary.
__global__ void softmax_split_kernel(const float* __restrict__ dots,
                                     fp16* __restrict__ ph, float scale)
{
    ll r = blockIdx.x;
    int q = (int)(r & (Tt-1));
    const float* row = dots + r * Tt;
    fp16* hrow = ph + r * Tt;
    int nv = q + 1;
    int kmax = ((q >> 7) + 1) << 7;
    float vals[4];
    float m = -INFINITY;
    #pragma unroll
    for (int it=0; it<4; it++){
        int k = threadIdx.x + it*256;
        float v = (k < nv) ? row[k]*scale : -INFINITY;
        vals[it] = v;
        m = fmaxf(m, v);
    }
    m = blockMax(m);
    float sum = 0.f;
    #pragma unroll
    for (int it=0; it<4; it++){
        int k = threadIdx.x + it*256;
        float e = (k < nv) ? __expf(vals[it]-m) : 0.0f;
        vals[it] = e; sum += e;
    }
    sum = blockSum(sum);
    float invs = 1.0f / sum;
    #pragma unroll
    for (int it=0; it<4; it++){
        int k = threadIdx.x + it*256;
        if (k < kmax) hrow[k] = __float2half_rn(vals[it]*invs);
    }
}

__global__ void split_f32(const float* __restrict__ in, fp16* __restrict__ hi,
                          fp16* __restrict__ lo, ll n)
{
    ll i = ((ll)blockIdx.x*blockDim.x + threadIdx.x)*4;
    if (i >= n) return;
    float4 v = *(const float4*)(in + i);
    fp16 h0,l0,h1,l1,h2,l2,h3,l3;
    split2(v.x,h0,l0); split2(v.y,h1,l1); split2(v.z,h2,l2); split2(v.w,h3,l3);
    __half2 a; a.x=h0; a.y=h1; __half2 b; b.x=h2; b.y=h3;
    __half2 c; c.x=l0; c.y=l1; __half2 d; d.x=l2; d.y=l3;
    *(__half2*)(hi+i)   = a; *(__half2*)(hi+i+2) = b;
    *(__half2*)(lo+i)   = c; *(__half2*)(lo+i+2) = d;
}

__global__ void conv_f32_hi(const float* __restrict__ in, fp16* __restrict__ hi, ll n)
{
    ll i = ((ll)blockIdx.x*blockDim.x + threadIdx.x)*4;
    if (i >= n) return;
    float4 v = *(const float4*)(in + i);
    __half2 a; a.x=__float2half_rn(v.x); a.y=__float2half_rn(v.y);
    __half2 b; b.x=__float2half_rn(v.z); b.y=__float2half_rn(v.w);
    *(__half2*)(hi+i)   = a; *(__half2*)(hi+i+2) = b;
}

// ---------------- host ---------------------------------------------------------
extern "C" void kernel_launch(void* const* d_in, const int* in_sizes, int n_in,
                              void* d_out, int out_size)
{
    const int*   idx  = (const int*)  d_in[0];
    const float* wte  = (const float*)d_in[1];
    const float* lmh  = (const float*)d_in[2];
    const float* qkvw = (const float*)d_in[3];
    const float* cpjw = (const float*)d_in[4];
    const float* denc = (const float*)d_in[5];
    const float* ddec = (const float*)d_in[6];
    const float* thr  = (const float*)d_in[7];
    const float* lamr = (const float*)d_in[8];
    const float* lamx = (const float*)d_in[9];
    float* out = (float*)d_out;

    constexpr int DSZ1 = Cfg<1>::DSZ;   // 61440
    constexpr int DSZ2 = Cfg<2>::DSZ;   // 92160
    cudaFuncSetAttribute(gemm_mm<2,0,false,false>, cudaFuncAttributeMaxDynamicSharedMemorySize, DSZ2);
    cudaFuncSetAttribute(gemm_mm<2,0,true ,false>, cudaFuncAttributeMaxDynamicSharedMemorySize, DSZ2);
    cudaFuncSetAttribute(gemm_mm<2,1,false,false>, cudaFuncAttributeMaxDynamicSharedMemorySize, DSZ2);
    cudaFuncSetAttribute(gemm_mm<2,2,false,false>, cudaFuncAttributeMaxDynamicSharedMemorySize, DSZ2);
    cudaFuncSetAttribute(gemm_mm<1,3,false,true >, cudaFuncAttributeMaxDynamicSharedMemorySize, DSZ1);
    cudaFuncSetAttribute(gemm_mm<1,0,false,false>, cudaFuncAttributeMaxDynamicSharedMemorySize, DSZ1);

    float *x, *x0, *wf, *dots, *cst, *snt;
    cudaGetSymbolAddress((void**)&x,    g_x);
    cudaGetSymbolAddress((void**)&x0,   g_x0);
    cudaGetSymbolAddress((void**)&wf,   g_w);
    cudaGetSymbolAddress((void**)&dots, g_dots);
    cudaGetSymbolAddress((void**)&cst,  g_cos);
    cudaGetSymbolAddress((void**)&snt,  g_sin);
    fp16 *hh,*wh,*wl,*wth,*ph,*oh,*ah;
    cudaGetSymbolAddress((void**)&hh,  g_hh);
    cudaGetSymbolAddress((void**)&wh,  g_wh);  cudaGetSymbolAddress((void**)&wl,  g_wl);
    cudaGetSymbolAddress((void**)&wth, g_wth);
    cudaGetSymbolAddress((void**)&ph,  g_ph);
    cudaGetSymbolAddress((void**)&oh,  g_oh);
    cudaGetSymbolAddress((void**)&ah,  g_ah);
    fp16 *qh,*ql,*ch,*cl,*eh,*el,*dh,*dl,*lh;
    cudaGetSymbolAddress((void**)&qh, g_qkvh); cudaGetSymbolAddress((void**)&ql, g_qkvl);
    cudaGetSymbolAddress((void**)&ch, g_cpjh); cudaGetSymbolAddress((void**)&cl, g_cpjl);
    cudaGetSymbolAddress((void**)&eh, g_dech); cudaGetSymbolAddress((void**)&el, g_decl);
    cudaGetSymbolAddress((void**)&dh, g_ddh);  cudaGetSymbolAddress((void**)&dl, g_ddl);
    cudaGetSymbolAddress((void**)&lh, g_lmhh);

    {
        ll n;
        n = (ll)Ll*Ee*Ee;    split_f32<<<(int)((n/4+255)/256),256>>>(qkvw, qh, ql, n);
        n = (ll)Ll*Ee*Ee;    split_f32<<<(int)((n/4+255)/256),256>>>(cpjw, ch, cl, n);
        n = (ll)Ll*HIDh*Ee;  split_f32<<<(int)((n/4+255)/256),256>>>(denc, eh, el, n);
        n = (ll)Ll*Ee*HIDh;  split_f32<<<(int)((n/4+255)/256),256>>>(ddec, dh, dl, n);
        n = (ll)Vv*Ee;       conv_f32_hi<<<(int)((n/4+255)/256),256>>>(lmh, lh, n);
        rope_table_kernel<<<Tt*64/256,256>>>(cst, snt);
    }

    const float scale = 0.08838834764831845f;
    const ll TE = (ll)Tt*Ee;
    const ll TT = (ll)Tt*Tt;
    const ll WT = (ll)HDd*Tt;

    embed_norm_kernel<<<NTOK,256>>>(idx, wte, x, x0);

    for (int i=0;i<Ll;i++){
        mix_norm_split<<<NTOK,256>>>(x, x0, hh, lamr, lamx, i);

        // w = h @ qkv^T (fp32 out for rope), 2-product
        gemm_mm<2,0,false,false><<<dim3(6,32,1),256,DSZ2>>>(
            hh, qh + (ll)i*Ee*Ee, ql + (ll)i*Ee*Ee,
            wf, nullptr, nullptr,
            Ee, Ee, Ee, Ee, 1, 0,0, 0,0, 0,0);

        rope_split_kernel<<<NTOK*Hh,128>>>(wf, cst, snt, wh, wl);
        transpose_hd<<<dim3(Tt/32, HDd/32, Bb*Hh), dim3(32,8)>>>(wh, wth);

        // dots = W W^T (lower-triangular tiles only), 2-product (B-lo = wl)
        gemm_mm<2,0,true,false><<<dim3(36,1,Bb*Hh),256,DSZ2>>>(
            wh, wh, wl,
            dots, nullptr, nullptr,
            HDd, Ee, Ee, Tt, Hh, TE,(ll)HDd, TE,(ll)HDd, (ll)Hh*TT, TT);

        softmax_split_kernel<<<Bb*Hh*Tt,256>>>(dots, ph, scale);

        // o = P @ W (K limited to bm+128), hi store, 1-product
        gemm_mm<1,3,false,true><<<dim3(1,8,Bb*Hh),256,DSZ1>>>(
            ph, wth, wth,
            nullptr, oh, nullptr,
            Tt, Tt, Tt, Ee, Hh, (ll)Hh*TT,TT, (ll)Hh*WT,WT, TE,(ll)HDd);

        // x += o @ cproj^T, 2-product
        gemm_mm<2,1,false,false><<<dim3(6,32,1),256,DSZ2>>>(
            oh, ch + (ll)i*Ee*Ee, cl + (ll)i*Ee*Ee,
            x, nullptr, nullptr,
            Ee, Ee, Ee, Ee, 1, 0,0, 0,0, 0,0);

        mix_norm_split<<<NTOK,256>>>(x, x0, hh, nullptr, nullptr, 0);

        // a = relu(h @ denc^T - thr), hi store, 2-product
        gemm_mm<2,2,false,false><<<dim3(24,32,1),256,DSZ2>>>(
            hh, eh + (ll)i*HIDh*Ee, el + (ll)i*HIDh*Ee,
            nullptr, ah, thr + (ll)i*HIDh,
            Ee, Ee, Ee, HIDh, 1, 0,0, 0,0, 0,0);

        // x += a @ ddec^T, 2-product
        gemm_mm<2,1,false,false><<<dim3(6,32,1),256,DSZ2>>>(
            ah, dh + (ll)i*Ee*HIDh, dl + (ll)i*Ee*HIDh,
            x, nullptr, nullptr,
            HIDh, HIDh, HIDh, Ee, 1, 0,0, 0,0, 0,0);
    }

    mix_norm_split<<<NTOK,256>>>(x, x0, hh, nullptr, nullptr, 0);
    // lm_head: 1-product pure fp16 (terminal op)
    gemm_mm<1,0,false,false><<<dim3(393,32,1),256,DSZ1>>>(
        hh, lh, lh, out, nullptr, nullptr,
        Ee, Ee, Ee, Vv, 1, 0,0, 0,0, 0,0);
}